// round 1
// baseline (speedup 1.0000x reference)
#include <cuda_runtime.h>
#include <cstdint>

#define L_SEQ   4096
#define B_SZ    4
#define D_MODEL 512
#define D_INNER 1024
#define D_XZ    2048
#define NTOK    (B_SZ*L_SEQ)   /* 16384 */
#define DT_RANK 32
#define D_STATE 16

// ---------------- scratch (static device allocations; harness forbids cudaMalloc) ---
__device__ float g_xz  [(size_t)NTOK*D_XZ];          // 134 MB
__device__ float g_axz [(size_t)NTOK*D_XZ];          // 134 MB
__device__ float g_xs  [3][(size_t)NTOK*D_INNER];    // 3 x 67 MB  (post conv+silu x)
__device__ float g_u   [3][(size_t)NTOK*D_INNER];    // 3 x 67 MB  (pre-softplus dt logits)
__device__ float g_dbl [3][(size_t)NTOK*64];         // 3 x 4 MB   (dt_low | B | C)
__device__ float g_y   [3][(size_t)NTOK*D_INNER];    // 3 x 67 MB  (branch outputs)
__device__ float g_comb[(size_t)NTOK*D_INNER];       // 67 MB

__device__ __forceinline__ float sigmoidf_(float x){ return 1.0f/(1.0f+__expf(-x)); }
__device__ __forceinline__ float siluf_(float x){ return x*sigmoidf_(x); }

// ---------------- generic TN SGEMM: C[m,n] = sum_k A[m,k]*W[n,k] (+bias[n]) --------
struct GemmB { const float* A; const float* W; const float* bias; float* C; };
struct GemmB3 { GemmB g[3]; };

template<int BM,int BN,int BK,int TM,int TN,bool BIAS>
__global__ void sgemm_tn(GemmB3 P, int M, int N, int K, int lda)
{
    constexpr int NT = (BM/TM)*(BN/TN);
    __shared__ float As[BK][BM+4];
    __shared__ float Ws[BK][BN+4];
    const GemmB g = P.g[blockIdx.z];
    const int tid = threadIdx.x;
    const int tx  = tid % (BN/TN);
    const int ty  = tid / (BN/TN);
    const int m0  = blockIdx.y*BM;
    const int n0  = blockIdx.x*BN;

    float acc[TM][TN];
#pragma unroll
    for (int i=0;i<TM;i++)
#pragma unroll
        for (int j=0;j<TN;j++) acc[i][j]=0.f;

    for (int k0=0;k0<K;k0+=BK){
        // load A tile (BM x BK), transpose into As[k][m]
#pragma unroll
        for (int s = tid; s < BM*BK/4; s += NT){
            const int row = s / (BK/4);
            const int kq  = s % (BK/4);
            const float4 v = *(const float4*)(g.A + (size_t)(m0+row)*lda + k0 + kq*4);
            As[kq*4+0][row]=v.x; As[kq*4+1][row]=v.y;
            As[kq*4+2][row]=v.z; As[kq*4+3][row]=v.w;
        }
        // load W tile (BN x BK), transpose into Ws[k][n]
#pragma unroll
        for (int s = tid; s < BN*BK/4; s += NT){
            const int row = s / (BK/4);
            const int kq  = s % (BK/4);
            const float4 v = *(const float4*)(g.W + (size_t)(n0+row)*K + k0 + kq*4);
            Ws[kq*4+0][row]=v.x; Ws[kq*4+1][row]=v.y;
            Ws[kq*4+2][row]=v.z; Ws[kq*4+3][row]=v.w;
        }
        __syncthreads();
#pragma unroll
        for (int k=0;k<BK;k++){
            float a[TM], bw[TN];
#pragma unroll
            for (int v=0;v<TM/4;v++) *(float4*)&a[v*4]  = *(const float4*)&As[k][ty*TM+v*4];
#pragma unroll
            for (int v=0;v<TN/4;v++) *(float4*)&bw[v*4] = *(const float4*)&Ws[k][tx*TN+v*4];
#pragma unroll
            for (int i=0;i<TM;i++)
#pragma unroll
                for (int j=0;j<TN;j++) acc[i][j] = fmaf(a[i], bw[j], acc[i][j]);
        }
        __syncthreads();
    }
    // epilogue
#pragma unroll
    for (int i=0;i<TM;i++){
        const int m = m0 + ty*TM + i;
#pragma unroll
        for (int jv=0;jv<TN/4;jv++){
            float4 v;
            const int nb = n0 + tx*TN + jv*4;
            v.x = acc[i][jv*4+0]; v.y = acc[i][jv*4+1];
            v.z = acc[i][jv*4+2]; v.w = acc[i][jv*4+3];
            if (BIAS){
                v.x += g.bias[nb+0]; v.y += g.bias[nb+1];
                v.z += g.bias[nb+2]; v.w += g.bias[nb+3];
            }
            *(float4*)(g.C + (size_t)m*N + nb) = v;
        }
    }
}

// ---------------- depthwise causal conv (kernel 4) + SiLU, optional time-flip -------
struct ConvB { const float* X; const float* w; const float* b; float* xs; int rev; };
struct ConvB3 { ConvB c[3]; };
#define CCH 512

__global__ void conv_silu_kernel(ConvB3 P)
{
    const ConvB c = P.c[blockIdx.z];
    const int d  = blockIdx.x*128 + threadIdx.x;
    const int bt = blockIdx.y;            // 0..31 -> (b, t-chunk)
    const int b  = bt >> 3;
    const int t0 = (bt & 7)*CCH;
    const float w0=c.w[d*4+0], w1=c.w[d*4+1], w2=c.w[d*4+2], w3=c.w[d*4+3];
    const float bb=c.b[d];
    const size_t bL = (size_t)b*L_SEQ;

    auto X = [&](int i)->float{
        if (i < 0) return 0.f;
        const int l = c.rev ? (L_SEQ-1-i) : i;
        return c.X[(bL + l)*(size_t)D_XZ + d];
    };
    float x0=X(t0-3), x1=X(t0-2), x2=X(t0-1);
#pragma unroll 4
    for (int t=t0; t<t0+CCH; t++){
        const float x3 = X(t);
        const float v = fmaf(w0,x0,fmaf(w1,x1,fmaf(w2,x2,fmaf(w3,x3,bb))));
        c.xs[(bL+t)*(size_t)D_INNER + d] = siluf_(v);
        x0=x1; x1=x2; x2=x3;
    }
}

// ---------------- fused selective scan (3 branches in one launch) -------------------
struct ScanB { const float* U; const float* XS; const float* DBL; const float* XZb;
               const float* Alog; const float* Dp; float* Y; int rev; };
struct ScanB3 { ScanB s[3]; };

__global__ void scan_kernel(ScanB3 P)
{
    constexpr int TC = 128;
    __shared__ float sBC[TC][32];          // B(16) | C(16) per timestep
    const ScanB S = P.s[blockIdx.z];
    const int tid = threadIdx.x;
    const int d   = blockIdx.x*128 + tid;
    const int b   = blockIdx.y;
    const size_t bL = (size_t)b * L_SEQ;

    float a[16];
#pragma unroll
    for (int n=0;n<16;n++) a[n] = -__expf(S.Alog[d*16+n]);
    const float a0 = a[0];
    bool pw = fabsf(a0) > 1e-20f;
#pragma unroll
    for (int n=0;n<16;n++){
        const float r = a[n]/a0;
        pw = pw && (fabsf(r - (float)(n+1)) < 1e-4f);
    }
    const float Dd = S.Dp[d];
    float h[16];
#pragma unroll
    for (int n=0;n<16;n++) h[n]=0.f;

    for (int t0=0;t0<L_SEQ;t0+=TC){
        __syncthreads();
#pragma unroll
        for (int r=0;r<(TC*32)/(4*128);r++){       // 8 float4 loads per thread
            const int slot = tid + r*128;
            const int tt = slot>>3, q = slot&7;
            const float4 v = *(const float4*)(S.DBL + (bL + t0 + tt)*64 + 32 + q*4);
            *(float4*)&sBC[tt][q*4] = v;
        }
        __syncthreads();
#pragma unroll 4
        for (int tt=0;tt<TC;tt++){
            const int t = t0+tt;
            const size_t idx = (bL + t)*(size_t)D_INNER + d;
            const float u  = S.U[idx];
            const float xv = S.XS[idx];
            const int   lz = S.rev ? (L_SEQ-1-t) : t;
            const float zv = S.XZb[(bL+lz)*(size_t)D_XZ + D_INNER + d];
            const float dt = (u > 20.f) ? u : log1pf(__expf(u));
            const float dtx = dt*xv;
            float Bv[16], Cv[16];
#pragma unroll
            for (int q=0;q<4;q++){
                *(float4*)&Bv[q*4] = *(const float4*)&sBC[tt][q*4];
                *(float4*)&Cv[q*4] = *(const float4*)&sBC[tt][16+q*4];
            }
            float ya[4] = {0.f,0.f,0.f,0.f};
            if (pw){
                const float p = __expf(dt*a0);
                float e = p;
#pragma unroll
                for (int n=0;n<16;n++){
                    h[n] = fmaf(e, h[n], dtx*Bv[n]);
                    ya[n&3] = fmaf(h[n], Cv[n], ya[n&3]);
                    e *= p;
                }
            } else {
#pragma unroll
                for (int n=0;n<16;n++){
                    const float e = __expf(dt*a[n]);
                    h[n] = fmaf(e, h[n], dtx*Bv[n]);
                    ya[n&3] = fmaf(h[n], Cv[n], ya[n&3]);
                }
            }
            const float y = (ya[0]+ya[1]) + (ya[2]+ya[3]);
            S.Y[idx] = (y + Dd*xv) * siluf_(zv);
        }
    }
}

// ---------------- gated combine: (y_f + flip(y_r)) * silu(y_g) ----------------------
__global__ void combine_kernel(const float* __restrict__ yf, const float* __restrict__ yr,
                               const float* __restrict__ yg, float* __restrict__ o)
{
    const size_t i = (size_t)blockIdx.x*256 + threadIdx.x;
    const int d = (int)(i % D_INNER);
    const size_t rr = i / D_INNER;
    const int l = (int)(rr % L_SEQ);
    const int b = (int)(rr / L_SEQ);
    const size_t ridx = ((size_t)b*L_SEQ + (L_SEQ-1-l))*(size_t)D_INNER + d;
    o[i] = (yf[i] + yr[ridx]) * siluf_(yg[i]);
}

// ------------------------------- host driver ----------------------------------------
extern "C" void kernel_launch(void* const* d_in, const int* in_sizes, int n_in,
                              void* d_out, int out_size)
{
    const float* H    = (const float*)d_in[0];
    const float* AH   = (const float*)d_in[1];
    const float* Winp = (const float*)d_in[2];
    const float* Wing = (const float*)d_in[3];
    const float* convw[3] = { (const float*)d_in[4], (const float*)d_in[6], (const float*)d_in[8] };
    const float* convb[3] = { (const float*)d_in[5], (const float*)d_in[7], (const float*)d_in[9] };
    const float* xproj[3] = { (const float*)d_in[10], (const float*)d_in[11], (const float*)d_in[12] };
    const float* dtw[3]   = { (const float*)d_in[13], (const float*)d_in[15], (const float*)d_in[17] };
    const float* dtb[3]   = { (const float*)d_in[14], (const float*)d_in[16], (const float*)d_in[18] };
    const float* Alog[3]  = { (const float*)d_in[19], (const float*)d_in[20], (const float*)d_in[21] };
    const float* Dp[3]    = { (const float*)d_in[22], (const float*)d_in[23], (const float*)d_in[24] };
    const float* Wout = (const float*)d_in[25];
    float* out = (float*)d_out;

    float *p_xz, *p_axz, *p_xs, *p_u, *p_dbl, *p_y, *p_comb;
    cudaGetSymbolAddress((void**)&p_xz,   g_xz);
    cudaGetSymbolAddress((void**)&p_axz,  g_axz);
    cudaGetSymbolAddress((void**)&p_xs,   g_xs);
    cudaGetSymbolAddress((void**)&p_u,    g_u);
    cudaGetSymbolAddress((void**)&p_dbl,  g_dbl);
    cudaGetSymbolAddress((void**)&p_y,    g_y);
    cudaGetSymbolAddress((void**)&p_comb, g_comb);
    const size_t SXS  = (size_t)NTOK*D_INNER;
    const size_t SDBL = (size_t)NTOK*64;

    // 1) in-projections: xz = H @ Winp^T ; axz = AH @ Wing^T   (batched z=2)
    {
        GemmB3 P;
        P.g[0] = { H,  Winp, nullptr, p_xz  };
        P.g[1] = { AH, Wing, nullptr, p_axz };
        P.g[2] = P.g[0];
        sgemm_tn<128,128,16,8,8,false><<<dim3(D_XZ/128, NTOK/128, 2), 256>>>(P, NTOK, D_XZ, D_MODEL, D_MODEL);
    }
    // 2) depthwise conv + silu, 3 branches (r works on time-flipped xz)
    {
        ConvB3 P;
        P.c[0] = { p_xz,  convw[0], convb[0], p_xs + 0*SXS, 0 };
        P.c[1] = { p_xz,  convw[1], convb[1], p_xs + 1*SXS, 1 };
        P.c[2] = { p_axz, convw[2], convb[2], p_xs + 2*SXS, 0 };
        conv_silu_kernel<<<dim3(D_INNER/128, 32, 3), 128>>>(P);
    }
    // 3) x-projection: dbl = xs @ xproj^T   (N = 64)
    {
        GemmB3 P;
        for (int z=0; z<3; z++) P.g[z] = { p_xs + z*SXS, xproj[z], nullptr, p_dbl + z*SDBL };
        sgemm_tn<128,64,16,8,4,false><<<dim3(1, NTOK/128, 3), 256>>>(P, NTOK, 64, D_INNER, D_INNER);
    }
    // 4) dt-projection: u = dbl[:, :32] @ dtw^T + dtb   (K = 32, lda = 64)
    {
        GemmB3 P;
        for (int z=0; z<3; z++) P.g[z] = { p_dbl + z*SDBL, dtw[z], dtb[z], p_u + z*SXS };
        sgemm_tn<128,128,16,8,8,true><<<dim3(D_INNER/128, NTOK/128, 3), 256>>>(P, NTOK, D_INNER, DT_RANK, 64);
    }
    // 5) selective scan, 3 branches in one launch; fuses softplus, D*x skip, silu(z) gate
    {
        ScanB3 P;
        P.s[0] = { p_u + 0*SXS, p_xs + 0*SXS, p_dbl + 0*SDBL, p_xz,  Alog[0], Dp[0], p_y + 0*SXS, 0 };
        P.s[1] = { p_u + 1*SXS, p_xs + 1*SXS, p_dbl + 1*SDBL, p_xz,  Alog[1], Dp[1], p_y + 1*SXS, 1 };
        P.s[2] = { p_u + 2*SXS, p_xs + 2*SXS, p_dbl + 2*SDBL, p_axz, Alog[2], Dp[2], p_y + 2*SXS, 0 };
        scan_kernel<<<dim3(D_INNER/128, B_SZ, 3), 128>>>(P);
    }
    // 6) combine: (y_f + flip(y_r)) * silu(y_g)
    combine_kernel<<<(unsigned)(SXS/256), 256>>>(p_y + 0*SXS, p_y + 1*SXS, p_y + 2*SXS, p_comb);

    // 7) out-projection: out = comb @ Wout^T
    {
        GemmB3 P;
        P.g[0] = { p_comb, Wout, nullptr, out };
        P.g[1] = P.g[0]; P.g[2] = P.g[0];
        sgemm_tn<128,128,16,8,8,false><<<dim3(D_MODEL/128, NTOK/128, 1), 256>>>(P, NTOK, D_MODEL, D_INNER, D_INNER);
    }
    (void)in_sizes; (void)n_in; (void)out_size;
}

// round 4
// speedup vs baseline: 1.2928x; 1.2928x over previous
#include <cuda_runtime.h>
#include <cuda_bf16.h>
#include <cstdint>

#define L_SEQ   4096
#define B_SZ    4
#define D_MODEL 512
#define D_INNER 1024
#define D_XZ    2048
#define NTOK    (B_SZ*L_SEQ)   /* 16384 */
#define DT_RANK 32
#define D_STATE 16

// ---------------- scratch (static device allocations; harness forbids cudaMalloc) ---
__device__ float g_xz  [(size_t)NTOK*D_XZ];
__device__ float g_axz [(size_t)NTOK*D_XZ];
__device__ float g_xs  [3][(size_t)NTOK*D_INNER];      // conv+silu x (fp32, for scan)
__device__ float g_u   [3][(size_t)NTOK*D_INNER];      // dt logits
__device__ float g_dbl [3][(size_t)NTOK*64];           // dt_low | B | C
__device__ float g_y   [3][(size_t)NTOK*D_INNER];      // branch outputs
// augmented bf16 operands, K' = 3K.  A-side: [hi|lo|hi].  W-side: [hi|hi|lo].
__device__ __nv_bfloat16 g_Haug [(size_t)NTOK*3*D_MODEL];
__device__ __nv_bfloat16 g_AHaug[(size_t)NTOK*3*D_MODEL];
__device__ __nv_bfloat16 g_Wiaug[(size_t)D_XZ*3*D_MODEL];
__device__ __nv_bfloat16 g_Wgaug[(size_t)D_XZ*3*D_MODEL];
__device__ __nv_bfloat16 g_xsaug[3][(size_t)NTOK*3*D_INNER];
__device__ __nv_bfloat16 g_Xpaug[3][(size_t)64*3*D_INNER];
__device__ __nv_bfloat16 g_dtwaug[3][(size_t)D_INNER*3*DT_RANK];
__device__ __nv_bfloat16 g_dblaug[3][(size_t)NTOK*3*DT_RANK];
__device__ __nv_bfloat16 g_Woaug[(size_t)D_MODEL*3*D_INNER];
__device__ __nv_bfloat16 g_combaug[(size_t)NTOK*3*D_INNER];

__device__ __forceinline__ float sigmoidf_(float x){ return 1.0f/(1.0f+__expf(-x)); }
__device__ __forceinline__ float siluf_(float x){ return x*sigmoidf_(x); }

__device__ __forceinline__ uint32_t smem_u32(const void* p){
    uint32_t a;
    asm("{ .reg .u64 t; cvta.to.shared.u64 t, %1; cvt.u32.u64 %0, t; }" : "=r"(a) : "l"(p));
    return a;
}
__device__ __forceinline__ void cp_async16(uint32_t dst, const void* src){
    asm volatile("cp.async.cg.shared.global [%0], [%1], 16;\n" :: "r"(dst), "l"(src));
}

// ====== split: fp32 [R,K] (ld_src) -> bf16 aug [R, 3K] =============================
// MODE 0 (A-side): [hi | lo | hi].   MODE 1 (W-side): [hi | hi | lo].
template<int MODE>
__global__ void split_aug(const float* __restrict__ src, __nv_bfloat16* __restrict__ dst,
                          int K, int ld_src, int n4total)
{
    const int i = blockIdx.x*256 + threadIdx.x;
    if (i >= n4total) return;
    const int kq = K >> 2;
    const int r  = i / kq, k4 = i % kq;
    const float4 v = *(const float4*)(src + (size_t)r*ld_src + k4*4);
    const float f[4] = {v.x, v.y, v.z, v.w};
    __align__(8) __nv_bfloat16 hh[4], ll[4];
#pragma unroll
    for (int j=0;j<4;j++){
        hh[j] = __float2bfloat16_rn(f[j]);
        ll[j] = __float2bfloat16_rn(f[j] - __bfloat162float(hh[j]));
    }
    __nv_bfloat16* o = dst + (size_t)r*3*K + k4*4;
    if (MODE == 0){
        *(uint2*)(o)       = *(const uint2*)hh;
        *(uint2*)(o + K)   = *(const uint2*)ll;
        *(uint2*)(o + 2*K) = *(const uint2*)hh;
    } else {
        *(uint2*)(o)       = *(const uint2*)hh;
        *(uint2*)(o + K)   = *(const uint2*)hh;
        *(uint2*)(o + 2*K) = *(const uint2*)ll;
    }
}

// ================= mma.sync bf16 GEMM: C[m,n] = A[m,:]·W[n,:] (+bias) ================
// A: [M, K3] bf16 row-major, W: [N, K3] bf16 row-major (= B col-major for mma).
// BM=128, BN in {64,128}, BK=32, 256 threads, warp tile 32 x (BN/2).
struct MG  { const __nv_bfloat16 *A, *W; const float* bias; float* C; };
struct MG3 { MG g[3]; int N, K3; };

template<int BN, bool BIAS>
__global__ void __launch_bounds__(256) mma_gemm(MG3 P)
{
    constexpr int WN = BN/2;
    constexpr int NTL = WN/8;
    const MG g = P.g[blockIdx.z];
    const int N = P.N, K3 = P.K3;
    const int tid  = threadIdx.x;
    const int lane = tid & 31, wid = tid >> 5;
    const int warp_m = wid & 3, warp_n = wid >> 2;
    const int m0 = blockIdx.y * 128, n0 = blockIdx.x * BN;

    __shared__ __align__(128) __nv_bfloat16 sA[2][128*40];
    __shared__ __align__(128) __nv_bfloat16 sW[2][BN*40];
    const uint32_t aB[2] = { smem_u32(sA[0]), smem_u32(sA[1]) };
    const uint32_t wB[2] = { smem_u32(sW[0]), smem_u32(sW[1]) };

    float acc[2][NTL][4];
#pragma unroll
    for (int mt=0;mt<2;mt++)
#pragma unroll
        for (int nt=0;nt<NTL;nt++)
#pragma unroll
            for (int j=0;j<4;j++) acc[mt][nt][j]=0.f;

    const int nk = K3 / 32;

    auto load_tiles = [&](int buf, int k0){
        const __nv_bfloat16* Ap = g.A + (size_t)m0*K3 + k0;
#pragma unroll
        for (int s = tid; s < 512; s += 256){
            const int r = s>>2, c = s&3;
            cp_async16(aB[buf] + r*80 + c*16, Ap + (size_t)r*K3 + c*8);
        }
        const __nv_bfloat16* Wp = g.W + (size_t)n0*K3 + k0;
#pragma unroll
        for (int s = tid; s < BN*4; s += 256){
            const int r = s>>2, c = s&3;
            cp_async16(wB[buf] + r*80 + c*16, Wp + (size_t)r*K3 + c*8);
        }
        asm volatile("cp.async.commit_group;\n" ::: "memory");
    };

    load_tiles(0, 0);
    const int lr       = lane & 7;
    const int arow_off = ((lane>>3)&1)*8 + lr;
    const int akb      = (lane>>4)*16;
    const int bkb      = ((lane>>3)&1)*16;

    for (int kt = 0; kt < nk; kt++){
        const int buf = kt & 1;
        if (kt + 1 < nk){
            load_tiles(buf^1, (kt+1)*32);
            asm volatile("cp.async.wait_group 1;\n" ::: "memory");
        } else {
            asm volatile("cp.async.wait_group 0;\n" ::: "memory");
        }
        __syncthreads();

#pragma unroll
        for (int ks = 0; ks < 2; ks++){
            uint32_t a[2][4];
#pragma unroll
            for (int mt=0; mt<2; mt++){
                const uint32_t addr = aB[buf] + (warp_m*32 + mt*16 + arow_off)*80 + ks*32 + akb;
                asm volatile("ldmatrix.sync.aligned.m8n8.x4.shared.b16 {%0,%1,%2,%3}, [%4];"
                    : "=r"(a[mt][0]),"=r"(a[mt][1]),"=r"(a[mt][2]),"=r"(a[mt][3]) : "r"(addr));
            }
            uint32_t b[NTL][2];
#pragma unroll
            for (int nt=0; nt<NTL; nt++){
                const uint32_t addr = wB[buf] + (warp_n*WN + nt*8 + lr)*80 + ks*32 + bkb;
                asm volatile("ldmatrix.sync.aligned.m8n8.x2.shared.b16 {%0,%1}, [%2];"
                    : "=r"(b[nt][0]),"=r"(b[nt][1]) : "r"(addr));
            }
#pragma unroll
            for (int mt=0; mt<2; mt++)
#pragma unroll
                for (int nt=0; nt<NTL; nt++){
                    asm volatile("mma.sync.aligned.m16n8k16.row.col.f32.bf16.bf16.f32 "
                        "{%0,%1,%2,%3}, {%4,%5,%6,%7}, {%8,%9}, {%0,%1,%2,%3};"
                        : "+f"(acc[mt][nt][0]),"+f"(acc[mt][nt][1]),
                          "+f"(acc[mt][nt][2]),"+f"(acc[mt][nt][3])
                        : "r"(a[mt][0]),"r"(a[mt][1]),"r"(a[mt][2]),"r"(a[mt][3]),
                          "r"(b[nt][0]),"r"(b[nt][1]));
                }
        }
        __syncthreads();
    }

    // epilogue
    const int lr4 = lane>>2, lc2 = (lane&3)*2;
#pragma unroll
    for (int mt=0; mt<2; mt++){
        const int r0 = m0 + warp_m*32 + mt*16 + lr4;
#pragma unroll
        for (int nt=0; nt<NTL; nt++){
            const int col = n0 + warp_n*WN + nt*8 + lc2;
            float b0=0.f, b1=0.f;
            if (BIAS){ b0 = g.bias[col]; b1 = g.bias[col+1]; }
            float2 v0, v1;
            v0.x = acc[mt][nt][0]+b0; v0.y = acc[mt][nt][1]+b1;
            v1.x = acc[mt][nt][2]+b0; v1.y = acc[mt][nt][3]+b1;
            *(float2*)(g.C + (size_t)r0*N + col)     = v0;
            *(float2*)(g.C + (size_t)(r0+8)*N + col) = v1;
        }
    }
}

// ---------------- depthwise causal conv (k=4) + SiLU + aug bf16 out (A-side) --------
struct ConvB { const float* X; const float* w; const float* b;
               float* xs; __nv_bfloat16* xsaug; int rev; };
struct ConvB3 { ConvB c[3]; };
#define CCH 512

__global__ void conv_silu_kernel(ConvB3 P)
{
    const ConvB c = P.c[blockIdx.z];
    const int d  = blockIdx.x*128 + threadIdx.x;
    const int bt = blockIdx.y;
    const int b  = bt >> 3;
    const int t0 = (bt & 7)*CCH;
    const float w0=c.w[d*4+0], w1=c.w[d*4+1], w2=c.w[d*4+2], w3=c.w[d*4+3];
    const float bb=c.b[d];
    const size_t bL = (size_t)b*L_SEQ;

    auto X = [&](int i)->float{
        if (i < 0) return 0.f;
        const int l = c.rev ? (L_SEQ-1-i) : i;
        return c.X[(bL + l)*(size_t)D_XZ + d];
    };
    float x0=X(t0-3), x1=X(t0-2), x2=X(t0-1);
#pragma unroll 4
    for (int t=t0; t<t0+CCH; t++){
        const float x3 = X(t);
        const float v = fmaf(w0,x0,fmaf(w1,x1,fmaf(w2,x2,fmaf(w3,x3,bb))));
        const float s = siluf_(v);
        c.xs[(bL+t)*(size_t)D_INNER + d] = s;
        const __nv_bfloat16 hb = __float2bfloat16_rn(s);
        const __nv_bfloat16 lb = __float2bfloat16_rn(s - __bfloat162float(hb));
        __nv_bfloat16* o = c.xsaug + (bL+t)*(size_t)(3*D_INNER) + d;
        o[0] = hb; o[D_INNER] = lb; o[2*D_INNER] = hb;   // A-side: hi|lo|hi
        x0=x1; x1=x2; x2=x3;
    }
}

// ---------------- fused selective scan (3 branches in one launch) -------------------
struct ScanB { const float* U; const float* XS; const float* DBL; const float* XZb;
               const float* Alog; const float* Dp; float* Y; int rev; };
struct ScanB3 { ScanB s[3]; };

__global__ void scan_kernel(ScanB3 P)
{
    constexpr int TC = 128;
    __shared__ float sBC[TC][32];
    const ScanB S = P.s[blockIdx.z];
    const int tid = threadIdx.x;
    const int d   = blockIdx.x*128 + tid;
    const int b   = blockIdx.y;
    const size_t bL = (size_t)b * L_SEQ;

    float a[16];
#pragma unroll
    for (int n=0;n<16;n++) a[n] = -__expf(S.Alog[d*16+n]);
    const float a0 = a[0];
    bool pw = fabsf(a0) > 1e-20f;
#pragma unroll
    for (int n=0;n<16;n++){
        const float r = a[n]/a0;
        pw = pw && (fabsf(r - (float)(n+1)) < 1e-4f);
    }
    const float Dd = S.Dp[d];
    float h[16];
#pragma unroll
    for (int n=0;n<16;n++) h[n]=0.f;

    for (int t0=0;t0<L_SEQ;t0+=TC){
        __syncthreads();
#pragma unroll
        for (int r=0;r<(TC*32)/(4*128);r++){
            const int slot = tid + r*128;
            const int tt = slot>>3, q = slot&7;
            const float4 v = *(const float4*)(S.DBL + (bL + t0 + tt)*64 + 32 + q*4);
            *(float4*)&sBC[tt][q*4] = v;
        }
        __syncthreads();
#pragma unroll 4
        for (int tt=0;tt<TC;tt++){
            const int t = t0+tt;
            const size_t idx = (bL + t)*(size_t)D_INNER + d;
            const float u  = S.U[idx];
            const float xv = S.XS[idx];
            const int   lz = S.rev ? (L_SEQ-1-t) : t;
            const float zv = S.XZb[(bL+lz)*(size_t)D_XZ + D_INNER + d];
            const float dt = (u > 20.f) ? u : log1pf(__expf(u));
            const float dtx = dt*xv;
            float Bv[16], Cv[16];
#pragma unroll
            for (int q=0;q<4;q++){
                *(float4*)&Bv[q*4] = *(const float4*)&sBC[tt][q*4];
                *(float4*)&Cv[q*4] = *(const float4*)&sBC[tt][16+q*4];
            }
            float ya[4] = {0.f,0.f,0.f,0.f};
            if (pw){
                const float p = __expf(dt*a0);
                float e = p;
#pragma unroll
                for (int n=0;n<16;n++){
                    h[n] = fmaf(e, h[n], dtx*Bv[n]);
                    ya[n&3] = fmaf(h[n], Cv[n], ya[n&3]);
                    e *= p;
                }
            } else {
#pragma unroll
                for (int n=0;n<16;n++){
                    const float e = __expf(dt*a[n]);
                    h[n] = fmaf(e, h[n], dtx*Bv[n]);
                    ya[n&3] = fmaf(h[n], Cv[n], ya[n&3]);
                }
            }
            const float y = (ya[0]+ya[1]) + (ya[2]+ya[3]);
            S.Y[idx] = (y + Dd*xv) * siluf_(zv);
        }
    }
}

// ---------------- gated combine -> aug bf16 (A-side) --------------------------------
__global__ void combine_kernel(const float* __restrict__ yf, const float* __restrict__ yr,
                               const float* __restrict__ yg, __nv_bfloat16* __restrict__ o)
{
    const size_t i = (size_t)blockIdx.x*256 + threadIdx.x;
    const int d = (int)(i % D_INNER);
    const size_t rr = i / D_INNER;
    const int l = (int)(rr % L_SEQ);
    const int b = (int)(rr / L_SEQ);
    const size_t ridx = ((size_t)b*L_SEQ + (L_SEQ-1-l))*(size_t)D_INNER + d;
    const float v = (yf[i] + yr[ridx]) * siluf_(yg[i]);
    const __nv_bfloat16 hb = __float2bfloat16_rn(v);
    const __nv_bfloat16 lb = __float2bfloat16_rn(v - __bfloat162float(hb));
    __nv_bfloat16* p = o + rr*(size_t)(3*D_INNER) + d;
    p[0] = hb; p[D_INNER] = lb; p[2*D_INNER] = hb;       // A-side: hi|lo|hi
}

// ------------------------------- host driver ----------------------------------------
extern "C" void kernel_launch(void* const* d_in, const int* in_sizes, int n_in,
                              void* d_out, int out_size)
{
    const float* H    = (const float*)d_in[0];
    const float* AH   = (const float*)d_in[1];
    const float* Winp = (const float*)d_in[2];
    const float* Wing = (const float*)d_in[3];
    const float* convw[3] = { (const float*)d_in[4], (const float*)d_in[6], (const float*)d_in[8] };
    const float* convb[3] = { (const float*)d_in[5], (const float*)d_in[7], (const float*)d_in[9] };
    const float* xproj[3] = { (const float*)d_in[10], (const float*)d_in[11], (const float*)d_in[12] };
    const float* dtw[3]   = { (const float*)d_in[13], (const float*)d_in[15], (const float*)d_in[17] };
    const float* dtb[3]   = { (const float*)d_in[14], (const float*)d_in[16], (const float*)d_in[18] };
    const float* Alog[3]  = { (const float*)d_in[19], (const float*)d_in[20], (const float*)d_in[21] };
    const float* Dp[3]    = { (const float*)d_in[22], (const float*)d_in[23], (const float*)d_in[24] };
    const float* Wout = (const float*)d_in[25];
    float* out = (float*)d_out;

    float *p_xz, *p_axz, *p_xs, *p_u, *p_dbl, *p_y;
    __nv_bfloat16 *p_Haug, *p_AHaug, *p_Wiaug, *p_Wgaug, *p_xsaug, *p_Xpaug;
    __nv_bfloat16 *p_dtwaug, *p_dblaug, *p_Woaug, *p_combaug;
    cudaGetSymbolAddress((void**)&p_xz,     g_xz);
    cudaGetSymbolAddress((void**)&p_axz,    g_axz);
    cudaGetSymbolAddress((void**)&p_xs,     g_xs);
    cudaGetSymbolAddress((void**)&p_u,      g_u);
    cudaGetSymbolAddress((void**)&p_dbl,    g_dbl);
    cudaGetSymbolAddress((void**)&p_y,      g_y);
    cudaGetSymbolAddress((void**)&p_Haug,   g_Haug);
    cudaGetSymbolAddress((void**)&p_AHaug,  g_AHaug);
    cudaGetSymbolAddress((void**)&p_Wiaug,  g_Wiaug);
    cudaGetSymbolAddress((void**)&p_Wgaug,  g_Wgaug);
    cudaGetSymbolAddress((void**)&p_xsaug,  g_xsaug);
    cudaGetSymbolAddress((void**)&p_Xpaug,  g_Xpaug);
    cudaGetSymbolAddress((void**)&p_dtwaug, g_dtwaug);
    cudaGetSymbolAddress((void**)&p_dblaug, g_dblaug);
    cudaGetSymbolAddress((void**)&p_Woaug,  g_Woaug);
    cudaGetSymbolAddress((void**)&p_combaug,g_combaug);

    const size_t SXS   = (size_t)NTOK*D_INNER;
    const size_t SDBL  = (size_t)NTOK*64;
    const size_t SXSA  = (size_t)NTOK*3*D_INNER;
    const size_t SXPA  = (size_t)64*3*D_INNER;
    const size_t SDTWA = (size_t)D_INNER*3*DT_RANK;
    const size_t SDBLA = (size_t)NTOK*3*DT_RANK;

    auto splitA = [&](const float* s, __nv_bfloat16* dst, int K, int ld, size_t R){
        const int n4 = (int)(R*K/4);
        split_aug<0><<<(n4+255)/256, 256>>>(s, dst, K, ld, n4);
    };
    auto splitW = [&](const float* s, __nv_bfloat16* dst, int K, int ld, size_t R){
        const int n4 = (int)(R*K/4);
        split_aug<1><<<(n4+255)/256, 256>>>(s, dst, K, ld, n4);
    };

    // 0) augment operands: activations A-side [hi|lo|hi], weights W-side [hi|hi|lo]
    splitA(H,    p_Haug,  D_MODEL, D_MODEL, NTOK);
    splitA(AH,   p_AHaug, D_MODEL, D_MODEL, NTOK);
    splitW(Winp, p_Wiaug, D_MODEL, D_MODEL, D_XZ);
    splitW(Wing, p_Wgaug, D_MODEL, D_MODEL, D_XZ);
    for (int z=0; z<3; z++){
        splitW(xproj[z], p_Xpaug + z*SXPA, D_INNER, D_INNER, 64);
        splitW(dtw[z],   p_dtwaug + z*SDTWA, DT_RANK, DT_RANK, D_INNER);
    }
    splitW(Wout, p_Woaug, D_INNER, D_INNER, D_MODEL);

    // 1) in-projections: xz = H @ Winp^T ; axz = AH @ Wing^T   (K'=1536)
    {
        MG3 P; P.N = D_XZ; P.K3 = 3*D_MODEL;
        P.g[0] = { p_Haug,  p_Wiaug, nullptr, p_xz  };
        P.g[1] = { p_AHaug, p_Wgaug, nullptr, p_axz };
        P.g[2] = P.g[0];
        mma_gemm<128,false><<<dim3(D_XZ/128, NTOK/128, 2), 256>>>(P);
    }
    // 2) depthwise conv + silu (fp32 + aug bf16 out)
    {
        ConvB3 P;
        P.c[0] = { p_xz,  convw[0], convb[0], p_xs + 0*SXS, p_xsaug + 0*SXSA, 0 };
        P.c[1] = { p_xz,  convw[1], convb[1], p_xs + 1*SXS, p_xsaug + 1*SXSA, 1 };
        P.c[2] = { p_axz, convw[2], convb[2], p_xs + 2*SXS, p_xsaug + 2*SXSA, 0 };
        conv_silu_kernel<<<dim3(D_INNER/128, 32, 3), 128>>>(P);
    }
    // 3) x-projection (N=64, K'=3072): dbl = xs @ xproj^T
    {
        MG3 P; P.N = 64; P.K3 = 3*D_INNER;
        for (int z=0; z<3; z++)
            P.g[z] = { p_xsaug + z*SXSA, p_Xpaug + z*SXPA, nullptr, p_dbl + z*SDBL };
        mma_gemm<64,false><<<dim3(1, NTOK/128, 3), 256>>>(P);
    }
    // 3b) augment dbl[:, :32] (A-side) for the dt GEMM
    for (int z=0; z<3; z++)
        splitA(p_dbl + z*SDBL, p_dblaug + z*SDBLA, DT_RANK, 64, NTOK);
    // 4) dt-projection (K'=96): u = dbl_low @ dtw^T + dtb
    {
        MG3 P; P.N = D_INNER; P.K3 = 3*DT_RANK;
        for (int z=0; z<3; z++)
            P.g[z] = { p_dblaug + z*SDBLA, p_dtwaug + z*SDTWA, dtb[z], p_u + z*SXS };
        mma_gemm<128,true><<<dim3(D_INNER/128, NTOK/128, 3), 256>>>(P);
    }
    // 5) selective scan
    {
        ScanB3 P;
        P.s[0] = { p_u + 0*SXS, p_xs + 0*SXS, p_dbl + 0*SDBL, p_xz,  Alog[0], Dp[0], p_y + 0*SXS, 0 };
        P.s[1] = { p_u + 1*SXS, p_xs + 1*SXS, p_dbl + 1*SDBL, p_xz,  Alog[1], Dp[1], p_y + 1*SXS, 1 };
        P.s[2] = { p_u + 2*SXS, p_xs + 2*SXS, p_dbl + 2*SDBL, p_axz, Alog[2], Dp[2], p_y + 2*SXS, 0 };
        scan_kernel<<<dim3(D_INNER/128, B_SZ, 3), 128>>>(P);
    }
    // 6) combine -> aug bf16 (A-side)
    combine_kernel<<<(unsigned)(SXS/256), 256>>>(p_y + 0*SXS, p_y + 1*SXS, p_y + 2*SXS, p_combaug);
    // 7) out-projection (K'=3072): out = comb @ Wout^T
    {
        MG3 P; P.N = D_MODEL; P.K3 = 3*D_INNER;
        P.g[0] = { p_combaug, p_Woaug, nullptr, out };
        P.g[1] = P.g[0]; P.g[2] = P.g[0];
        mma_gemm<128,false><<<dim3(D_MODEL/128, NTOK/128, 1), 256>>>(P);
    }
    (void)in_sizes; (void)n_in; (void)out_size;
}

// round 5
// speedup vs baseline: 1.3447x; 1.0401x over previous
#include <cuda_runtime.h>
#include <cuda_bf16.h>
#include <cstdint>

#define L_SEQ   4096
#define B_SZ    4
#define D_MODEL 512
#define D_INNER 1024
#define D_XZ    2048
#define NTOK    (B_SZ*L_SEQ)   /* 16384 */
#define DT_RANK 32
#define D_STATE 16

// ---------------- scratch (static device allocations; harness forbids cudaMalloc) ---
__device__ float g_xz  [(size_t)NTOK*D_XZ];
__device__ float g_axz [(size_t)NTOK*D_XZ];
__device__ float g_xs  [3][(size_t)NTOK*D_INNER];      // conv+silu x (fp32, for scan)
__device__ float g_u   [3][(size_t)NTOK*D_INNER];      // dt logits
__device__ float g_dbl [3][(size_t)NTOK*64];           // dt_low | B | C
__device__ float g_y   [3][(size_t)NTOK*D_INNER];      // branch outputs
// augmented bf16 operands, K' = 3K.  A-side: [hi|lo|hi].  W-side: [hi|hi|lo].
__device__ __nv_bfloat16 g_Haug [(size_t)NTOK*3*D_MODEL];
__device__ __nv_bfloat16 g_AHaug[(size_t)NTOK*3*D_MODEL];
__device__ __nv_bfloat16 g_Wiaug[(size_t)D_XZ*3*D_MODEL];
__device__ __nv_bfloat16 g_Wgaug[(size_t)D_XZ*3*D_MODEL];
__device__ __nv_bfloat16 g_xsaug[3][(size_t)NTOK*3*D_INNER];
__device__ __nv_bfloat16 g_Xpaug[3][(size_t)64*3*D_INNER];
__device__ __nv_bfloat16 g_dtwaug[3][(size_t)D_INNER*3*DT_RANK];
__device__ __nv_bfloat16 g_dblaug[3][(size_t)NTOK*3*DT_RANK];
__device__ __nv_bfloat16 g_Woaug[(size_t)D_MODEL*3*D_INNER];
__device__ __nv_bfloat16 g_combaug[(size_t)NTOK*3*D_INNER];

__device__ __forceinline__ float sigmoidf_(float x){ return 1.0f/(1.0f+__expf(-x)); }
__device__ __forceinline__ float siluf_(float x){ return x*sigmoidf_(x); }

__device__ __forceinline__ uint32_t smem_u32(const void* p){
    uint32_t a;
    asm("{ .reg .u64 t; cvta.to.shared.u64 t, %1; cvt.u32.u64 %0, t; }" : "=r"(a) : "l"(p));
    return a;
}
__device__ __forceinline__ void cp_async16(uint32_t dst, const void* src){
    asm volatile("cp.async.cg.shared.global [%0], [%1], 16;\n" :: "r"(dst), "l"(src));
}

// ====== split: fp32 [R,K] (ld_src) -> bf16 aug [R, 3K] =============================
// MODE 0 (A-side): [hi | lo | hi].   MODE 1 (W-side): [hi | hi | lo].
template<int MODE>
__global__ void split_aug(const float* __restrict__ src, __nv_bfloat16* __restrict__ dst,
                          int K, int ld_src, int n4total)
{
    const int i = blockIdx.x*256 + threadIdx.x;
    if (i >= n4total) return;
    const int kq = K >> 2;
    const int r  = i / kq, k4 = i % kq;
    const float4 v = *(const float4*)(src + (size_t)r*ld_src + k4*4);
    const float f[4] = {v.x, v.y, v.z, v.w};
    __align__(8) __nv_bfloat16 hh[4], ll[4];
#pragma unroll
    for (int j=0;j<4;j++){
        hh[j] = __float2bfloat16_rn(f[j]);
        ll[j] = __float2bfloat16_rn(f[j] - __bfloat162float(hh[j]));
    }
    __nv_bfloat16* o = dst + (size_t)r*3*K + k4*4;
    if (MODE == 0){
        *(uint2*)(o)       = *(const uint2*)hh;
        *(uint2*)(o + K)   = *(const uint2*)ll;
        *(uint2*)(o + 2*K) = *(const uint2*)hh;
    } else {
        *(uint2*)(o)       = *(const uint2*)hh;
        *(uint2*)(o + K)   = *(const uint2*)hh;
        *(uint2*)(o + 2*K) = *(const uint2*)ll;
    }
}

// ================= mma.sync bf16 GEMM: C[m,n] = A[m,:]·W[n,:] (+bias) ================
// A: [M, K3] bf16 row-major, W: [N, K3] bf16 row-major (= B col-major for mma).
// BM=128, BN in {64,128}, BK=32, 3-stage cp.async pipeline, 256 threads, 2 CTA/SM.
struct MG  { const __nv_bfloat16 *A, *W; const float* bias; float* C; };
struct MG3 { MG g[3]; int N, K3; };

template<int BN, bool BIAS>
__global__ void __launch_bounds__(256, 2) mma_gemm(MG3 P)
{
    constexpr int NS  = 3;
    constexpr int WN  = BN/2;
    constexpr int NTL = WN/8;            // 8 (BN=128) or 4 (BN=64)
    constexpr int SAE = 128*40;          // A elems per stage (80B rows)
    constexpr int SWE = BN*40;
    const MG g = P.g[blockIdx.z];
    const int N = P.N, K3 = P.K3;
    const int tid  = threadIdx.x;
    const int lane = tid & 31, wid = tid >> 5;
    const int warp_m = wid & 3, warp_n = wid >> 2;
    const int m0 = blockIdx.y * 128, n0 = blockIdx.x * BN;

    extern __shared__ __align__(128) __nv_bfloat16 sm[];
    const uint32_t base = smem_u32(sm);
    uint32_t aB[NS], wB[NS];
#pragma unroll
    for (int s=0;s<NS;s++){
        aB[s] = base + (uint32_t)(s*(SAE+SWE)*2);
        wB[s] = aB[s] + SAE*2;
    }

    float acc[2][NTL][4];
#pragma unroll
    for (int mt=0;mt<2;mt++)
#pragma unroll
        for (int nt=0;nt<NTL;nt++)
#pragma unroll
            for (int j=0;j<4;j++) acc[mt][nt][j]=0.f;

    const int nk = K3 / 32;

    auto load_tiles = [&](int s, int kt){
        const int k0 = kt*32;
        const __nv_bfloat16* Ap = g.A + (size_t)m0*K3 + k0;
#pragma unroll
        for (int q = tid; q < 512; q += 256){
            const int r = q>>2, c = q&3;
            cp_async16(aB[s] + r*80 + c*16, Ap + (size_t)r*K3 + c*8);
        }
        const __nv_bfloat16* Wp = g.W + (size_t)n0*K3 + k0;
#pragma unroll
        for (int q = tid; q < BN*4; q += 256){
            const int r = q>>2, c = q&3;
            cp_async16(wB[s] + r*80 + c*16, Wp + (size_t)r*K3 + c*8);
        }
        asm volatile("cp.async.commit_group;\n" ::: "memory");
    };

    // prologue: stages 0..NS-2
#pragma unroll
    for (int s=0; s<NS-1; s++) load_tiles(s, s);

    const int lr       = lane & 7;
    const int arow_off = ((lane>>3)&1)*8 + lr;
    const int akb      = (lane>>4)*16;
    const int brow_off = ((lane>>4)&1)*8 + lr;       // x4 W: matrix pair rows
    const int bkb      = ((lane>>3)&1)*16;

    for (int kt = 0; kt < nk; kt++){
        asm volatile("cp.async.wait_group 1;\n" ::: "memory");
        __syncthreads();
        const int pf = kt + NS - 1;
        if (pf < nk) load_tiles(pf % NS, pf);
        else asm volatile("cp.async.commit_group;\n" ::: "memory");

        const uint32_t aBc = aB[kt % NS], wBc = wB[kt % NS];
#pragma unroll
        for (int ks = 0; ks < 2; ks++){
            uint32_t a[2][4];
#pragma unroll
            for (int mt=0; mt<2; mt++){
                const uint32_t addr = aBc + (warp_m*32 + mt*16 + arow_off)*80 + ks*32 + akb;
                asm volatile("ldmatrix.sync.aligned.m8n8.x4.shared.b16 {%0,%1,%2,%3}, [%4];"
                    : "=r"(a[mt][0]),"=r"(a[mt][1]),"=r"(a[mt][2]),"=r"(a[mt][3]) : "r"(addr));
            }
            uint32_t b[NTL][2];
#pragma unroll
            for (int ntp=0; ntp<NTL/2; ntp++){
                const uint32_t addr = wBc + (warp_n*WN + ntp*16 + brow_off)*80 + ks*32 + bkb;
                asm volatile("ldmatrix.sync.aligned.m8n8.x4.shared.b16 {%0,%1,%2,%3}, [%4];"
                    : "=r"(b[2*ntp][0]),"=r"(b[2*ntp][1]),
                      "=r"(b[2*ntp+1][0]),"=r"(b[2*ntp+1][1]) : "r"(addr));
            }
#pragma unroll
            for (int mt=0; mt<2; mt++)
#pragma unroll
                for (int nt=0; nt<NTL; nt++){
                    asm volatile("mma.sync.aligned.m16n8k16.row.col.f32.bf16.bf16.f32 "
                        "{%0,%1,%2,%3}, {%4,%5,%6,%7}, {%8,%9}, {%0,%1,%2,%3};"
                        : "+f"(acc[mt][nt][0]),"+f"(acc[mt][nt][1]),
                          "+f"(acc[mt][nt][2]),"+f"(acc[mt][nt][3])
                        : "r"(a[mt][0]),"r"(a[mt][1]),"r"(a[mt][2]),"r"(a[mt][3]),
                          "r"(b[nt][0]),"r"(b[nt][1]));
                }
        }
        __syncthreads();
    }

    // epilogue
    const int lr4 = lane>>2, lc2 = (lane&3)*2;
#pragma unroll
    for (int mt=0; mt<2; mt++){
        const int r0 = m0 + warp_m*32 + mt*16 + lr4;
#pragma unroll
        for (int nt=0; nt<NTL; nt++){
            const int col = n0 + warp_n*WN + nt*8 + lc2;
            float b0=0.f, b1=0.f;
            if (BIAS){ b0 = g.bias[col]; b1 = g.bias[col+1]; }
            float2 v0, v1;
            v0.x = acc[mt][nt][0]+b0; v0.y = acc[mt][nt][1]+b1;
            v1.x = acc[mt][nt][2]+b0; v1.y = acc[mt][nt][3]+b1;
            *(float2*)(g.C + (size_t)r0*N + col)     = v0;
            *(float2*)(g.C + (size_t)(r0+8)*N + col) = v1;
        }
    }
}

// ---------------- depthwise causal conv (k=4) + SiLU + aug bf16 out (A-side) --------
struct ConvB { const float* X; const float* w; const float* b;
               float* xs; __nv_bfloat16* xsaug; int rev; };
struct ConvB3 { ConvB c[3]; };
#define CCH 512

__global__ void conv_silu_kernel(ConvB3 P)
{
    const ConvB c = P.c[blockIdx.z];
    const int d  = blockIdx.x*128 + threadIdx.x;
    const int bt = blockIdx.y;
    const int b  = bt >> 3;
    const int t0 = (bt & 7)*CCH;
    const float w0=c.w[d*4+0], w1=c.w[d*4+1], w2=c.w[d*4+2], w3=c.w[d*4+3];
    const float bb=c.b[d];
    const size_t bL = (size_t)b*L_SEQ;

    auto X = [&](int i)->float{
        if (i < 0) return 0.f;
        const int l = c.rev ? (L_SEQ-1-i) : i;
        return c.X[(bL + l)*(size_t)D_XZ + d];
    };
    float x0=X(t0-3), x1=X(t0-2), x2=X(t0-1);
#pragma unroll 4
    for (int t=t0; t<t0+CCH; t++){
        const float x3 = X(t);
        const float v = fmaf(w0,x0,fmaf(w1,x1,fmaf(w2,x2,fmaf(w3,x3,bb))));
        const float s = siluf_(v);
        c.xs[(bL+t)*(size_t)D_INNER + d] = s;
        const __nv_bfloat16 hb = __float2bfloat16_rn(s);
        const __nv_bfloat16 lb = __float2bfloat16_rn(s - __bfloat162float(hb));
        __nv_bfloat16* o = c.xsaug + (bL+t)*(size_t)(3*D_INNER) + d;
        o[0] = hb; o[D_INNER] = lb; o[2*D_INNER] = hb;   // A-side: hi|lo|hi
        x0=x1; x1=x2; x2=x3;
    }
}

// ---------------- fused selective scan (3 branches in one launch) -------------------
struct ScanB { const float* U; const float* XS; const float* DBL; const float* XZb;
               const float* Alog; const float* Dp; float* Y; int rev; };
struct ScanB3 { ScanB s[3]; };

__global__ void scan_kernel(ScanB3 P)
{
    constexpr int TC = 128;
    __shared__ float sBC[TC][32];
    const ScanB S = P.s[blockIdx.z];
    const int tid = threadIdx.x;
    const int d   = blockIdx.x*128 + tid;
    const int b   = blockIdx.y;
    const size_t bL = (size_t)b * L_SEQ;

    float a[16];
#pragma unroll
    for (int n=0;n<16;n++) a[n] = -__expf(S.Alog[d*16+n]);
    const float a0 = a[0];
    bool pw = fabsf(a0) > 1e-20f;
#pragma unroll
    for (int n=0;n<16;n++){
        const float r = a[n]/a0;
        pw = pw && (fabsf(r - (float)(n+1)) < 1e-4f);
    }
    const float Dd = S.Dp[d];
    float h[16];
#pragma unroll
    for (int n=0;n<16;n++) h[n]=0.f;

    for (int t0=0;t0<L_SEQ;t0+=TC){
        __syncthreads();
#pragma unroll
        for (int r=0;r<(TC*32)/(4*128);r++){
            const int slot = tid + r*128;
            const int tt = slot>>3, q = slot&7;
            const float4 v = *(const float4*)(S.DBL + (bL + t0 + tt)*64 + 32 + q*4);
            *(float4*)&sBC[tt][q*4] = v;
        }
        __syncthreads();
#pragma unroll 4
        for (int tt=0;tt<TC;tt++){
            const int t = t0+tt;
            const size_t idx = (bL + t)*(size_t)D_INNER + d;
            const float u  = S.U[idx];
            const float xv = S.XS[idx];
            const int   lz = S.rev ? (L_SEQ-1-t) : t;
            const float zv = S.XZb[(bL+lz)*(size_t)D_XZ + D_INNER + d];
            const float dt = (u > 20.f) ? u : log1pf(__expf(u));
            const float dtx = dt*xv;
            float Bv[16], Cv[16];
#pragma unroll
            for (int q=0;q<4;q++){
                *(float4*)&Bv[q*4] = *(const float4*)&sBC[tt][q*4];
                *(float4*)&Cv[q*4] = *(const float4*)&sBC[tt][16+q*4];
            }
            float ya[4] = {0.f,0.f,0.f,0.f};
            if (pw){
                const float p = __expf(dt*a0);
                float e = p;
#pragma unroll
                for (int n=0;n<16;n++){
                    h[n] = fmaf(e, h[n], dtx*Bv[n]);
                    ya[n&3] = fmaf(h[n], Cv[n], ya[n&3]);
                    e *= p;
                }
            } else {
#pragma unroll
                for (int n=0;n<16;n++){
                    const float e = __expf(dt*a[n]);
                    h[n] = fmaf(e, h[n], dtx*Bv[n]);
                    ya[n&3] = fmaf(h[n], Cv[n], ya[n&3]);
                }
            }
            const float y = (ya[0]+ya[1]) + (ya[2]+ya[3]);
            S.Y[idx] = (y + Dd*xv) * siluf_(zv);
        }
    }
}

// ---------------- gated combine -> aug bf16 (A-side) --------------------------------
__global__ void combine_kernel(const float* __restrict__ yf, const float* __restrict__ yr,
                               const float* __restrict__ yg, __nv_bfloat16* __restrict__ o)
{
    const size_t i = (size_t)blockIdx.x*256 + threadIdx.x;
    const int d = (int)(i % D_INNER);
    const size_t rr = i / D_INNER;
    const int l = (int)(rr % L_SEQ);
    const int b = (int)(rr / L_SEQ);
    const size_t ridx = ((size_t)b*L_SEQ + (L_SEQ-1-l))*(size_t)D_INNER + d;
    const float v = (yf[i] + yr[ridx]) * siluf_(yg[i]);
    const __nv_bfloat16 hb = __float2bfloat16_rn(v);
    const __nv_bfloat16 lb = __float2bfloat16_rn(v - __bfloat162float(hb));
    __nv_bfloat16* p = o + rr*(size_t)(3*D_INNER) + d;
    p[0] = hb; p[D_INNER] = lb; p[2*D_INNER] = hb;       // A-side: hi|lo|hi
}

// ------------------------------- host driver ----------------------------------------
extern "C" void kernel_launch(void* const* d_in, const int* in_sizes, int n_in,
                              void* d_out, int out_size)
{
    const float* H    = (const float*)d_in[0];
    const float* AH   = (const float*)d_in[1];
    const float* Winp = (const float*)d_in[2];
    const float* Wing = (const float*)d_in[3];
    const float* convw[3] = { (const float*)d_in[4], (const float*)d_in[6], (const float*)d_in[8] };
    const float* convb[3] = { (const float*)d_in[5], (const float*)d_in[7], (const float*)d_in[9] };
    const float* xproj[3] = { (const float*)d_in[10], (const float*)d_in[11], (const float*)d_in[12] };
    const float* dtw[3]   = { (const float*)d_in[13], (const float*)d_in[15], (const float*)d_in[17] };
    const float* dtb[3]   = { (const float*)d_in[14], (const float*)d_in[16], (const float*)d_in[18] };
    const float* Alog[3]  = { (const float*)d_in[19], (const float*)d_in[20], (const float*)d_in[21] };
    const float* Dp[3]    = { (const float*)d_in[22], (const float*)d_in[23], (const float*)d_in[24] };
    const float* Wout = (const float*)d_in[25];
    float* out = (float*)d_out;

    float *p_xz, *p_axz, *p_xs, *p_u, *p_dbl, *p_y;
    __nv_bfloat16 *p_Haug, *p_AHaug, *p_Wiaug, *p_Wgaug, *p_xsaug, *p_Xpaug;
    __nv_bfloat16 *p_dtwaug, *p_dblaug, *p_Woaug, *p_combaug;
    cudaGetSymbolAddress((void**)&p_xz,     g_xz);
    cudaGetSymbolAddress((void**)&p_axz,    g_axz);
    cudaGetSymbolAddress((void**)&p_xs,     g_xs);
    cudaGetSymbolAddress((void**)&p_u,      g_u);
    cudaGetSymbolAddress((void**)&p_dbl,    g_dbl);
    cudaGetSymbolAddress((void**)&p_y,      g_y);
    cudaGetSymbolAddress((void**)&p_Haug,   g_Haug);
    cudaGetSymbolAddress((void**)&p_AHaug,  g_AHaug);
    cudaGetSymbolAddress((void**)&p_Wiaug,  g_Wiaug);
    cudaGetSymbolAddress((void**)&p_Wgaug,  g_Wgaug);
    cudaGetSymbolAddress((void**)&p_xsaug,  g_xsaug);
    cudaGetSymbolAddress((void**)&p_Xpaug,  g_Xpaug);
    cudaGetSymbolAddress((void**)&p_dtwaug, g_dtwaug);
    cudaGetSymbolAddress((void**)&p_dblaug, g_dblaug);
    cudaGetSymbolAddress((void**)&p_Woaug,  g_Woaug);
    cudaGetSymbolAddress((void**)&p_combaug,g_combaug);

    const size_t SXS   = (size_t)NTOK*D_INNER;
    const size_t SDBL  = (size_t)NTOK*64;
    const size_t SXSA  = (size_t)NTOK*3*D_INNER;
    const size_t SXPA  = (size_t)64*3*D_INNER;
    const size_t SDTWA = (size_t)D_INNER*3*DT_RANK;
    const size_t SDBLA = (size_t)NTOK*3*DT_RANK;

    const int SMEM128 = 3*(128*40 + 128*40)*2;   // 61440 B
    const int SMEM64  = 3*(128*40 +  64*40)*2;   // 46080 B
    cudaFuncSetAttribute(mma_gemm<128,false>, cudaFuncAttributeMaxDynamicSharedMemorySize, SMEM128);
    cudaFuncSetAttribute(mma_gemm<128,true>,  cudaFuncAttributeMaxDynamicSharedMemorySize, SMEM128);
    cudaFuncSetAttribute(mma_gemm<64,false>,  cudaFuncAttributeMaxDynamicSharedMemorySize, SMEM64);

    auto splitA = [&](const float* s, __nv_bfloat16* dst, int K, int ld, size_t R){
        const int n4 = (int)(R*K/4);
        split_aug<0><<<(n4+255)/256, 256>>>(s, dst, K, ld, n4);
    };
    auto splitW = [&](const float* s, __nv_bfloat16* dst, int K, int ld, size_t R){
        const int n4 = (int)(R*K/4);
        split_aug<1><<<(n4+255)/256, 256>>>(s, dst, K, ld, n4);
    };

    // 0) augment operands: activations A-side [hi|lo|hi], weights W-side [hi|hi|lo]
    splitA(H,    p_Haug,  D_MODEL, D_MODEL, NTOK);
    splitA(AH,   p_AHaug, D_MODEL, D_MODEL, NTOK);
    splitW(Winp, p_Wiaug, D_MODEL, D_MODEL, D_XZ);
    splitW(Wing, p_Wgaug, D_MODEL, D_MODEL, D_XZ);
    for (int z=0; z<3; z++){
        splitW(xproj[z], p_Xpaug + z*SXPA, D_INNER, D_INNER, 64);
        splitW(dtw[z],   p_dtwaug + z*SDTWA, DT_RANK, DT_RANK, D_INNER);
    }
    splitW(Wout, p_Woaug, D_INNER, D_INNER, D_MODEL);

    // 1) in-projections: xz = H @ Winp^T ; axz = AH @ Wing^T   (K'=1536)
    {
        MG3 P; P.N = D_XZ; P.K3 = 3*D_MODEL;
        P.g[0] = { p_Haug,  p_Wiaug, nullptr, p_xz  };
        P.g[1] = { p_AHaug, p_Wgaug, nullptr, p_axz };
        P.g[2] = P.g[0];
        mma_gemm<128,false><<<dim3(D_XZ/128, NTOK/128, 2), 256, SMEM128>>>(P);
    }
    // 2) depthwise conv + silu (fp32 + aug bf16 out)
    {
        ConvB3 P;
        P.c[0] = { p_xz,  convw[0], convb[0], p_xs + 0*SXS, p_xsaug + 0*SXSA, 0 };
        P.c[1] = { p_xz,  convw[1], convb[1], p_xs + 1*SXS, p_xsaug + 1*SXSA, 1 };
        P.c[2] = { p_axz, convw[2], convb[2], p_xs + 2*SXS, p_xsaug + 2*SXSA, 0 };
        conv_silu_kernel<<<dim3(D_INNER/128, 32, 3), 128>>>(P);
    }
    // 3) x-projection (N=64, K'=3072): dbl = xs @ xproj^T
    {
        MG3 P; P.N = 64; P.K3 = 3*D_INNER;
        for (int z=0; z<3; z++)
            P.g[z] = { p_xsaug + z*SXSA, p_Xpaug + z*SXPA, nullptr, p_dbl + z*SDBL };
        mma_gemm<64,false><<<dim3(1, NTOK/128, 3), 256, SMEM64>>>(P);
    }
    // 3b) augment dbl[:, :32] (A-side) for the dt GEMM
    for (int z=0; z<3; z++)
        splitA(p_dbl + z*SDBL, p_dblaug + z*SDBLA, DT_RANK, 64, NTOK);
    // 4) dt-projection (K'=96): u = dbl_low @ dtw^T + dtb
    {
        MG3 P; P.N = D_INNER; P.K3 = 3*DT_RANK;
        for (int z=0; z<3; z++)
            P.g[z] = { p_dblaug + z*SDBLA, p_dtwaug + z*SDTWA, dtb[z], p_u + z*SXS };
        mma_gemm<128,true><<<dim3(D_INNER/128, NTOK/128, 3), 256, SMEM128>>>(P);
    }
    // 5) selective scan
    {
        ScanB3 P;
        P.s[0] = { p_u + 0*SXS, p_xs + 0*SXS, p_dbl + 0*SDBL, p_xz,  Alog[0], Dp[0], p_y + 0*SXS, 0 };
        P.s[1] = { p_u + 1*SXS, p_xs + 1*SXS, p_dbl + 1*SDBL, p_xz,  Alog[1], Dp[1], p_y + 1*SXS, 1 };
        P.s[2] = { p_u + 2*SXS, p_xs + 2*SXS, p_dbl + 2*SDBL, p_axz, Alog[2], Dp[2], p_y + 2*SXS, 0 };
        scan_kernel<<<dim3(D_INNER/128, B_SZ, 3), 128>>>(P);
    }
    // 6) combine -> aug bf16 (A-side)
    combine_kernel<<<(unsigned)(SXS/256), 256>>>(p_y + 0*SXS, p_y + 1*SXS, p_y + 2*SXS, p_combaug);
    // 7) out-projection (K'=3072): out = comb @ Wout^T
    {
        MG3 P; P.N = D_MODEL; P.K3 = 3*D_INNER;
        P.g[0] = { p_combaug, p_Woaug, nullptr, out };
        P.g[1] = P.g[0]; P.g[2] = P.g[0];
        mma_gemm<128,false><<<dim3(D_MODEL/128, NTOK/128, 1), 256, SMEM128>>>(P);
    }
    (void)in_sizes; (void)n_in; (void)out_size;
}

// round 6
// speedup vs baseline: 1.4909x; 1.1088x over previous
#include <cuda_runtime.h>
#include <cuda_fp16.h>
#include <cstdint>

#define L_SEQ   4096
#define B_SZ    4
#define D_MODEL 512
#define D_INNER 1024
#define D_XZ    2048
#define NTOK    (B_SZ*L_SEQ)   /* 16384 */
#define DT_RANK 32
#define D_STATE 16

// ---------------- scratch (static device allocations) -------------------------------
__device__ float g_xz  [(size_t)NTOK*D_XZ];
__device__ float g_axz [(size_t)NTOK*D_XZ];
__device__ float g_xs  [3][(size_t)NTOK*D_INNER];      // conv+silu x (fp32, for scan)
__device__ float g_u   [3][(size_t)NTOK*D_INNER];      // dt logits
__device__ float g_dbl [3][(size_t)NTOK*64];           // dt_low | B | C (fp32 for scan)
__device__ float g_y   [3][(size_t)NTOK*D_INNER];      // branch outputs
// fp16 operands. A-side: [ah | al] (K2 = 2K). W-side: single fp16 copy [N, K].
__device__ __half g_Haug [(size_t)NTOK*2*D_MODEL];
__device__ __half g_AHaug[(size_t)NTOK*2*D_MODEL];
__device__ __half g_Wi16 [(size_t)D_XZ*D_MODEL];
__device__ __half g_Wg16 [(size_t)D_XZ*D_MODEL];
__device__ __half g_xsaug[3][(size_t)NTOK*2*D_INNER];
__device__ __half g_Xp16 [3][(size_t)64*D_INNER];
__device__ __half g_dtw16[3][(size_t)D_INNER*DT_RANK];
__device__ __half g_dblaug[3][(size_t)NTOK*64];        // [ah(32)|al(32)] of dt_low
__device__ __half g_Wo16 [(size_t)D_MODEL*D_INNER];
__device__ __half g_combaug[(size_t)NTOK*2*D_INNER];

__device__ __forceinline__ float sigmoidf_(float x){ return 1.0f/(1.0f+__expf(-x)); }
__device__ __forceinline__ float siluf_(float x){ return x*sigmoidf_(x); }

__device__ __forceinline__ uint32_t smem_u32(const void* p){
    uint32_t a;
    asm("{ .reg .u64 t; cvta.to.shared.u64 t, %1; cvt.u32.u64 %0, t; }" : "=r"(a) : "l"(p));
    return a;
}
__device__ __forceinline__ void cp_async16(uint32_t dst, const void* src){
    asm volatile("cp.async.cg.shared.global [%0], [%1], 16;\n" :: "r"(dst), "l"(src));
}

// ====== W convert: fp32 -> fp16 (plain) ============================================
__global__ void convW(const float* __restrict__ src, __half* __restrict__ dst, int n4)
{
    const int i = blockIdx.x*256 + threadIdx.x;
    if (i >= n4) return;
    const float4 v = ((const float4*)src)[i];
    __align__(8) __half h[4] = { __float2half_rn(v.x), __float2half_rn(v.y),
                                 __float2half_rn(v.z), __float2half_rn(v.w) };
    *(uint2*)(dst + (size_t)i*4) = *(const uint2*)h;
}
struct CJob { const float* src; __half* dst; int n4; };
struct CJobs7 { CJob j[7]; };
__global__ void convW_multi(CJobs7 J)
{
    const CJob jb = J.j[blockIdx.z];
    const int i = blockIdx.x*256 + threadIdx.x;
    if (i >= jb.n4) return;
    const float4 v = ((const float4*)jb.src)[i];
    __align__(8) __half h[4] = { __float2half_rn(v.x), __float2half_rn(v.y),
                                 __float2half_rn(v.z), __float2half_rn(v.w) };
    *(uint2*)(jb.dst + (size_t)i*4) = *(const uint2*)h;
}

// ====== A split: fp32 [R,K] -> fp16 [R, 2K] = [ah | al] ============================
__global__ void splitA16(const float* __restrict__ src, __half* __restrict__ dst,
                         int K, int n4total)
{
    const int i = blockIdx.x*256 + threadIdx.x;
    if (i >= n4total) return;
    const int kq = K >> 2;
    const int r  = i / kq, k4 = i % kq;
    const float4 v = *(const float4*)(src + (size_t)r*K + k4*4);
    const float f[4] = {v.x, v.y, v.z, v.w};
    __align__(8) __half hh[4], ll[4];
#pragma unroll
    for (int j=0;j<4;j++){
        hh[j] = __float2half_rn(f[j]);
        ll[j] = __float2half_rn(f[j] - __half2float(hh[j]));
    }
    __half* o = dst + (size_t)r*2*K + k4*4;
    *(uint2*)(o)     = *(const uint2*)hh;
    *(uint2*)(o + K) = *(const uint2*)ll;
}

// ================= mma.sync fp16 GEMM: C[m,n] = (ah+al)[m,:]·W16[n,:] (+bias) =======
// A: [M, K2=2K] fp16 row-major ([ah|al]).  W: [N, K] fp16 row-major, read twice via wrap.
// BM=128, BN in {64,128}, BK=32, 3-stage cp.async pipeline, 256 threads.
struct MG  { const __half *A, *W; const float* bias; float* C; __half* Daug; };
struct MG3 { MG g[3]; int N, K2, KW; };

template<int BN, bool BIAS, bool DBLAUG>
__global__ void __launch_bounds__(256, 2) mma_gemm(MG3 P)
{
    constexpr int NS  = 3;
    constexpr int WN  = BN/2;
    constexpr int NTL = WN/8;
    constexpr int SAE = 128*40;          // halves per A stage (80B rows)
    constexpr int SWE = BN*40;
    const MG g = P.g[blockIdx.z];
    const int N = P.N, K2 = P.K2, KW = P.KW;
    const int tid  = threadIdx.x;
    const int lane = tid & 31, wid = tid >> 5;
    const int warp_m = wid & 3, warp_n = wid >> 2;
    const int m0 = blockIdx.y * 128, n0 = blockIdx.x * BN;

    extern __shared__ __align__(128) __half sm[];
    const uint32_t base = smem_u32(sm);
    uint32_t aB[NS], wB[NS];
#pragma unroll
    for (int s=0;s<NS;s++){
        aB[s] = base + (uint32_t)(s*(SAE+SWE)*2);
        wB[s] = aB[s] + SAE*2;
    }

    float acc[2][NTL][4];
#pragma unroll
    for (int mt=0;mt<2;mt++)
#pragma unroll
        for (int nt=0;nt<NTL;nt++)
#pragma unroll
            for (int j=0;j<4;j++) acc[mt][nt][j]=0.f;

    const int nk = K2 / 32;

    auto load_tiles = [&](int s, int kt){
        const int k0 = kt*32;
        const int k0w = (k0 >= KW) ? (k0 - KW) : k0;
        const __half* Ap = g.A + (size_t)m0*K2 + k0;
#pragma unroll
        for (int q = tid; q < 512; q += 256){
            const int r = q>>2, c = q&3;
            cp_async16(aB[s] + r*80 + c*16, Ap + (size_t)r*K2 + c*8);
        }
        const __half* Wp = g.W + (size_t)n0*KW + k0w;
#pragma unroll
        for (int q = tid; q < BN*4; q += 256){
            const int r = q>>2, c = q&3;
            cp_async16(wB[s] + r*80 + c*16, Wp + (size_t)r*KW + c*8);
        }
        asm volatile("cp.async.commit_group;\n" ::: "memory");
    };

#pragma unroll
    for (int s=0; s<NS-1; s++) load_tiles(s, s);

    const int lr       = lane & 7;
    const int arow_off = ((lane>>3)&1)*8 + lr;
    const int akb      = (lane>>4)*16;
    const int brow_off = ((lane>>4)&1)*8 + lr;
    const int bkb      = ((lane>>3)&1)*16;

    for (int kt = 0; kt < nk; kt++){
        asm volatile("cp.async.wait_group 1;\n" ::: "memory");
        __syncthreads();
        const int pf = kt + NS - 1;
        if (pf < nk) load_tiles(pf % NS, pf);
        else asm volatile("cp.async.commit_group;\n" ::: "memory");

        const uint32_t aBc = aB[kt % NS], wBc = wB[kt % NS];
#pragma unroll
        for (int ks = 0; ks < 2; ks++){
            uint32_t a[2][4];
#pragma unroll
            for (int mt=0; mt<2; mt++){
                const uint32_t addr = aBc + (warp_m*32 + mt*16 + arow_off)*80 + ks*32 + akb;
                asm volatile("ldmatrix.sync.aligned.m8n8.x4.shared.b16 {%0,%1,%2,%3}, [%4];"
                    : "=r"(a[mt][0]),"=r"(a[mt][1]),"=r"(a[mt][2]),"=r"(a[mt][3]) : "r"(addr));
            }
            uint32_t b[NTL][2];
#pragma unroll
            for (int ntp=0; ntp<NTL/2; ntp++){
                const uint32_t addr = wBc + (warp_n*WN + ntp*16 + brow_off)*80 + ks*32 + bkb;
                asm volatile("ldmatrix.sync.aligned.m8n8.x4.shared.b16 {%0,%1,%2,%3}, [%4];"
                    : "=r"(b[2*ntp][0]),"=r"(b[2*ntp][1]),
                      "=r"(b[2*ntp+1][0]),"=r"(b[2*ntp+1][1]) : "r"(addr));
            }
#pragma unroll
            for (int mt=0; mt<2; mt++)
#pragma unroll
                for (int nt=0; nt<NTL; nt++){
                    asm volatile("mma.sync.aligned.m16n8k16.row.col.f32.f16.f16.f32 "
                        "{%0,%1,%2,%3}, {%4,%5,%6,%7}, {%8,%9}, {%0,%1,%2,%3};"
                        : "+f"(acc[mt][nt][0]),"+f"(acc[mt][nt][1]),
                          "+f"(acc[mt][nt][2]),"+f"(acc[mt][nt][3])
                        : "r"(a[mt][0]),"r"(a[mt][1]),"r"(a[mt][2]),"r"(a[mt][3]),
                          "r"(b[nt][0]),"r"(b[nt][1]));
                }
        }
        __syncthreads();
    }

    // epilogue
    const int lr4 = lane>>2, lc2 = (lane&3)*2;
#pragma unroll
    for (int mt=0; mt<2; mt++){
        const int r0 = m0 + warp_m*32 + mt*16 + lr4;
#pragma unroll
        for (int nt=0; nt<NTL; nt++){
            const int col = n0 + warp_n*WN + nt*8 + lc2;
            float b0=0.f, b1=0.f;
            if (BIAS){ b0 = g.bias[col]; b1 = g.bias[col+1]; }
            float2 v0, v1;
            v0.x = acc[mt][nt][0]+b0; v0.y = acc[mt][nt][1]+b1;
            v1.x = acc[mt][nt][2]+b0; v1.y = acc[mt][nt][3]+b1;
            *(float2*)(g.C + (size_t)r0*N + col)     = v0;
            *(float2*)(g.C + (size_t)(r0+8)*N + col) = v1;
            if (DBLAUG && col < 32){
                __half* D0 = g.Daug + (size_t)r0*64;
                __half* D1 = g.Daug + (size_t)(r0+8)*64;
                __half h;
                h = __float2half_rn(v0.x); D0[col]      = h; D0[32+col]   = __float2half_rn(v0.x - __half2float(h));
                h = __float2half_rn(v0.y); D0[col+1]    = h; D0[33+col]   = __float2half_rn(v0.y - __half2float(h));
                h = __float2half_rn(v1.x); D1[col]      = h; D1[32+col]   = __float2half_rn(v1.x - __half2float(h));
                h = __float2half_rn(v1.y); D1[col+1]    = h; D1[33+col]   = __float2half_rn(v1.y - __half2float(h));
            }
        }
    }
}

// ---------------- depthwise causal conv (k=4) + SiLU + fp16 [ah|al] out -------------
struct ConvB { const float* X; const float* w; const float* b;
               float* xs; __half* xsaug; int rev; };
struct ConvB3 { ConvB c[3]; };
#define CCH 512

__global__ void conv_silu_kernel(ConvB3 P)
{
    const ConvB c = P.c[blockIdx.z];
    const int d  = blockIdx.x*128 + threadIdx.x;
    const int bt = blockIdx.y;
    const int b  = bt >> 3;
    const int t0 = (bt & 7)*CCH;
    const float w0=c.w[d*4+0], w1=c.w[d*4+1], w2=c.w[d*4+2], w3=c.w[d*4+3];
    const float bb=c.b[d];
    const size_t bL = (size_t)b*L_SEQ;

    auto X = [&](int i)->float{
        if (i < 0) return 0.f;
        const int l = c.rev ? (L_SEQ-1-i) : i;
        return c.X[(bL + l)*(size_t)D_XZ + d];
    };
    float x0=X(t0-3), x1=X(t0-2), x2=X(t0-1);
#pragma unroll 4
    for (int t=t0; t<t0+CCH; t++){
        const float x3 = X(t);
        const float v = fmaf(w0,x0,fmaf(w1,x1,fmaf(w2,x2,fmaf(w3,x3,bb))));
        const float s = siluf_(v);
        c.xs[(bL+t)*(size_t)D_INNER + d] = s;
        const __half hh = __float2half_rn(s);
        const __half ll = __float2half_rn(s - __half2float(hh));
        __half* o = c.xsaug + (bL+t)*(size_t)(2*D_INNER) + d;
        o[0] = hh; o[D_INNER] = ll;
        x0=x1; x1=x2; x2=x3;
    }
}

// ---------------- fused selective scan (3 branches in one launch) -------------------
struct ScanB { const float* U; const float* XS; const float* DBL; const float* XZb;
               const float* Alog; const float* Dp; float* Y; int rev; };
struct ScanB3 { ScanB s[3]; };

__global__ void scan_kernel(ScanB3 P)
{
    constexpr int TC = 128;
    __shared__ float sBC[TC][32];
    const ScanB S = P.s[blockIdx.z];
    const int tid = threadIdx.x;
    const int d   = blockIdx.x*128 + tid;
    const int b   = blockIdx.y;
    const size_t bL = (size_t)b * L_SEQ;

    float a[16];
#pragma unroll
    for (int n=0;n<16;n++) a[n] = -__expf(S.Alog[d*16+n]);
    const float a0 = a[0];
    bool pw = fabsf(a0) > 1e-20f;
#pragma unroll
    for (int n=0;n<16;n++){
        const float r = a[n]/a0;
        pw = pw && (fabsf(r - (float)(n+1)) < 1e-4f);
    }
    const float Dd = S.Dp[d];
    float h[16];
#pragma unroll
    for (int n=0;n<16;n++) h[n]=0.f;

    for (int t0=0;t0<L_SEQ;t0+=TC){
        __syncthreads();
#pragma unroll
        for (int r=0;r<(TC*32)/(4*128);r++){
            const int slot = tid + r*128;
            const int tt = slot>>3, q = slot&7;
            const float4 v = *(const float4*)(S.DBL + (bL + t0 + tt)*64 + 32 + q*4);
            *(float4*)&sBC[tt][q*4] = v;
        }
        __syncthreads();
#pragma unroll 4
        for (int tt=0;tt<TC;tt++){
            const int t = t0+tt;
            const size_t idx = (bL + t)*(size_t)D_INNER + d;
            const float u  = S.U[idx];
            const float xv = S.XS[idx];
            const int   lz = S.rev ? (L_SEQ-1-t) : t;
            const float zv = S.XZb[(bL+lz)*(size_t)D_XZ + D_INNER + d];
            const float dt = (u > 20.f) ? u : log1pf(__expf(u));
            const float dtx = dt*xv;
            float Bv[16], Cv[16];
#pragma unroll
            for (int q=0;q<4;q++){
                *(float4*)&Bv[q*4] = *(const float4*)&sBC[tt][q*4];
                *(float4*)&Cv[q*4] = *(const float4*)&sBC[tt][16+q*4];
            }
            float ya[4] = {0.f,0.f,0.f,0.f};
            if (pw){
                const float p = __expf(dt*a0);
                float e[17];                        // log-depth power tree
                e[1] = p;
#pragma unroll
                for (int n=2;n<=16;n++) e[n] = e[n>>1]*e[n-(n>>1)];
#pragma unroll
                for (int n=0;n<16;n++){
                    h[n] = fmaf(e[n+1], h[n], dtx*Bv[n]);
                    ya[n&3] = fmaf(h[n], Cv[n], ya[n&3]);
                }
            } else {
#pragma unroll
                for (int n=0;n<16;n++){
                    const float e = __expf(dt*a[n]);
                    h[n] = fmaf(e, h[n], dtx*Bv[n]);
                    ya[n&3] = fmaf(h[n], Cv[n], ya[n&3]);
                }
            }
            const float y = (ya[0]+ya[1]) + (ya[2]+ya[3]);
            S.Y[idx] = (y + Dd*xv) * siluf_(zv);
        }
    }
}

// ---------------- gated combine -> fp16 [ah|al] -------------------------------------
__global__ void combine_kernel(const float* __restrict__ yf, const float* __restrict__ yr,
                               const float* __restrict__ yg, __half* __restrict__ o)
{
    const size_t i = (size_t)blockIdx.x*256 + threadIdx.x;
    const int d = (int)(i % D_INNER);
    const size_t rr = i / D_INNER;
    const int l = (int)(rr % L_SEQ);
    const int b = (int)(rr / L_SEQ);
    const size_t ridx = ((size_t)b*L_SEQ + (L_SEQ-1-l))*(size_t)D_INNER + d;
    const float v = (yf[i] + yr[ridx]) * siluf_(yg[i]);
    const __half hh = __float2half_rn(v);
    const __half ll = __float2half_rn(v - __half2float(hh));
    __half* p = o + rr*(size_t)(2*D_INNER) + d;
    p[0] = hh; p[D_INNER] = ll;
}

// ------------------------------- host driver ----------------------------------------
extern "C" void kernel_launch(void* const* d_in, const int* in_sizes, int n_in,
                              void* d_out, int out_size)
{
    const float* H    = (const float*)d_in[0];
    const float* AH   = (const float*)d_in[1];
    const float* Winp = (const float*)d_in[2];
    const float* Wing = (const float*)d_in[3];
    const float* convw[3] = { (const float*)d_in[4], (const float*)d_in[6], (const float*)d_in[8] };
    const float* convb[3] = { (const float*)d_in[5], (const float*)d_in[7], (const float*)d_in[9] };
    const float* xproj[3] = { (const float*)d_in[10], (const float*)d_in[11], (const float*)d_in[12] };
    const float* dtw[3]   = { (const float*)d_in[13], (const float*)d_in[15], (const float*)d_in[17] };
    const float* dtb[3]   = { (const float*)d_in[14], (const float*)d_in[16], (const float*)d_in[18] };
    const float* Alog[3]  = { (const float*)d_in[19], (const float*)d_in[20], (const float*)d_in[21] };
    const float* Dp[3]    = { (const float*)d_in[22], (const float*)d_in[23], (const float*)d_in[24] };
    const float* Wout = (const float*)d_in[25];
    float* out = (float*)d_out;

    float *p_xz, *p_axz, *p_xs, *p_u, *p_dbl, *p_y;
    __half *p_Haug, *p_AHaug, *p_Wi16, *p_Wg16, *p_xsaug, *p_Xp16;
    __half *p_dtw16, *p_dblaug, *p_Wo16, *p_combaug;
    cudaGetSymbolAddress((void**)&p_xz,     g_xz);
    cudaGetSymbolAddress((void**)&p_axz,    g_axz);
    cudaGetSymbolAddress((void**)&p_xs,     g_xs);
    cudaGetSymbolAddress((void**)&p_u,      g_u);
    cudaGetSymbolAddress((void**)&p_dbl,    g_dbl);
    cudaGetSymbolAddress((void**)&p_y,      g_y);
    cudaGetSymbolAddress((void**)&p_Haug,   g_Haug);
    cudaGetSymbolAddress((void**)&p_AHaug,  g_AHaug);
    cudaGetSymbolAddress((void**)&p_Wi16,   g_Wi16);
    cudaGetSymbolAddress((void**)&p_Wg16,   g_Wg16);
    cudaGetSymbolAddress((void**)&p_xsaug,  g_xsaug);
    cudaGetSymbolAddress((void**)&p_Xp16,   g_Xp16);
    cudaGetSymbolAddress((void**)&p_dtw16,  g_dtw16);
    cudaGetSymbolAddress((void**)&p_dblaug, g_dblaug);
    cudaGetSymbolAddress((void**)&p_Wo16,   g_Wo16);
    cudaGetSymbolAddress((void**)&p_combaug,g_combaug);

    const size_t SXS   = (size_t)NTOK*D_INNER;
    const size_t SDBL  = (size_t)NTOK*64;
    const size_t SXSA  = (size_t)NTOK*2*D_INNER;
    const size_t SXP   = (size_t)64*D_INNER;
    const size_t SDTW  = (size_t)D_INNER*DT_RANK;
    const size_t SDBLA = (size_t)NTOK*64;

    const int SMEM128 = 3*(128*40 + 128*40)*2;   // 61440 B
    const int SMEM64  = 3*(128*40 +  64*40)*2;   // 46080 B
    cudaFuncSetAttribute((const void*)mma_gemm<128,false,false>, cudaFuncAttributeMaxDynamicSharedMemorySize, SMEM128);
    cudaFuncSetAttribute((const void*)mma_gemm<128,true,false>,  cudaFuncAttributeMaxDynamicSharedMemorySize, SMEM128);
    cudaFuncSetAttribute((const void*)mma_gemm<64,false,true>,   cudaFuncAttributeMaxDynamicSharedMemorySize, SMEM64);

    // [0] convert Winp, [1] convert Wing
    convW<<<(D_XZ*D_MODEL/4+255)/256, 256>>>(Winp, p_Wi16, D_XZ*D_MODEL/4);
    convW<<<(D_XZ*D_MODEL/4+255)/256, 256>>>(Wing, p_Wg16, D_XZ*D_MODEL/4);
    // [2] convert misc weights (xproj x3, dtw x3, Wout) in one launch
    {
        CJobs7 J;
        for (int z=0; z<3; z++){
            J.j[z]   = { xproj[z], p_Xp16  + z*SXP,  (int)(SXP/4)  };
            J.j[3+z] = { dtw[z],   p_dtw16 + z*SDTW, (int)(SDTW/4) };
        }
        J.j[6] = { Wout, p_Wo16, (int)((size_t)D_MODEL*D_INNER/4) };
        const int maxb = ((int)((size_t)D_MODEL*D_INNER/4) + 255)/256;
        convW_multi<<<dim3(maxb,1,7), 256>>>(J);
    }
    // [3] split H, [4] split AH  (A-side fp16 pairs)
    splitA16<<<(NTOK*D_MODEL/4+255)/256, 256>>>(H,  p_Haug,  D_MODEL, NTOK*D_MODEL/4);
    splitA16<<<(NTOK*D_MODEL/4+255)/256, 256>>>(AH, p_AHaug, D_MODEL, NTOK*D_MODEL/4);

    // [5] in-projections (K2=1024, KW=512)  <-- ncu -s 5 profiles this launch
    {
        MG3 P; P.N = D_XZ; P.K2 = 2*D_MODEL; P.KW = D_MODEL;
        P.g[0] = { p_Haug,  p_Wi16, nullptr, p_xz,  nullptr };
        P.g[1] = { p_AHaug, p_Wg16, nullptr, p_axz, nullptr };
        P.g[2] = P.g[0];
        mma_gemm<128,false,false><<<dim3(D_XZ/128, NTOK/128, 2), 256, SMEM128>>>(P);
    }
    // [6] depthwise conv + silu
    {
        ConvB3 P;
        P.c[0] = { p_xz,  convw[0], convb[0], p_xs + 0*SXS, p_xsaug + 0*SXSA, 0 };
        P.c[1] = { p_xz,  convw[1], convb[1], p_xs + 1*SXS, p_xsaug + 1*SXSA, 1 };
        P.c[2] = { p_axz, convw[2], convb[2], p_xs + 2*SXS, p_xsaug + 2*SXSA, 0 };
        conv_silu_kernel<<<dim3(D_INNER/128, 32, 3), 128>>>(P);
    }
    // [7] x-projection (N=64, K2=2048, KW=1024), fused dblaug epilogue
    {
        MG3 P; P.N = 64; P.K2 = 2*D_INNER; P.KW = D_INNER;
        for (int z=0; z<3; z++)
            P.g[z] = { p_xsaug + z*SXSA, p_Xp16 + z*SXP, nullptr, p_dbl + z*SDBL, p_dblaug + z*SDBLA };
        mma_gemm<64,false,true><<<dim3(1, NTOK/128, 3), 256, SMEM64>>>(P);
    }
    // [8] dt-projection (K2=64, KW=32)
    {
        MG3 P; P.N = D_INNER; P.K2 = 2*DT_RANK; P.KW = DT_RANK;
        for (int z=0; z<3; z++)
            P.g[z] = { p_dblaug + z*SDBLA, p_dtw16 + z*SDTW, dtb[z], p_u + z*SXS, nullptr };
        mma_gemm<128,true,false><<<dim3(D_INNER/128, NTOK/128, 3), 256, SMEM128>>>(P);
    }
    // [9] selective scan
    {
        ScanB3 P;
        P.s[0] = { p_u + 0*SXS, p_xs + 0*SXS, p_dbl + 0*SDBL, p_xz,  Alog[0], Dp[0], p_y + 0*SXS, 0 };
        P.s[1] = { p_u + 1*SXS, p_xs + 1*SXS, p_dbl + 1*SDBL, p_xz,  Alog[1], Dp[1], p_y + 1*SXS, 1 };
        P.s[2] = { p_u + 2*SXS, p_xs + 2*SXS, p_dbl + 2*SDBL, p_axz, Alog[2], Dp[2], p_y + 2*SXS, 0 };
        scan_kernel<<<dim3(D_INNER/128, B_SZ, 3), 128>>>(P);
    }
    // [10] combine
    combine_kernel<<<(unsigned)(SXS/256), 256>>>(p_y + 0*SXS, p_y + 1*SXS, p_y + 2*SXS, p_combaug);
    // [11] out-projection (K2=2048, KW=1024)
    {
        MG3 P; P.N = D_MODEL; P.K2 = 2*D_INNER; P.KW = D_INNER;
        P.g[0] = { p_combaug, p_Wo16, nullptr, out, nullptr };
        P.g[1] = P.g[0]; P.g[2] = P.g[0];
        mma_gemm<128,false,false><<<dim3(D_MODEL/128, NTOK/128, 1), 256, SMEM128>>>(P);
    }
    (void)in_sizes; (void)n_in; (void)out_size;
}

// round 7
// speedup vs baseline: 1.5364x; 1.0305x over previous
#include <cuda_runtime.h>
#include <cuda_fp16.h>
#include <cstdint>

#define L_SEQ   4096
#define B_SZ    4
#define D_MODEL 512
#define D_INNER 1024
#define D_XZ    2048
#define NTOK    (B_SZ*L_SEQ)   /* 16384 */
#define DT_RANK 32
#define D_STATE 16

// ---------------- scratch (static device allocations) -------------------------------
__device__ float g_xz  [(size_t)NTOK*D_XZ];
__device__ float g_axz [(size_t)NTOK*D_XZ];
__device__ float g_u   [3][(size_t)NTOK*D_INNER];      // dt logits (fp32)
__device__ float g_dbl [3][(size_t)NTOK*64];           // dt_low | B | C (fp32 for scan)
__device__ float g_y   [3][(size_t)NTOK*D_INNER];      // branch outputs
// interleaved fp16 pairs. A-side rows: [h0,l0,h1,l1,...] (K2=2K halves).
// W-side rows: duplicated [w0,w0,w1,w1,...] (K2 halves).
__device__ __half g_Haug [(size_t)NTOK*2*D_MODEL];
__device__ __half g_AHaug[(size_t)NTOK*2*D_MODEL];
__device__ __half g_Wi16 [(size_t)D_XZ*2*D_MODEL];
__device__ __half g_Wg16 [(size_t)D_XZ*2*D_MODEL];
__device__ __half g_xsaug[3][(size_t)NTOK*2*D_INNER];  // conv+silu x as {hi,lo} pairs
__device__ __half g_Xp16 [3][(size_t)64*2*D_INNER];
__device__ __half g_dtw16[3][(size_t)D_INNER*2*DT_RANK];
__device__ __half g_dblaug[3][(size_t)NTOK*64];        // interleaved pairs of dt_low(32)
__device__ __half g_Wo16 [(size_t)D_MODEL*2*D_INNER];
__device__ __half g_combaug[(size_t)NTOK*2*D_INNER];

__device__ __forceinline__ float sigmoidf_(float x){ return 1.0f/(1.0f+__expf(-x)); }
__device__ __forceinline__ float siluf_(float x){ return x*sigmoidf_(x); }

__device__ __forceinline__ uint32_t smem_u32(const void* p){
    uint32_t a;
    asm("{ .reg .u64 t; cvta.to.shared.u64 t, %1; cvt.u32.u64 %0, t; }" : "=r"(a) : "l"(p));
    return a;
}
__device__ __forceinline__ void cp_async16(uint32_t dst, const void* src){
    asm volatile("cp.async.cg.shared.global [%0], [%1], 16;\n" :: "r"(dst), "l"(src));
}

// ====== W convert: fp32 [.,K] -> fp16 duplicated-interleave [., 2K] ================
struct CJob { const float* src; __half* dst; int n4; };
struct CJobs7 { CJob j[7]; };
template<int NJ>
__global__ void convWdup_multi(CJobs7 J)
{
    const CJob jb = J.j[blockIdx.z];
    const int i = blockIdx.x*256 + threadIdx.x;
    if (i >= jb.n4) return;
    const float4 v = ((const float4*)jb.src)[i];
    __half h0=__float2half_rn(v.x), h1=__float2half_rn(v.y),
           h2=__float2half_rn(v.z), h3=__float2half_rn(v.w);
    __align__(16) __half o[8] = {h0,h0,h1,h1,h2,h2,h3,h3};
    *(uint4*)(jb.dst + (size_t)i*8) = *(const uint4*)o;
}

// ====== A split: fp32 [R,K] -> fp16 interleaved [R, 2K] = [h,l,h,l,...] ============
__global__ void splitA16(const float* __restrict__ src, __half* __restrict__ dst,
                         int K, int n4total)
{
    const int i = blockIdx.x*256 + threadIdx.x;
    if (i >= n4total) return;
    const int kq = K >> 2;
    const int r  = i / kq, k4 = i % kq;
    const float4 v = *(const float4*)(src + (size_t)r*K + k4*4);
    const float f[4] = {v.x, v.y, v.z, v.w};
    __align__(16) __half o[8];
#pragma unroll
    for (int j=0;j<4;j++){
        const __half hh = __float2half_rn(f[j]);
        o[2*j]   = hh;
        o[2*j+1] = __float2half_rn(f[j] - __half2float(hh));
    }
    *(uint4*)(dst + (size_t)r*2*K + (size_t)k4*8) = *(const uint4*)o;
}

// ================= mma.sync fp16 GEMM: C[m,n] = Σ_k2 A[m,k2]·W[n,k2] (+bias) ========
// A: [M,K2] interleaved pairs.  W: [N,K2] duplicated.  BM=128, BN∈{64,128}, BK=32,
// 4-stage cp.async pipeline, 256 threads, 2 CTA/SM.
struct MG  { const __half *A, *W; const float* bias; float* C; __half* Daug; };
struct MG3 { MG g[3]; int N, K2; };

template<int BN, bool BIAS, bool DBLAUG>
__global__ void __launch_bounds__(256, 2) mma_gemm(MG3 P)
{
    constexpr int NS  = 4;
    constexpr int WN  = BN/2;
    constexpr int NTL = WN/8;
    constexpr int SAE = 128*40;
    constexpr int SWE = BN*40;
    const MG g = P.g[blockIdx.z];
    const int N = P.N, K2 = P.K2;
    const int tid  = threadIdx.x;
    const int lane = tid & 31, wid = tid >> 5;
    const int warp_m = wid & 3, warp_n = wid >> 2;
    const int m0 = blockIdx.y * 128, n0 = blockIdx.x * BN;

    extern __shared__ __align__(128) __half sm[];
    const uint32_t base = smem_u32(sm);
    uint32_t aB[NS], wB[NS];
#pragma unroll
    for (int s=0;s<NS;s++){
        aB[s] = base + (uint32_t)(s*(SAE+SWE)*2);
        wB[s] = aB[s] + SAE*2;
    }

    float acc[2][NTL][4];
#pragma unroll
    for (int mt=0;mt<2;mt++)
#pragma unroll
        for (int nt=0;nt<NTL;nt++)
#pragma unroll
            for (int j=0;j<4;j++) acc[mt][nt][j]=0.f;

    const int nk = K2 / 32;

    auto load_tiles = [&](int s, int kt){
        const int k0 = kt*32;
        const __half* Ap = g.A + (size_t)m0*K2 + k0;
#pragma unroll
        for (int q = tid; q < 512; q += 256){
            const int r = q>>2, c = q&3;
            cp_async16(aB[s] + r*80 + c*16, Ap + (size_t)r*K2 + c*8);
        }
        const __half* Wp = g.W + (size_t)n0*K2 + k0;
#pragma unroll
        for (int q = tid; q < BN*4; q += 256){
            const int r = q>>2, c = q&3;
            cp_async16(wB[s] + r*80 + c*16, Wp + (size_t)r*K2 + c*8);
        }
        asm volatile("cp.async.commit_group;\n" ::: "memory");
    };

#pragma unroll
    for (int s=0; s<NS-1; s++){
        if (s < nk) load_tiles(s, s);
        else asm volatile("cp.async.commit_group;\n" ::: "memory");
    }

    const int lr       = lane & 7;
    const int arow_off = ((lane>>3)&1)*8 + lr;
    const int akb      = (lane>>4)*16;
    const int brow_off = ((lane>>4)&1)*8 + lr;
    const int bkb      = ((lane>>3)&1)*16;

    for (int kt = 0; kt < nk; kt++){
        asm volatile("cp.async.wait_group %0;\n" :: "n"(NS-2) : "memory");
        __syncthreads();
        const int pf = kt + NS - 1;
        if (pf < nk) load_tiles(pf % NS, pf);
        else asm volatile("cp.async.commit_group;\n" ::: "memory");

        const uint32_t aBc = aB[kt % NS], wBc = wB[kt % NS];
#pragma unroll
        for (int ks = 0; ks < 2; ks++){
            uint32_t a[2][4];
#pragma unroll
            for (int mt=0; mt<2; mt++){
                const uint32_t addr = aBc + (warp_m*32 + mt*16 + arow_off)*80 + ks*32 + akb;
                asm volatile("ldmatrix.sync.aligned.m8n8.x4.shared.b16 {%0,%1,%2,%3}, [%4];"
                    : "=r"(a[mt][0]),"=r"(a[mt][1]),"=r"(a[mt][2]),"=r"(a[mt][3]) : "r"(addr));
            }
            uint32_t b[NTL][2];
#pragma unroll
            for (int ntp=0; ntp<NTL/2; ntp++){
                const uint32_t addr = wBc + (warp_n*WN + ntp*16 + brow_off)*80 + ks*32 + bkb;
                asm volatile("ldmatrix.sync.aligned.m8n8.x4.shared.b16 {%0,%1,%2,%3}, [%4];"
                    : "=r"(b[2*ntp][0]),"=r"(b[2*ntp][1]),
                      "=r"(b[2*ntp+1][0]),"=r"(b[2*ntp+1][1]) : "r"(addr));
            }
#pragma unroll
            for (int mt=0; mt<2; mt++)
#pragma unroll
                for (int nt=0; nt<NTL; nt++){
                    asm volatile("mma.sync.aligned.m16n8k16.row.col.f32.f16.f16.f32 "
                        "{%0,%1,%2,%3}, {%4,%5,%6,%7}, {%8,%9}, {%0,%1,%2,%3};"
                        : "+f"(acc[mt][nt][0]),"+f"(acc[mt][nt][1]),
                          "+f"(acc[mt][nt][2]),"+f"(acc[mt][nt][3])
                        : "r"(a[mt][0]),"r"(a[mt][1]),"r"(a[mt][2]),"r"(a[mt][3]),
                          "r"(b[nt][0]),"r"(b[nt][1]));
                }
        }
        __syncthreads();
    }

    // epilogue
    const int lr4 = lane>>2, lc2 = (lane&3)*2;
#pragma unroll
    for (int mt=0; mt<2; mt++){
        const int r0 = m0 + warp_m*32 + mt*16 + lr4;
#pragma unroll
        for (int nt=0; nt<NTL; nt++){
            const int col = n0 + warp_n*WN + nt*8 + lc2;
            float b0=0.f, b1=0.f;
            if (BIAS){ b0 = g.bias[col]; b1 = g.bias[col+1]; }
            float2 v0, v1;
            v0.x = acc[mt][nt][0]+b0; v0.y = acc[mt][nt][1]+b1;
            v1.x = acc[mt][nt][2]+b0; v1.y = acc[mt][nt][3]+b1;
            *(float2*)(g.C + (size_t)r0*N + col)     = v0;
            *(float2*)(g.C + (size_t)(r0+8)*N + col) = v1;
            if (DBLAUG && col < 32){
                __half2* D0 = (__half2*)(g.Daug + (size_t)r0*64);
                __half2* D1 = (__half2*)(g.Daug + (size_t)(r0+8)*64);
                __half h;
                h = __float2half_rn(v0.x); D0[col]   = __halves2half2(h, __float2half_rn(v0.x - __half2float(h)));
                h = __float2half_rn(v0.y); D0[col+1] = __halves2half2(h, __float2half_rn(v0.y - __half2float(h)));
                h = __float2half_rn(v1.x); D1[col]   = __halves2half2(h, __float2half_rn(v1.x - __half2float(h)));
                h = __float2half_rn(v1.y); D1[col+1] = __halves2half2(h, __float2half_rn(v1.y - __half2float(h)));
            }
        }
    }
}

// ---------------- depthwise causal conv (k=4) + SiLU -> interleaved half2 -----------
struct ConvB { const float* X; const float* w; const float* b;
               __half2* xsi; int rev; };
struct ConvB3 { ConvB c[3]; };
#define CCH 512

__global__ void conv_silu_kernel(ConvB3 P)
{
    const ConvB c = P.c[blockIdx.z];
    const int d  = blockIdx.x*128 + threadIdx.x;
    const int bt = blockIdx.y;
    const int b  = bt >> 3;
    const int t0 = (bt & 7)*CCH;
    const float w0=c.w[d*4+0], w1=c.w[d*4+1], w2=c.w[d*4+2], w3=c.w[d*4+3];
    const float bb=c.b[d];
    const size_t bL = (size_t)b*L_SEQ;

    auto X = [&](int i)->float{
        if (i < 0) return 0.f;
        const int l = c.rev ? (L_SEQ-1-i) : i;
        return c.X[(bL + l)*(size_t)D_XZ + d];
    };
    float x0=X(t0-3), x1=X(t0-2), x2=X(t0-1);
#pragma unroll 4
    for (int t=t0; t<t0+CCH; t++){
        const float x3 = X(t);
        const float v = fmaf(w0,x0,fmaf(w1,x1,fmaf(w2,x2,fmaf(w3,x3,bb))));
        const float s = siluf_(v);
        const __half hh = __float2half_rn(s);
        const __half ll = __float2half_rn(s - __half2float(hh));
        c.xsi[(bL+t)*(size_t)D_INNER + d] = __halves2half2(hh, ll);
        x0=x1; x1=x2; x2=x3;
    }
}

// ---------------- fused selective scan (3 branches, prefetched) ---------------------
struct ScanB { const float* U; const __half2* XS2; const float* DBL; const float* XZb;
               const float* Alog; const float* Dp; float* Y; int rev; };
struct ScanB3 { ScanB s[3]; };

__global__ void scan_kernel(ScanB3 P)
{
    constexpr int TC = 128;
    __shared__ float sBC[TC][32];
    const ScanB S = P.s[blockIdx.z];
    const int tid = threadIdx.x;
    const int d   = blockIdx.x*128 + tid;
    const int b   = blockIdx.y;
    const size_t bL = (size_t)b * L_SEQ;

    float a[16];
#pragma unroll
    for (int n=0;n<16;n++) a[n] = -__expf(S.Alog[d*16+n]);
    const float a0 = a[0];
    bool pw = fabsf(a0) > 1e-20f;
#pragma unroll
    for (int n=0;n<16;n++){
        const float r = a[n]/a0;
        pw = pw && (fabsf(r - (float)(n+1)) < 1e-4f);
    }
    const float Dd = S.Dp[d];
    float h[16];
#pragma unroll
    for (int n=0;n<16;n++) h[n]=0.f;

    // prefetch t=0
    float u_c, x_c, z_c;
    {
        const size_t idx0 = bL*(size_t)D_INNER + d;
        u_c = S.U[idx0];
        const __half2 xp = S.XS2[idx0];
        x_c = __half2float(__low2half(xp)) + __half2float(__high2half(xp));
        const int lz0 = S.rev ? (L_SEQ-1) : 0;
        z_c = S.XZb[(bL+lz0)*(size_t)D_XZ + D_INNER + d];
    }

    for (int t0=0;t0<L_SEQ;t0+=TC){
        __syncthreads();
#pragma unroll
        for (int r=0;r<(TC*32)/(4*128);r++){
            const int slot = tid + r*128;
            const int tt = slot>>3, q = slot&7;
            const float4 v = *(const float4*)(S.DBL + (bL + t0 + tt)*64 + 32 + q*4);
            *(float4*)&sBC[tt][q*4] = v;
        }
        __syncthreads();
#pragma unroll 4
        for (int tt=0;tt<TC;tt++){
            const int t = t0+tt;
            const size_t idx = (bL + t)*(size_t)D_INNER + d;
            // prefetch t+1
            float u_n=0.f, x_n=0.f, z_n=0.f;
            if (t+1 < L_SEQ){
                const size_t idxn = idx + D_INNER;
                u_n = S.U[idxn];
                const __half2 xp = S.XS2[idxn];
                x_n = __half2float(__low2half(xp)) + __half2float(__high2half(xp));
                const int lzn = S.rev ? (L_SEQ-2-t) : (t+1);
                z_n = S.XZb[(bL+lzn)*(size_t)D_XZ + D_INNER + d];
            }
            const float dt = (u_c > 20.f) ? u_c : log1pf(__expf(u_c));
            const float dtx = dt*x_c;
            float Bv[16], Cv[16];
#pragma unroll
            for (int q=0;q<4;q++){
                *(float4*)&Bv[q*4] = *(const float4*)&sBC[tt][q*4];
                *(float4*)&Cv[q*4] = *(const float4*)&sBC[tt][16+q*4];
            }
            float ya[4] = {0.f,0.f,0.f,0.f};
            if (pw){
                const float p = __expf(dt*a0);
                float e[17];
                e[1] = p;
#pragma unroll
                for (int n=2;n<=16;n++) e[n] = e[n>>1]*e[n-(n>>1)];
#pragma unroll
                for (int n=0;n<16;n++){
                    h[n] = fmaf(e[n+1], h[n], dtx*Bv[n]);
                    ya[n&3] = fmaf(h[n], Cv[n], ya[n&3]);
                }
            } else {
#pragma unroll
                for (int n=0;n<16;n++){
                    const float e = __expf(dt*a[n]);
                    h[n] = fmaf(e, h[n], dtx*Bv[n]);
                    ya[n&3] = fmaf(h[n], Cv[n], ya[n&3]);
                }
            }
            const float y = (ya[0]+ya[1]) + (ya[2]+ya[3]);
            S.Y[idx] = (y + Dd*x_c) * siluf_(z_c);
            u_c = u_n; x_c = x_n; z_c = z_n;
        }
    }
}

// ---------------- gated combine -> interleaved half2 --------------------------------
__global__ void combine_kernel(const float* __restrict__ yf, const float* __restrict__ yr,
                               const float* __restrict__ yg, __half2* __restrict__ o)
{
    const size_t i = (size_t)blockIdx.x*256 + threadIdx.x;
    const int d = (int)(i % D_INNER);
    const size_t rr = i / D_INNER;
    const int l = (int)(rr % L_SEQ);
    const int b = (int)(rr / L_SEQ);
    const size_t ridx = ((size_t)b*L_SEQ + (L_SEQ-1-l))*(size_t)D_INNER + d;
    const float v = (yf[i] + yr[ridx]) * siluf_(yg[i]);
    const __half hh = __float2half_rn(v);
    o[rr*(size_t)D_INNER + d] = __halves2half2(hh, __float2half_rn(v - __half2float(hh)));
}

// ------------------------------- host driver ----------------------------------------
extern "C" void kernel_launch(void* const* d_in, const int* in_sizes, int n_in,
                              void* d_out, int out_size)
{
    const float* H    = (const float*)d_in[0];
    const float* AH   = (const float*)d_in[1];
    const float* Winp = (const float*)d_in[2];
    const float* Wing = (const float*)d_in[3];
    const float* convw[3] = { (const float*)d_in[4], (const float*)d_in[6], (const float*)d_in[8] };
    const float* convb[3] = { (const float*)d_in[5], (const float*)d_in[7], (const float*)d_in[9] };
    const float* xproj[3] = { (const float*)d_in[10], (const float*)d_in[11], (const float*)d_in[12] };
    const float* dtw[3]   = { (const float*)d_in[13], (const float*)d_in[15], (const float*)d_in[17] };
    const float* dtb[3]   = { (const float*)d_in[14], (const float*)d_in[16], (const float*)d_in[18] };
    const float* Alog[3]  = { (const float*)d_in[19], (const float*)d_in[20], (const float*)d_in[21] };
    const float* Dp[3]    = { (const float*)d_in[22], (const float*)d_in[23], (const float*)d_in[24] };
    const float* Wout = (const float*)d_in[25];
    float* out = (float*)d_out;

    float *p_xz, *p_axz, *p_u, *p_dbl, *p_y;
    __half *p_Haug, *p_AHaug, *p_Wi16, *p_Wg16, *p_xsaug, *p_Xp16;
    __half *p_dtw16, *p_dblaug, *p_Wo16, *p_combaug;
    cudaGetSymbolAddress((void**)&p_xz,     g_xz);
    cudaGetSymbolAddress((void**)&p_axz,    g_axz);
    cudaGetSymbolAddress((void**)&p_u,      g_u);
    cudaGetSymbolAddress((void**)&p_dbl,    g_dbl);
    cudaGetSymbolAddress((void**)&p_y,      g_y);
    cudaGetSymbolAddress((void**)&p_Haug,   g_Haug);
    cudaGetSymbolAddress((void**)&p_AHaug,  g_AHaug);
    cudaGetSymbolAddress((void**)&p_Wi16,   g_Wi16);
    cudaGetSymbolAddress((void**)&p_Wg16,   g_Wg16);
    cudaGetSymbolAddress((void**)&p_xsaug,  g_xsaug);
    cudaGetSymbolAddress((void**)&p_Xp16,   g_Xp16);
    cudaGetSymbolAddress((void**)&p_dtw16,  g_dtw16);
    cudaGetSymbolAddress((void**)&p_dblaug, g_dblaug);
    cudaGetSymbolAddress((void**)&p_Wo16,   g_Wo16);
    cudaGetSymbolAddress((void**)&p_combaug,g_combaug);

    const size_t SXS   = (size_t)NTOK*D_INNER;
    const size_t SDBL  = (size_t)NTOK*64;
    const size_t SXSA  = (size_t)NTOK*2*D_INNER;
    const size_t SXP   = (size_t)64*2*D_INNER;
    const size_t SDTW  = (size_t)D_INNER*2*DT_RANK;
    const size_t SDBLA = (size_t)NTOK*64;

    const int SMEM128 = 4*(128*40 + 128*40)*2;   // 81920 B
    const int SMEM64  = 4*(128*40 +  64*40)*2;   // 61440 B
    cudaFuncSetAttribute((const void*)mma_gemm<128,false,false>, cudaFuncAttributeMaxDynamicSharedMemorySize, SMEM128);
    cudaFuncSetAttribute((const void*)mma_gemm<128,true,false>,  cudaFuncAttributeMaxDynamicSharedMemorySize, SMEM128);
    cudaFuncSetAttribute((const void*)mma_gemm<64,false,true>,   cudaFuncAttributeMaxDynamicSharedMemorySize, SMEM64);

    // launch #1 (1-based): big W conversions (duplicated interleave)
    {
        CJobs7 J;
        J.j[0] = { Winp, p_Wi16, (int)((size_t)D_XZ*D_MODEL/4) };
        J.j[1] = { Wing, p_Wg16, (int)((size_t)D_XZ*D_MODEL/4) };
        const int maxb = ((int)((size_t)D_XZ*D_MODEL/4) + 255)/256;
        convWdup_multi<2><<<dim3(maxb,1,2), 256>>>(J);
    }
    // launch #2: misc W conversions
    {
        CJobs7 J;
        for (int z=0; z<3; z++){
            J.j[z]   = { xproj[z], p_Xp16  + z*SXP,  (int)((size_t)64*D_INNER/4) };
            J.j[3+z] = { dtw[z],   p_dtw16 + z*SDTW, (int)((size_t)D_INNER*DT_RANK/4) };
        }
        J.j[6] = { Wout, p_Wo16, (int)((size_t)D_MODEL*D_INNER/4) };
        const int maxb = ((int)((size_t)D_MODEL*D_INNER/4) + 255)/256;
        convWdup_multi<7><<<dim3(maxb,1,7), 256>>>(J);
    }
    // launches #3, #4: A-side splits of H / AH
    splitA16<<<(NTOK*D_MODEL/4+255)/256, 256>>>(H,  p_Haug,  D_MODEL, NTOK*D_MODEL/4);
    splitA16<<<(NTOK*D_MODEL/4+255)/256, 256>>>(AH, p_AHaug, D_MODEL, NTOK*D_MODEL/4);

    // launch #5: in-projections (K2=1024)  <-- ncu profiles this one
    {
        MG3 P; P.N = D_XZ; P.K2 = 2*D_MODEL;
        P.g[0] = { p_Haug,  p_Wi16, nullptr, p_xz,  nullptr };
        P.g[1] = { p_AHaug, p_Wg16, nullptr, p_axz, nullptr };
        P.g[2] = P.g[0];
        mma_gemm<128,false,false><<<dim3(D_XZ/128, NTOK/128, 2), 256, SMEM128>>>(P);
    }
    // #6: depthwise conv + silu -> interleaved pairs
    {
        ConvB3 P;
        P.c[0] = { p_xz,  convw[0], convb[0], (__half2*)(p_xsaug + 0*SXSA), 0 };
        P.c[1] = { p_xz,  convw[1], convb[1], (__half2*)(p_xsaug + 1*SXSA), 1 };
        P.c[2] = { p_axz, convw[2], convb[2], (__half2*)(p_xsaug + 2*SXSA), 0 };
        conv_silu_kernel<<<dim3(D_INNER/128, 32, 3), 128>>>(P);
    }
    // #7: x-projection (N=64, K2=2048), fused dblaug epilogue
    {
        MG3 P; P.N = 64; P.K2 = 2*D_INNER;
        for (int z=0; z<3; z++)
            P.g[z] = { p_xsaug + z*SXSA, p_Xp16 + z*SXP, nullptr, p_dbl + z*SDBL, p_dblaug + z*SDBLA };
        mma_gemm<64,false,true><<<dim3(1, NTOK/128, 3), 256, SMEM64>>>(P);
    }
    // #8: dt-projection (K2=64)
    {
        MG3 P; P.N = D_INNER; P.K2 = 2*DT_RANK;
        for (int z=0; z<3; z++)
            P.g[z] = { p_dblaug + z*SDBLA, p_dtw16 + z*SDTW, dtb[z], p_u + z*SXS, nullptr };
        mma_gemm<128,true,false><<<dim3(D_INNER/128, NTOK/128, 3), 256, SMEM128>>>(P);
    }
    // #9: selective scan
    {
        ScanB3 P;
        P.s[0] = { p_u + 0*SXS, (const __half2*)(p_xsaug + 0*SXSA), p_dbl + 0*SDBL, p_xz,  Alog[0], Dp[0], p_y + 0*SXS, 0 };
        P.s[1] = { p_u + 1*SXS, (const __half2*)(p_xsaug + 1*SXSA), p_dbl + 1*SDBL, p_xz,  Alog[1], Dp[1], p_y + 1*SXS, 1 };
        P.s[2] = { p_u + 2*SXS, (const __half2*)(p_xsaug + 2*SXSA), p_dbl + 2*SDBL, p_axz, Alog[2], Dp[2], p_y + 2*SXS, 0 };
        scan_kernel<<<dim3(D_INNER/128, B_SZ, 3), 128>>>(P);
    }
    // #10: combine -> interleaved pairs
    combine_kernel<<<(unsigned)(SXS/256), 256>>>(p_y + 0*SXS, p_y + 1*SXS, p_y + 2*SXS, (__half2*)p_combaug);
    // #11: out-projection (K2=2048)
    {
        MG3 P; P.N = D_MODEL; P.K2 = 2*D_INNER;
        P.g[0] = { p_combaug, p_Wo16, nullptr, out, nullptr };
        P.g[1] = P.g[0]; P.g[2] = P.g[0];
        mma_gemm<128,false,false><<<dim3(D_MODEL/128, NTOK/128, 1), 256, SMEM128>>>(P);
    }
    (void)in_sizes; (void)n_in; (void)out_size;
}

// round 8
// speedup vs baseline: 3.4101x; 2.2196x over previous
#include <cuda_runtime.h>
#include <cuda_fp16.h>
#include <cstdint>

#define L_SEQ   4096
#define B_SZ    4
#define D_MODEL 512
#define D_INNER 1024
#define D_XZ    2048
#define NTOK    (B_SZ*L_SEQ)   /* 16384 */
#define DT_RANK 32
#define D_STATE 16
#define NCH     32              /* time chunks for parallel scan */
#define TCH     (L_SEQ/NCH)     /* 128 steps per chunk */

// ---------------- scratch (static device allocations) -------------------------------
__device__ float g_xz  [(size_t)NTOK*D_XZ];
__device__ float g_axz [(size_t)NTOK*D_XZ];
__device__ float g_u   [3][(size_t)NTOK*D_INNER];      // dt logits (fp32)
__device__ float g_dbl [3][(size_t)NTOK*64];           // dt_low | B | C (fp32 for scan)
__device__ float g_y   [3][(size_t)NTOK*D_INNER];      // branch outputs
// chunked-scan carries
__device__ float g_hend  [3][(size_t)B_SZ*NCH*D_INNER*16];
__device__ float g_hstart[3][(size_t)B_SZ*NCH*D_INNER*16];
__device__ float g_ssum  [3][(size_t)B_SZ*NCH*D_INNER];
// interleaved fp16 pairs. A-side rows: [h0,l0,h1,l1,...] (K2=2K halves).
// W-side rows: duplicated [w0,w0,w1,w1,...] (K2 halves).
__device__ __half g_Haug [(size_t)NTOK*2*D_MODEL];
__device__ __half g_AHaug[(size_t)NTOK*2*D_MODEL];
__device__ __half g_Wi16 [(size_t)D_XZ*2*D_MODEL];
__device__ __half g_Wg16 [(size_t)D_XZ*2*D_MODEL];
__device__ __half g_xsaug[3][(size_t)NTOK*2*D_INNER];  // conv+silu x as {hi,lo} pairs
__device__ __half g_Xp16 [3][(size_t)64*2*D_INNER];
__device__ __half g_dtw16[3][(size_t)D_INNER*2*DT_RANK];
__device__ __half g_dblaug[3][(size_t)NTOK*64];        // interleaved pairs of dt_low(32)
__device__ __half g_Wo16 [(size_t)D_MODEL*2*D_INNER];
__device__ __half g_combaug[(size_t)NTOK*2*D_INNER];

__device__ __forceinline__ float sigmoidf_(float x){ return 1.0f/(1.0f+__expf(-x)); }
__device__ __forceinline__ float siluf_(float x){ return x*sigmoidf_(x); }

__device__ __forceinline__ uint32_t smem_u32(const void* p){
    uint32_t a;
    asm("{ .reg .u64 t; cvta.to.shared.u64 t, %1; cvt.u32.u64 %0, t; }" : "=r"(a) : "l"(p));
    return a;
}
__device__ __forceinline__ void cp_async16(uint32_t dst, const void* src){
    asm volatile("cp.async.cg.shared.global [%0], [%1], 16;\n" :: "r"(dst), "l"(src));
}

// ====== W convert: fp32 [.,K] -> fp16 duplicated-interleave [., 2K] ================
struct CJob { const float* src; __half* dst; int n4; };
struct CJobs7 { CJob j[7]; };
template<int NJ>
__global__ void convWdup_multi(CJobs7 J)
{
    const CJob jb = J.j[blockIdx.z];
    const int i = blockIdx.x*256 + threadIdx.x;
    if (i >= jb.n4) return;
    const float4 v = ((const float4*)jb.src)[i];
    __half h0=__float2half_rn(v.x), h1=__float2half_rn(v.y),
           h2=__float2half_rn(v.z), h3=__float2half_rn(v.w);
    __align__(16) __half o[8] = {h0,h0,h1,h1,h2,h2,h3,h3};
    *(uint4*)(jb.dst + (size_t)i*8) = *(const uint4*)o;
}

// ====== A split: fp32 [R,K] -> fp16 interleaved [R, 2K] = [h,l,h,l,...] ============
__global__ void splitA16(const float* __restrict__ src, __half* __restrict__ dst,
                         int K, int n4total)
{
    const int i = blockIdx.x*256 + threadIdx.x;
    if (i >= n4total) return;
    const int kq = K >> 2;
    const int r  = i / kq, k4 = i % kq;
    const float4 v = *(const float4*)(src + (size_t)r*K + k4*4);
    const float f[4] = {v.x, v.y, v.z, v.w};
    __align__(16) __half o[8];
#pragma unroll
    for (int j=0;j<4;j++){
        const __half hh = __float2half_rn(f[j]);
        o[2*j]   = hh;
        o[2*j+1] = __float2half_rn(f[j] - __half2float(hh));
    }
    *(uint4*)(dst + (size_t)r*2*K + (size_t)k4*8) = *(const uint4*)o;
}

// ================= mma.sync fp16 GEMM (unchanged from R7) ===========================
struct MG  { const __half *A, *W; const float* bias; float* C; __half* Daug; };
struct MG3 { MG g[3]; int N, K2; };

template<int BN, bool BIAS, bool DBLAUG>
__global__ void __launch_bounds__(256, 2) mma_gemm(MG3 P)
{
    constexpr int NS  = 4;
    constexpr int WN  = BN/2;
    constexpr int NTL = WN/8;
    constexpr int SAE = 128*40;
    constexpr int SWE = BN*40;
    const MG g = P.g[blockIdx.z];
    const int N = P.N, K2 = P.K2;
    const int tid  = threadIdx.x;
    const int lane = tid & 31, wid = tid >> 5;
    const int warp_m = wid & 3, warp_n = wid >> 2;
    const int m0 = blockIdx.y * 128, n0 = blockIdx.x * BN;

    extern __shared__ __align__(128) __half sm[];
    const uint32_t base = smem_u32(sm);
    uint32_t aB[NS], wB[NS];
#pragma unroll
    for (int s=0;s<NS;s++){
        aB[s] = base + (uint32_t)(s*(SAE+SWE)*2);
        wB[s] = aB[s] + SAE*2;
    }

    float acc[2][NTL][4];
#pragma unroll
    for (int mt=0;mt<2;mt++)
#pragma unroll
        for (int nt=0;nt<NTL;nt++)
#pragma unroll
            for (int j=0;j<4;j++) acc[mt][nt][j]=0.f;

    const int nk = K2 / 32;

    auto load_tiles = [&](int s, int kt){
        const int k0 = kt*32;
        const __half* Ap = g.A + (size_t)m0*K2 + k0;
#pragma unroll
        for (int q = tid; q < 512; q += 256){
            const int r = q>>2, c = q&3;
            cp_async16(aB[s] + r*80 + c*16, Ap + (size_t)r*K2 + c*8);
        }
        const __half* Wp = g.W + (size_t)n0*K2 + k0;
#pragma unroll
        for (int q = tid; q < BN*4; q += 256){
            const int r = q>>2, c = q&3;
            cp_async16(wB[s] + r*80 + c*16, Wp + (size_t)r*K2 + c*8);
        }
        asm volatile("cp.async.commit_group;\n" ::: "memory");
    };

#pragma unroll
    for (int s=0; s<NS-1; s++){
        if (s < nk) load_tiles(s, s);
        else asm volatile("cp.async.commit_group;\n" ::: "memory");
    }

    const int lr       = lane & 7;
    const int arow_off = ((lane>>3)&1)*8 + lr;
    const int akb      = (lane>>4)*16;
    const int brow_off = ((lane>>4)&1)*8 + lr;
    const int bkb      = ((lane>>3)&1)*16;

    for (int kt = 0; kt < nk; kt++){
        asm volatile("cp.async.wait_group %0;\n" :: "n"(NS-2) : "memory");
        __syncthreads();
        const int pf = kt + NS - 1;
        if (pf < nk) load_tiles(pf % NS, pf);
        else asm volatile("cp.async.commit_group;\n" ::: "memory");

        const uint32_t aBc = aB[kt % NS], wBc = wB[kt % NS];
#pragma unroll
        for (int ks = 0; ks < 2; ks++){
            uint32_t a[2][4];
#pragma unroll
            for (int mt=0; mt<2; mt++){
                const uint32_t addr = aBc + (warp_m*32 + mt*16 + arow_off)*80 + ks*32 + akb;
                asm volatile("ldmatrix.sync.aligned.m8n8.x4.shared.b16 {%0,%1,%2,%3}, [%4];"
                    : "=r"(a[mt][0]),"=r"(a[mt][1]),"=r"(a[mt][2]),"=r"(a[mt][3]) : "r"(addr));
            }
            uint32_t b[NTL][2];
#pragma unroll
            for (int ntp=0; ntp<NTL/2; ntp++){
                const uint32_t addr = wBc + (warp_n*WN + ntp*16 + brow_off)*80 + ks*32 + bkb;
                asm volatile("ldmatrix.sync.aligned.m8n8.x4.shared.b16 {%0,%1,%2,%3}, [%4];"
                    : "=r"(b[2*ntp][0]),"=r"(b[2*ntp][1]),
                      "=r"(b[2*ntp+1][0]),"=r"(b[2*ntp+1][1]) : "r"(addr));
            }
#pragma unroll
            for (int mt=0; mt<2; mt++)
#pragma unroll
                for (int nt=0; nt<NTL; nt++){
                    asm volatile("mma.sync.aligned.m16n8k16.row.col.f32.f16.f16.f32 "
                        "{%0,%1,%2,%3}, {%4,%5,%6,%7}, {%8,%9}, {%0,%1,%2,%3};"
                        : "+f"(acc[mt][nt][0]),"+f"(acc[mt][nt][1]),
                          "+f"(acc[mt][nt][2]),"+f"(acc[mt][nt][3])
                        : "r"(a[mt][0]),"r"(a[mt][1]),"r"(a[mt][2]),"r"(a[mt][3]),
                          "r"(b[nt][0]),"r"(b[nt][1]));
                }
        }
        __syncthreads();
    }

    const int lr4 = lane>>2, lc2 = (lane&3)*2;
#pragma unroll
    for (int mt=0; mt<2; mt++){
        const int r0 = m0 + warp_m*32 + mt*16 + lr4;
#pragma unroll
        for (int nt=0; nt<NTL; nt++){
            const int col = n0 + warp_n*WN + nt*8 + lc2;
            float b0=0.f, b1=0.f;
            if (BIAS){ b0 = g.bias[col]; b1 = g.bias[col+1]; }
            float2 v0, v1;
            v0.x = acc[mt][nt][0]+b0; v0.y = acc[mt][nt][1]+b1;
            v1.x = acc[mt][nt][2]+b0; v1.y = acc[mt][nt][3]+b1;
            *(float2*)(g.C + (size_t)r0*N + col)     = v0;
            *(float2*)(g.C + (size_t)(r0+8)*N + col) = v1;
            if (DBLAUG && col < 32){
                __half2* D0 = (__half2*)(g.Daug + (size_t)r0*64);
                __half2* D1 = (__half2*)(g.Daug + (size_t)(r0+8)*64);
                __half h;
                h = __float2half_rn(v0.x); D0[col]   = __halves2half2(h, __float2half_rn(v0.x - __half2float(h)));
                h = __float2half_rn(v0.y); D0[col+1] = __halves2half2(h, __float2half_rn(v0.y - __half2float(h)));
                h = __float2half_rn(v1.x); D1[col]   = __halves2half2(h, __float2half_rn(v1.x - __half2float(h)));
                h = __float2half_rn(v1.y); D1[col+1] = __halves2half2(h, __float2half_rn(v1.y - __half2float(h)));
            }
        }
    }
}

// ---------------- depthwise causal conv (k=4) + SiLU -> interleaved half2 -----------
struct ConvB { const float* X; const float* w; const float* b;
               __half2* xsi; int rev; };
struct ConvB3 { ConvB c[3]; };
#define CCH 512

__global__ void conv_silu_kernel(ConvB3 P)
{
    const ConvB c = P.c[blockIdx.z];
    const int d  = blockIdx.x*128 + threadIdx.x;
    const int bt = blockIdx.y;
    const int b  = bt >> 3;
    const int t0 = (bt & 7)*CCH;
    const float w0=c.w[d*4+0], w1=c.w[d*4+1], w2=c.w[d*4+2], w3=c.w[d*4+3];
    const float bb=c.b[d];
    const size_t bL = (size_t)b*L_SEQ;

    auto X = [&](int i)->float{
        if (i < 0) return 0.f;
        const int l = c.rev ? (L_SEQ-1-i) : i;
        return c.X[(bL + l)*(size_t)D_XZ + d];
    };
    float x0=X(t0-3), x1=X(t0-2), x2=X(t0-1);
#pragma unroll 4
    for (int t=t0; t<t0+CCH; t++){
        const float x3 = X(t);
        const float v = fmaf(w0,x0,fmaf(w1,x1,fmaf(w2,x2,fmaf(w3,x3,bb))));
        const float s = siluf_(v);
        const __half hh = __float2half_rn(s);
        const __half ll = __float2half_rn(s - __half2float(hh));
        c.xsi[(bL+t)*(size_t)D_INNER + d] = __halves2half2(hh, ll);
        x0=x1; x1=x2; x2=x3;
    }
}

// ============== chunked selective scan ==============================================
struct ScanB { const float* U; const __half2* XS2; const float* DBL; const float* XZb;
               const float* Alog; const float* Dp; float* Y;
               float* Hend; float* Hstart; float* Ssum; int rev; };
struct ScanB3 { ScanB s[3]; };

__device__ __forceinline__ void load_A16(const float* Alog, int d, float* a,
                                         float& a0, bool& pw){
#pragma unroll
    for (int n=0;n<16;n++) a[n] = -__expf(Alog[d*16+n]);
    a0 = a[0];
    pw = fabsf(a0) > 1e-20f;
#pragma unroll
    for (int n=0;n<16;n++){
        const float r = a[n]/a0;
        pw = pw && (fabsf(r - (float)(n+1)) < 1e-4f);
    }
}

// Phase A: per-chunk local scan from h=0; stores h_end and S=Σdt. grid(8, B*NCH, 3)
__global__ void scanA_kernel(ScanB3 P)
{
    __shared__ float sB[TCH][16];
    const ScanB S = P.s[blockIdx.z];
    const int tid = threadIdx.x;
    const int d   = blockIdx.x*128 + tid;
    const int b   = blockIdx.y >> 5;
    const int ch  = blockIdx.y & (NCH-1);
    const size_t bL = (size_t)b*L_SEQ;
    const int t0 = ch*TCH;

    float a[16], a0; bool pw;
    load_A16(S.Alog, d, a, a0, pw);

    // stage B rows for this chunk: TCH*16 floats
#pragma unroll
    for (int r=0;r<(TCH*16)/(4*128);r++){
        const int slot = tid + r*128;
        const int tt = slot>>2, q = slot&3;
        const float4 v = *(const float4*)(S.DBL + (bL + t0 + tt)*64 + 32 + q*4);
        *(float4*)&sB[tt][q*4] = v;
    }
    __syncthreads();

    float h[16];
#pragma unroll
    for (int n=0;n<16;n++) h[n]=0.f;
    float Ss = 0.f;

#pragma unroll 2
    for (int tt=0;tt<TCH;tt++){
        const size_t idx = (bL + t0 + tt)*(size_t)D_INNER + d;
        const float u = S.U[idx];
        const __half2 xp = S.XS2[idx];
        const float xv = __half2float(__low2half(xp)) + __half2float(__high2half(xp));
        const float dt = (u > 20.f) ? u : log1pf(__expf(u));
        Ss += dt;
        const float dtx = dt*xv;
        if (pw){
            const float p = __expf(dt*a0);
            float e[17]; e[1]=p;
#pragma unroll
            for (int n=2;n<=16;n++) e[n] = e[n>>1]*e[n-(n>>1)];
#pragma unroll
            for (int n=0;n<16;n++) h[n] = fmaf(e[n+1], h[n], dtx*sB[tt][n]);
        } else {
#pragma unroll
            for (int n=0;n<16;n++){
                const float e = __expf(dt*a[n]);
                h[n] = fmaf(e, h[n], dtx*sB[tt][n]);
            }
        }
    }
    float* He = S.Hend + ((size_t)(b*NCH + ch)*D_INNER + d)*16;
#pragma unroll
    for (int q=0;q<4;q++) *(float4*)(He + q*4) = *(float4*)&h[q*4];
    S.Ssum[(size_t)(b*NCH + ch)*D_INNER + d] = Ss;
}

// Phase B: prefix over chunks. grid(8, B, 3), 128 threads
__global__ void scanB_kernel(ScanB3 P)
{
    const ScanB S = P.s[blockIdx.z];
    const int tid = threadIdx.x;
    const int d   = blockIdx.x*128 + tid;
    const int b   = blockIdx.y;

    float a[16], a0; bool pw;
    load_A16(S.Alog, d, a, a0, pw);

    float hs[16];
#pragma unroll
    for (int n=0;n<16;n++) hs[n]=0.f;

    for (int c=0;c<NCH;c++){
        const size_t off = ((size_t)(b*NCH + c)*D_INNER + d)*16;
        float* Hs = S.Hstart + off;
#pragma unroll
        for (int q=0;q<4;q++) *(float4*)(Hs + q*4) = *(float4*)&hs[q*4];
        const float Sc = S.Ssum[(size_t)(b*NCH + c)*D_INNER + d];
        const float* He = S.Hend + off;
        float he[16];
#pragma unroll
        for (int q=0;q<4;q++) *(float4*)&he[q*4] = *(const float4*)(He + q*4);
        if (pw){
            const float p = __expf(Sc*a0);
            float e[17]; e[1]=p;
#pragma unroll
            for (int n=2;n<=16;n++) e[n] = e[n>>1]*e[n-(n>>1)];
#pragma unroll
            for (int n=0;n<16;n++) hs[n] = fmaf(e[n+1], hs[n], he[n]);
        } else {
#pragma unroll
            for (int n=0;n<16;n++){
                const float e = __expf(Sc*a[n]);
                hs[n] = fmaf(e, hs[n], he[n]);
            }
        }
    }
}

// Phase C: re-run chunk from true h_start, emit gated y. grid(8, B*NCH, 3)
__global__ void scanC_kernel(ScanB3 P)
{
    __shared__ float sBC[TCH][32];
    const ScanB S = P.s[blockIdx.z];
    const int tid = threadIdx.x;
    const int d   = blockIdx.x*128 + tid;
    const int b   = blockIdx.y >> 5;
    const int ch  = blockIdx.y & (NCH-1);
    const size_t bL = (size_t)b*L_SEQ;
    const int t0 = ch*TCH;

    float a[16], a0; bool pw;
    load_A16(S.Alog, d, a, a0, pw);
    const float Dd = S.Dp[d];

    float h[16];
    {
        const float* Hs = S.Hstart + ((size_t)(b*NCH + ch)*D_INNER + d)*16;
#pragma unroll
        for (int q=0;q<4;q++) *(float4*)&h[q*4] = *(const float4*)(Hs + q*4);
    }

#pragma unroll
    for (int r=0;r<(TCH*32)/(4*128);r++){
        const int slot = tid + r*128;
        const int tt = slot>>3, q = slot&7;
        const float4 v = *(const float4*)(S.DBL + (bL + t0 + tt)*64 + 32 + q*4);
        *(float4*)&sBC[tt][q*4] = v;
    }
    __syncthreads();

#pragma unroll 2
    for (int tt=0;tt<TCH;tt++){
        const int t = t0+tt;
        const size_t idx = (bL + t)*(size_t)D_INNER + d;
        const float u = S.U[idx];
        const __half2 xp = S.XS2[idx];
        const float xv = __half2float(__low2half(xp)) + __half2float(__high2half(xp));
        const int lz = S.rev ? (L_SEQ-1-t) : t;
        const float zv = S.XZb[(bL+lz)*(size_t)D_XZ + D_INNER + d];
        const float dt = (u > 20.f) ? u : log1pf(__expf(u));
        const float dtx = dt*xv;
        float ya[4] = {0.f,0.f,0.f,0.f};
        if (pw){
            const float p = __expf(dt*a0);
            float e[17]; e[1]=p;
#pragma unroll
            for (int n=2;n<=16;n++) e[n] = e[n>>1]*e[n-(n>>1)];
#pragma unroll
            for (int n=0;n<16;n++){
                h[n] = fmaf(e[n+1], h[n], dtx*sBC[tt][n]);
                ya[n&3] = fmaf(h[n], sBC[tt][16+n], ya[n&3]);
            }
        } else {
#pragma unroll
            for (int n=0;n<16;n++){
                const float e = __expf(dt*a[n]);
                h[n] = fmaf(e, h[n], dtx*sBC[tt][n]);
                ya[n&3] = fmaf(h[n], sBC[tt][16+n], ya[n&3]);
            }
        }
        const float y = (ya[0]+ya[1]) + (ya[2]+ya[3]);
        S.Y[idx] = (y + Dd*xv) * siluf_(zv);
    }
}

// ---------------- gated combine -> interleaved half2 --------------------------------
__global__ void combine_kernel(const float* __restrict__ yf, const float* __restrict__ yr,
                               const float* __restrict__ yg, __half2* __restrict__ o)
{
    const size_t i = (size_t)blockIdx.x*256 + threadIdx.x;
    const int d = (int)(i % D_INNER);
    const size_t rr = i / D_INNER;
    const int l = (int)(rr % L_SEQ);
    const int b = (int)(rr / L_SEQ);
    const size_t ridx = ((size_t)b*L_SEQ + (L_SEQ-1-l))*(size_t)D_INNER + d;
    const float v = (yf[i] + yr[ridx]) * siluf_(yg[i]);
    const __half hh = __float2half_rn(v);
    o[rr*(size_t)D_INNER + d] = __halves2half2(hh, __float2half_rn(v - __half2float(hh)));
}

// ------------------------------- host driver ----------------------------------------
extern "C" void kernel_launch(void* const* d_in, const int* in_sizes, int n_in,
                              void* d_out, int out_size)
{
    const float* H    = (const float*)d_in[0];
    const float* AH   = (const float*)d_in[1];
    const float* Winp = (const float*)d_in[2];
    const float* Wing = (const float*)d_in[3];
    const float* convw[3] = { (const float*)d_in[4], (const float*)d_in[6], (const float*)d_in[8] };
    const float* convb[3] = { (const float*)d_in[5], (const float*)d_in[7], (const float*)d_in[9] };
    const float* xproj[3] = { (const float*)d_in[10], (const float*)d_in[11], (const float*)d_in[12] };
    const float* dtw[3]   = { (const float*)d_in[13], (const float*)d_in[15], (const float*)d_in[17] };
    const float* dtb[3]   = { (const float*)d_in[14], (const float*)d_in[16], (const float*)d_in[18] };
    const float* Alog[3]  = { (const float*)d_in[19], (const float*)d_in[20], (const float*)d_in[21] };
    const float* Dp[3]    = { (const float*)d_in[22], (const float*)d_in[23], (const float*)d_in[24] };
    const float* Wout = (const float*)d_in[25];
    float* out = (float*)d_out;

    float *p_xz, *p_axz, *p_u, *p_dbl, *p_y, *p_hend, *p_hstart, *p_ssum;
    __half *p_Haug, *p_AHaug, *p_Wi16, *p_Wg16, *p_xsaug, *p_Xp16;
    __half *p_dtw16, *p_dblaug, *p_Wo16, *p_combaug;
    cudaGetSymbolAddress((void**)&p_xz,     g_xz);
    cudaGetSymbolAddress((void**)&p_axz,    g_axz);
    cudaGetSymbolAddress((void**)&p_u,      g_u);
    cudaGetSymbolAddress((void**)&p_dbl,    g_dbl);
    cudaGetSymbolAddress((void**)&p_y,      g_y);
    cudaGetSymbolAddress((void**)&p_hend,   g_hend);
    cudaGetSymbolAddress((void**)&p_hstart, g_hstart);
    cudaGetSymbolAddress((void**)&p_ssum,   g_ssum);
    cudaGetSymbolAddress((void**)&p_Haug,   g_Haug);
    cudaGetSymbolAddress((void**)&p_AHaug,  g_AHaug);
    cudaGetSymbolAddress((void**)&p_Wi16,   g_Wi16);
    cudaGetSymbolAddress((void**)&p_Wg16,   g_Wg16);
    cudaGetSymbolAddress((void**)&p_xsaug,  g_xsaug);
    cudaGetSymbolAddress((void**)&p_Xp16,   g_Xp16);
    cudaGetSymbolAddress((void**)&p_dtw16,  g_dtw16);
    cudaGetSymbolAddress((void**)&p_dblaug, g_dblaug);
    cudaGetSymbolAddress((void**)&p_Wo16,   g_Wo16);
    cudaGetSymbolAddress((void**)&p_combaug,g_combaug);

    const size_t SXS   = (size_t)NTOK*D_INNER;
    const size_t SDBL  = (size_t)NTOK*64;
    const size_t SXSA  = (size_t)NTOK*2*D_INNER;
    const size_t SXP   = (size_t)64*2*D_INNER;
    const size_t SDTW  = (size_t)D_INNER*2*DT_RANK;
    const size_t SDBLA = (size_t)NTOK*64;
    const size_t SHE   = (size_t)B_SZ*NCH*D_INNER*16;
    const size_t SSS   = (size_t)B_SZ*NCH*D_INNER;

    const int SMEM128 = 4*(128*40 + 128*40)*2;
    const int SMEM64  = 4*(128*40 +  64*40)*2;
    cudaFuncSetAttribute((const void*)mma_gemm<128,false,false>, cudaFuncAttributeMaxDynamicSharedMemorySize, SMEM128);
    cudaFuncSetAttribute((const void*)mma_gemm<128,true,false>,  cudaFuncAttributeMaxDynamicSharedMemorySize, SMEM128);
    cudaFuncSetAttribute((const void*)mma_gemm<64,false,true>,   cudaFuncAttributeMaxDynamicSharedMemorySize, SMEM64);

    // #1: big W conversions
    {
        CJobs7 J;
        J.j[0] = { Winp, p_Wi16, (int)((size_t)D_XZ*D_MODEL/4) };
        J.j[1] = { Wing, p_Wg16, (int)((size_t)D_XZ*D_MODEL/4) };
        const int maxb = ((int)((size_t)D_XZ*D_MODEL/4) + 255)/256;
        convWdup_multi<2><<<dim3(maxb,1,2), 256>>>(J);
    }
    // #2, #3: A-side splits of H / AH
    splitA16<<<(NTOK*D_MODEL/4+255)/256, 256>>>(H,  p_Haug,  D_MODEL, NTOK*D_MODEL/4);
    splitA16<<<(NTOK*D_MODEL/4+255)/256, 256>>>(AH, p_AHaug, D_MODEL, NTOK*D_MODEL/4);

    // #4: in-projections  <-- ncu profile slot
    {
        MG3 P; P.N = D_XZ; P.K2 = 2*D_MODEL;
        P.g[0] = { p_Haug,  p_Wi16, nullptr, p_xz,  nullptr };
        P.g[1] = { p_AHaug, p_Wg16, nullptr, p_axz, nullptr };
        P.g[2] = P.g[0];
        mma_gemm<128,false,false><<<dim3(D_XZ/128, NTOK/128, 2), 256, SMEM128>>>(P);
    }
    // #5: misc W conversions
    {
        CJobs7 J;
        for (int z=0; z<3; z++){
            J.j[z]   = { xproj[z], p_Xp16  + z*SXP,  (int)((size_t)64*D_INNER/4) };
            J.j[3+z] = { dtw[z],   p_dtw16 + z*SDTW, (int)((size_t)D_INNER*DT_RANK/4) };
        }
        J.j[6] = { Wout, p_Wo16, (int)((size_t)D_MODEL*D_INNER/4) };
        const int maxb = ((int)((size_t)D_MODEL*D_INNER/4) + 255)/256;
        convWdup_multi<7><<<dim3(maxb,1,7), 256>>>(J);
    }
    // #6: depthwise conv + silu
    {
        ConvB3 P;
        P.c[0] = { p_xz,  convw[0], convb[0], (__half2*)(p_xsaug + 0*SXSA), 0 };
        P.c[1] = { p_xz,  convw[1], convb[1], (__half2*)(p_xsaug + 1*SXSA), 1 };
        P.c[2] = { p_axz, convw[2], convb[2], (__half2*)(p_xsaug + 2*SXSA), 0 };
        conv_silu_kernel<<<dim3(D_INNER/128, 32, 3), 128>>>(P);
    }
    // #7: x-projection (fused dblaug epilogue)
    {
        MG3 P; P.N = 64; P.K2 = 2*D_INNER;
        for (int z=0; z<3; z++)
            P.g[z] = { p_xsaug + z*SXSA, p_Xp16 + z*SXP, nullptr, p_dbl + z*SDBL, p_dblaug + z*SDBLA };
        mma_gemm<64,false,true><<<dim3(1, NTOK/128, 3), 256, SMEM64>>>(P);
    }
    // #8: dt-projection
    {
        MG3 P; P.N = D_INNER; P.K2 = 2*DT_RANK;
        for (int z=0; z<3; z++)
            P.g[z] = { p_dblaug + z*SDBLA, p_dtw16 + z*SDTW, dtb[z], p_u + z*SXS, nullptr };
        mma_gemm<128,true,false><<<dim3(D_INNER/128, NTOK/128, 3), 256, SMEM128>>>(P);
    }
    // #9-#11: chunked selective scan (A: local, B: prefix, C: emit)
    {
        ScanB3 P;
        P.s[0] = { p_u + 0*SXS, (const __half2*)(p_xsaug + 0*SXSA), p_dbl + 0*SDBL, p_xz,
                   Alog[0], Dp[0], p_y + 0*SXS, p_hend + 0*SHE, p_hstart + 0*SHE, p_ssum + 0*SSS, 0 };
        P.s[1] = { p_u + 1*SXS, (const __half2*)(p_xsaug + 1*SXSA), p_dbl + 1*SDBL, p_xz,
                   Alog[1], Dp[1], p_y + 1*SXS, p_hend + 1*SHE, p_hstart + 1*SHE, p_ssum + 1*SSS, 1 };
        P.s[2] = { p_u + 2*SXS, (const __half2*)(p_xsaug + 2*SXSA), p_dbl + 2*SDBL, p_axz,
                   Alog[2], Dp[2], p_y + 2*SXS, p_hend + 2*SHE, p_hstart + 2*SHE, p_ssum + 2*SSS, 0 };
        scanA_kernel<<<dim3(D_INNER/128, B_SZ*NCH, 3), 128>>>(P);
        scanB_kernel<<<dim3(D_INNER/128, B_SZ, 3), 128>>>(P);
        scanC_kernel<<<dim3(D_INNER/128, B_SZ*NCH, 3), 128>>>(P);
    }
    // #12: combine
    combine_kernel<<<(unsigned)(SXS/256), 256>>>(p_y + 0*SXS, p_y + 1*SXS, p_y + 2*SXS, (__half2*)p_combaug);
    // #13: out-projection
    {
        MG3 P; P.N = D_MODEL; P.K2 = 2*D_INNER;
        P.g[0] = { p_combaug, p_Wo16, nullptr, out, nullptr };
        P.g[1] = P.g[0]; P.g[2] = P.g[0];
        mma_gemm<128,false,false><<<dim3(D_MODEL/128, NTOK/128, 1), 256, SMEM128>>>(P);
    }
    (void)in_sizes; (void)n_in; (void)out_size;
}

// round 9
// speedup vs baseline: 3.5214x; 1.0326x over previous
#include <cuda_runtime.h>
#include <cuda_fp16.h>
#include <cstdint>

#define L_SEQ   4096
#define B_SZ    4
#define D_MODEL 512
#define D_INNER 1024
#define D_XZ    2048
#define NTOK    (B_SZ*L_SEQ)   /* 16384 */
#define DT_RANK 32
#define D_STATE 16
#define NCH     32              /* time chunks for parallel scan */
#define TCH     (L_SEQ/NCH)     /* 128 steps per chunk */

// ---------------- scratch (static device allocations) -------------------------------
__device__ float g_xz  [(size_t)NTOK*D_XZ];
__device__ float g_axz [(size_t)NTOK*D_XZ];
__device__ float g_u   [3][(size_t)NTOK*D_INNER];      // dt logits (fp32)
__device__ float g_dbl [3][(size_t)NTOK*64];           // dt_low | B | C (fp32 for scan)
__device__ float g_y   [3][(size_t)NTOK*D_INNER];      // branch outputs
// chunked-scan carries
__device__ float g_hend  [3][(size_t)B_SZ*NCH*D_INNER*16];
__device__ float g_hstart[3][(size_t)B_SZ*NCH*D_INNER*16];
__device__ float g_ssum  [3][(size_t)B_SZ*NCH*D_INNER];
// interleaved fp16 pairs. A-side rows: [h0,l0,h1,l1,...] (K2=2K halves).
// W-side rows: duplicated [w0,w0,w1,w1,...] (K2 halves).
__device__ __half g_Haug [(size_t)NTOK*2*D_MODEL];
__device__ __half g_AHaug[(size_t)NTOK*2*D_MODEL];
__device__ __half g_Wi16 [(size_t)D_XZ*2*D_MODEL];
__device__ __half g_Wg16 [(size_t)D_XZ*2*D_MODEL];
__device__ __half g_xsaug[3][(size_t)NTOK*2*D_INNER];  // conv+silu x as {hi,lo} pairs
__device__ __half g_Xp16 [3][(size_t)64*2*D_INNER];
__device__ __half g_dtw16[3][(size_t)D_INNER*2*DT_RANK];
__device__ __half g_dblaug[3][(size_t)NTOK*64];        // interleaved pairs of dt_low(32)
__device__ __half g_Wo16 [(size_t)D_MODEL*2*D_INNER];
__device__ __half g_combaug[(size_t)NTOK*2*D_INNER];

__device__ __forceinline__ float sigmoidf_(float x){ return 1.0f/(1.0f+__expf(-x)); }
__device__ __forceinline__ float siluf_(float x){ return x*sigmoidf_(x); }

__device__ __forceinline__ uint32_t smem_u32(const void* p){
    uint32_t a;
    asm("{ .reg .u64 t; cvta.to.shared.u64 t, %1; cvt.u32.u64 %0, t; }" : "=r"(a) : "l"(p));
    return a;
}
__device__ __forceinline__ void cp_async16(uint32_t dst, const void* src){
    asm volatile("cp.async.cg.shared.global [%0], [%1], 16;\n" :: "r"(dst), "l"(src));
}

// ====== W convert: fp32 [.,K] -> fp16 duplicated-interleave [., 2K] ================
struct CJob { const float* src; __half* dst; int n4; };
struct CJobs7 { CJob j[7]; };
template<int NJ>
__global__ void convWdup_multi(CJobs7 J)
{
    const CJob jb = J.j[blockIdx.z];
    const int i = blockIdx.x*256 + threadIdx.x;
    if (i >= jb.n4) return;
    const float4 v = ((const float4*)jb.src)[i];
    __half h0=__float2half_rn(v.x), h1=__float2half_rn(v.y),
           h2=__float2half_rn(v.z), h3=__float2half_rn(v.w);
    __align__(16) __half o[8] = {h0,h0,h1,h1,h2,h2,h3,h3};
    *(uint4*)(jb.dst + (size_t)i*8) = *(const uint4*)o;
}

// ====== A split: fp32 [R,K] -> fp16 interleaved [R, 2K] = [h,l,h,l,...] ============
__global__ void splitA16(const float* __restrict__ src, __half* __restrict__ dst,
                         int K, int n4total)
{
    const int i = blockIdx.x*256 + threadIdx.x;
    if (i >= n4total) return;
    const int kq = K >> 2;
    const int r  = i / kq, k4 = i % kq;
    const float4 v = *(const float4*)(src + (size_t)r*K + k4*4);
    const float f[4] = {v.x, v.y, v.z, v.w};
    __align__(16) __half o[8];
#pragma unroll
    for (int j=0;j<4;j++){
        const __half hh = __float2half_rn(f[j]);
        o[2*j]   = hh;
        o[2*j+1] = __float2half_rn(f[j] - __half2float(hh));
    }
    *(uint4*)(dst + (size_t)r*2*K + (size_t)k4*8) = *(const uint4*)o;
}

// ================= mma.sync fp16 GEMM: BK=64, NS=3, single sync per k-iter ==========
// A: [M,K2] interleaved pairs.  W: [N,K2] duplicated.  BM=128, BN∈{64,128},
// smem rows = 144B (64 halves data + pad), conflict-free for ldmatrix & stores.
struct MG  { const __half *A, *W; const float* bias; float* C; __half* Daug; };
struct MG3 { MG g[3]; int N, K2; };

template<int BN, bool BIAS, bool DBLAUG>
__global__ void __launch_bounds__(256, 2) mma_gemm(MG3 P)
{
    constexpr int NS  = 3;
    constexpr int WN  = BN/2;
    constexpr int NTL = WN/8;
    constexpr int RSTR = 144;                   // bytes per smem row
    constexpr int SA_B = 128*RSTR;              // A stage bytes
    constexpr int SW_B = BN*RSTR;               // W stage bytes
    const MG g = P.g[blockIdx.z];
    const int N = P.N, K2 = P.K2;
    const int tid  = threadIdx.x;
    const int lane = tid & 31, wid = tid >> 5;
    const int warp_m = wid & 3, warp_n = wid >> 2;
    const int m0 = blockIdx.y * 128, n0 = blockIdx.x * BN;

    extern __shared__ __align__(128) __half sm[];
    const uint32_t base = smem_u32(sm);
    uint32_t aB[NS], wB[NS];
#pragma unroll
    for (int s=0;s<NS;s++){
        aB[s] = base + (uint32_t)(s*(SA_B+SW_B));
        wB[s] = aB[s] + SA_B;
    }

    float acc[2][NTL][4];
#pragma unroll
    for (int mt=0;mt<2;mt++)
#pragma unroll
        for (int nt=0;nt<NTL;nt++)
#pragma unroll
            for (int j=0;j<4;j++) acc[mt][nt][j]=0.f;

    const int nk = K2 / 64;

    auto load_tiles = [&](int s, int kt){
        const int k0 = kt*64;
        const __half* Ap = g.A + (size_t)m0*K2 + k0;
#pragma unroll
        for (int q = tid; q < 1024; q += 256){
            const int r = q>>3, c = q&7;
            cp_async16(aB[s] + r*RSTR + c*16, Ap + (size_t)r*K2 + c*8);
        }
        const __half* Wp = g.W + (size_t)n0*K2 + k0;
#pragma unroll
        for (int q = tid; q < BN*8; q += 256){
            const int r = q>>3, c = q&7;
            cp_async16(wB[s] + r*RSTR + c*16, Wp + (size_t)r*K2 + c*8);
        }
        asm volatile("cp.async.commit_group;\n" ::: "memory");
    };

#pragma unroll
    for (int s=0; s<NS-1; s++){
        if (s < nk) load_tiles(s, s);
        else asm volatile("cp.async.commit_group;\n" ::: "memory");
    }

    const int lr       = lane & 7;
    const int arow_off = ((lane>>3)&1)*8 + lr;
    const int akb      = (lane>>4)*16;
    const int brow_off = ((lane>>4)&1)*8 + lr;
    const int bkb      = ((lane>>3)&1)*16;

    for (int kt = 0; kt < nk; kt++){
        asm volatile("cp.async.wait_group 1;\n" ::: "memory");
        __syncthreads();
        const int pf = kt + NS - 1;
        if (pf < nk) load_tiles(pf % NS, pf);
        else asm volatile("cp.async.commit_group;\n" ::: "memory");

        const uint32_t aBc = aB[kt % NS], wBc = wB[kt % NS];
#pragma unroll
        for (int ks = 0; ks < 4; ks++){
            uint32_t a[2][4];
#pragma unroll
            for (int mt=0; mt<2; mt++){
                const uint32_t addr = aBc + (warp_m*32 + mt*16 + arow_off)*RSTR + ks*32 + akb;
                asm volatile("ldmatrix.sync.aligned.m8n8.x4.shared.b16 {%0,%1,%2,%3}, [%4];"
                    : "=r"(a[mt][0]),"=r"(a[mt][1]),"=r"(a[mt][2]),"=r"(a[mt][3]) : "r"(addr));
            }
            uint32_t b[NTL][2];
#pragma unroll
            for (int ntp=0; ntp<NTL/2; ntp++){
                const uint32_t addr = wBc + (warp_n*WN + ntp*16 + brow_off)*RSTR + ks*32 + bkb;
                asm volatile("ldmatrix.sync.aligned.m8n8.x4.shared.b16 {%0,%1,%2,%3}, [%4];"
                    : "=r"(b[2*ntp][0]),"=r"(b[2*ntp][1]),
                      "=r"(b[2*ntp+1][0]),"=r"(b[2*ntp+1][1]) : "r"(addr));
            }
#pragma unroll
            for (int mt=0; mt<2; mt++)
#pragma unroll
                for (int nt=0; nt<NTL; nt++){
                    asm volatile("mma.sync.aligned.m16n8k16.row.col.f32.f16.f16.f32 "
                        "{%0,%1,%2,%3}, {%4,%5,%6,%7}, {%8,%9}, {%0,%1,%2,%3};"
                        : "+f"(acc[mt][nt][0]),"+f"(acc[mt][nt][1]),
                          "+f"(acc[mt][nt][2]),"+f"(acc[mt][nt][3])
                        : "r"(a[mt][0]),"r"(a[mt][1]),"r"(a[mt][2]),"r"(a[mt][3]),
                          "r"(b[nt][0]),"r"(b[nt][1]));
                }
        }
    }

    const int lr4 = lane>>2, lc2 = (lane&3)*2;
#pragma unroll
    for (int mt=0; mt<2; mt++){
        const int r0 = m0 + warp_m*32 + mt*16 + lr4;
#pragma unroll
        for (int nt=0; nt<NTL; nt++){
            const int col = n0 + warp_n*WN + nt*8 + lc2;
            float b0=0.f, b1=0.f;
            if (BIAS){ b0 = g.bias[col]; b1 = g.bias[col+1]; }
            float2 v0, v1;
            v0.x = acc[mt][nt][0]+b0; v0.y = acc[mt][nt][1]+b1;
            v1.x = acc[mt][nt][2]+b0; v1.y = acc[mt][nt][3]+b1;
            *(float2*)(g.C + (size_t)r0*N + col)     = v0;
            *(float2*)(g.C + (size_t)(r0+8)*N + col) = v1;
            if (DBLAUG && col < 32){
                __half2* D0 = (__half2*)(g.Daug + (size_t)r0*64);
                __half2* D1 = (__half2*)(g.Daug + (size_t)(r0+8)*64);
                __half h;
                h = __float2half_rn(v0.x); D0[col]   = __halves2half2(h, __float2half_rn(v0.x - __half2float(h)));
                h = __float2half_rn(v0.y); D0[col+1] = __halves2half2(h, __float2half_rn(v0.y - __half2float(h)));
                h = __float2half_rn(v1.x); D1[col]   = __halves2half2(h, __float2half_rn(v1.x - __half2float(h)));
                h = __float2half_rn(v1.y); D1[col+1] = __halves2half2(h, __float2half_rn(v1.y - __half2float(h)));
            }
        }
    }
}

// ---------------- depthwise causal conv (k=4) + SiLU -> interleaved half2 -----------
struct ConvB { const float* X; const float* w; const float* b;
               __half2* xsi; int rev; };
struct ConvB3 { ConvB c[3]; };
#define CCH 512

__global__ void conv_silu_kernel(ConvB3 P)
{
    const ConvB c = P.c[blockIdx.z];
    const int d  = blockIdx.x*128 + threadIdx.x;
    const int bt = blockIdx.y;
    const int b  = bt >> 3;
    const int t0 = (bt & 7)*CCH;
    const float w0=c.w[d*4+0], w1=c.w[d*4+1], w2=c.w[d*4+2], w3=c.w[d*4+3];
    const float bb=c.b[d];
    const size_t bL = (size_t)b*L_SEQ;

    auto X = [&](int i)->float{
        if (i < 0) return 0.f;
        const int l = c.rev ? (L_SEQ-1-i) : i;
        return c.X[(bL + l)*(size_t)D_XZ + d];
    };
    float x0=X(t0-3), x1=X(t0-2), x2=X(t0-1);
#pragma unroll 4
    for (int t=t0; t<t0+CCH; t++){
        const float x3 = X(t);
        const float v = fmaf(w0,x0,fmaf(w1,x1,fmaf(w2,x2,fmaf(w3,x3,bb))));
        const float s = siluf_(v);
        const __half hh = __float2half_rn(s);
        const __half ll = __float2half_rn(s - __half2float(hh));
        c.xsi[(bL+t)*(size_t)D_INNER + d] = __halves2half2(hh, ll);
        x0=x1; x1=x2; x2=x3;
    }
}

// ============== chunked selective scan ==============================================
struct ScanB { const float* U; const __half2* XS2; const float* DBL; const float* XZb;
               const float* Alog; const float* Dp; float* Y;
               float* Hend; float* Hstart; float* Ssum; int rev; };
struct ScanB3 { ScanB s[3]; };

__device__ __forceinline__ void load_A16(const float* Alog, int d, float* a,
                                         float& a0, bool& pw){
#pragma unroll
    for (int n=0;n<16;n++) a[n] = -__expf(Alog[d*16+n]);
    a0 = a[0];
    pw = fabsf(a0) > 1e-20f;
#pragma unroll
    for (int n=0;n<16;n++){
        const float r = a[n]/a0;
        pw = pw && (fabsf(r - (float)(n+1)) < 1e-4f);
    }
}

// Phase A: per-chunk local scan from h=0; stores h_end and S=Σdt. grid(8, B*NCH, 3)
__global__ void scanA_kernel(ScanB3 P)
{
    __shared__ float sB[TCH][16];
    const ScanB S = P.s[blockIdx.z];
    const int tid = threadIdx.x;
    const int d   = blockIdx.x*128 + tid;
    const int b   = blockIdx.y >> 5;
    const int ch  = blockIdx.y & (NCH-1);
    const size_t bL = (size_t)b*L_SEQ;
    const int t0 = ch*TCH;

    float a[16], a0; bool pw;
    load_A16(S.Alog, d, a, a0, pw);

#pragma unroll
    for (int r=0;r<(TCH*16)/(4*128);r++){
        const int slot = tid + r*128;
        const int tt = slot>>2, q = slot&3;
        const float4 v = *(const float4*)(S.DBL + (bL + t0 + tt)*64 + 32 + q*4);
        *(float4*)&sB[tt][q*4] = v;
    }
    __syncthreads();

    float h[16];
#pragma unroll
    for (int n=0;n<16;n++) h[n]=0.f;
    float Ss = 0.f;

#pragma unroll 2
    for (int tt=0;tt<TCH;tt++){
        const size_t idx = (bL + t0 + tt)*(size_t)D_INNER + d;
        const float u = S.U[idx];
        const __half2 xp = S.XS2[idx];
        const float xv = __half2float(__low2half(xp)) + __half2float(__high2half(xp));
        const float dt = (u > 20.f) ? u : log1pf(__expf(u));
        Ss += dt;
        const float dtx = dt*xv;
        if (pw){
            const float p = __expf(dt*a0);
            float e[17]; e[1]=p;
#pragma unroll
            for (int n=2;n<=16;n++) e[n] = e[n>>1]*e[n-(n>>1)];
#pragma unroll
            for (int n=0;n<16;n++) h[n] = fmaf(e[n+1], h[n], dtx*sB[tt][n]);
        } else {
#pragma unroll
            for (int n=0;n<16;n++){
                const float e = __expf(dt*a[n]);
                h[n] = fmaf(e, h[n], dtx*sB[tt][n]);
            }
        }
    }
    float* He = S.Hend + ((size_t)(b*NCH + ch)*D_INNER + d)*16;
#pragma unroll
    for (int q=0;q<4;q++) *(float4*)(He + q*4) = *(float4*)&h[q*4];
    S.Ssum[(size_t)(b*NCH + ch)*D_INNER + d] = Ss;
}

// Phase B: prefix over chunks. grid(8, B, 3), 128 threads
__global__ void scanB_kernel(ScanB3 P)
{
    const ScanB S = P.s[blockIdx.z];
    const int tid = threadIdx.x;
    const int d   = blockIdx.x*128 + tid;
    const int b   = blockIdx.y;

    float a[16], a0; bool pw;
    load_A16(S.Alog, d, a, a0, pw);

    float hs[16];
#pragma unroll
    for (int n=0;n<16;n++) hs[n]=0.f;

    for (int c=0;c<NCH;c++){
        const size_t off = ((size_t)(b*NCH + c)*D_INNER + d)*16;
        float* Hs = S.Hstart + off;
#pragma unroll
        for (int q=0;q<4;q++) *(float4*)(Hs + q*4) = *(float4*)&hs[q*4];
        const float Sc = S.Ssum[(size_t)(b*NCH + c)*D_INNER + d];
        const float* He = S.Hend + off;
        float he[16];
#pragma unroll
        for (int q=0;q<4;q++) *(float4*)&he[q*4] = *(const float4*)(He + q*4);
        if (pw){
            const float p = __expf(Sc*a0);
            float e[17]; e[1]=p;
#pragma unroll
            for (int n=2;n<=16;n++) e[n] = e[n>>1]*e[n-(n>>1)];
#pragma unroll
            for (int n=0;n<16;n++) hs[n] = fmaf(e[n+1], hs[n], he[n]);
        } else {
#pragma unroll
            for (int n=0;n<16;n++){
                const float e = __expf(Sc*a[n]);
                hs[n] = fmaf(e, hs[n], he[n]);
            }
        }
    }
}

// Phase C: re-run chunk from true h_start, emit gated y. grid(8, B*NCH, 3)
__global__ void scanC_kernel(ScanB3 P)
{
    __shared__ float sBC[TCH][32];
    const ScanB S = P.s[blockIdx.z];
    const int tid = threadIdx.x;
    const int d   = blockIdx.x*128 + tid;
    const int b   = blockIdx.y >> 5;
    const int ch  = blockIdx.y & (NCH-1);
    const size_t bL = (size_t)b*L_SEQ;
    const int t0 = ch*TCH;

    float a[16], a0; bool pw;
    load_A16(S.Alog, d, a, a0, pw);
    const float Dd = S.Dp[d];

    float h[16];
    {
        const float* Hs = S.Hstart + ((size_t)(b*NCH + ch)*D_INNER + d)*16;
#pragma unroll
        for (int q=0;q<4;q++) *(float4*)&h[q*4] = *(const float4*)(Hs + q*4);
    }

#pragma unroll
    for (int r=0;r<(TCH*32)/(4*128);r++){
        const int slot = tid + r*128;
        const int tt = slot>>3, q = slot&7;
        const float4 v = *(const float4*)(S.DBL + (bL + t0 + tt)*64 + 32 + q*4);
        *(float4*)&sBC[tt][q*4] = v;
    }
    __syncthreads();

#pragma unroll 2
    for (int tt=0;tt<TCH;tt++){
        const int t = t0+tt;
        const size_t idx = (bL + t)*(size_t)D_INNER + d;
        const float u = S.U[idx];
        const __half2 xp = S.XS2[idx];
        const float xv = __half2float(__low2half(xp)) + __half2float(__high2half(xp));
        const int lz = S.rev ? (L_SEQ-1-t) : t;
        const float zv = S.XZb[(bL+lz)*(size_t)D_XZ + D_INNER + d];
        const float dt = (u > 20.f) ? u : log1pf(__expf(u));
        const float dtx = dt*xv;
        float ya[4] = {0.f,0.f,0.f,0.f};
        if (pw){
            const float p = __expf(dt*a0);
            float e[17]; e[1]=p;
#pragma unroll
            for (int n=2;n<=16;n++) e[n] = e[n>>1]*e[n-(n>>1)];
#pragma unroll
            for (int n=0;n<16;n++){
                h[n] = fmaf(e[n+1], h[n], dtx*sBC[tt][n]);
                ya[n&3] = fmaf(h[n], sBC[tt][16+n], ya[n&3]);
            }
        } else {
#pragma unroll
            for (int n=0;n<16;n++){
                const float e = __expf(dt*a[n]);
                h[n] = fmaf(e, h[n], dtx*sBC[tt][n]);
                ya[n&3] = fmaf(h[n], sBC[tt][16+n], ya[n&3]);
            }
        }
        const float y = (ya[0]+ya[1]) + (ya[2]+ya[3]);
        S.Y[idx] = (y + Dd*xv) * siluf_(zv);
    }
}

// ---------------- gated combine -> interleaved half2 --------------------------------
__global__ void combine_kernel(const float* __restrict__ yf, const float* __restrict__ yr,
                               const float* __restrict__ yg, __half2* __restrict__ o)
{
    const size_t i = (size_t)blockIdx.x*256 + threadIdx.x;
    const int d = (int)(i % D_INNER);
    const size_t rr = i / D_INNER;
    const int l = (int)(rr % L_SEQ);
    const int b = (int)(rr / L_SEQ);
    const size_t ridx = ((size_t)b*L_SEQ + (L_SEQ-1-l))*(size_t)D_INNER + d;
    const float v = (yf[i] + yr[ridx]) * siluf_(yg[i]);
    const __half hh = __float2half_rn(v);
    o[rr*(size_t)D_INNER + d] = __halves2half2(hh, __float2half_rn(v - __half2float(hh)));
}

// ------------------------------- host driver ----------------------------------------
extern "C" void kernel_launch(void* const* d_in, const int* in_sizes, int n_in,
                              void* d_out, int out_size)
{
    const float* H    = (const float*)d_in[0];
    const float* AH   = (const float*)d_in[1];
    const float* Winp = (const float*)d_in[2];
    const float* Wing = (const float*)d_in[3];
    const float* convw[3] = { (const float*)d_in[4], (const float*)d_in[6], (const float*)d_in[8] };
    const float* convb[3] = { (const float*)d_in[5], (const float*)d_in[7], (const float*)d_in[9] };
    const float* xproj[3] = { (const float*)d_in[10], (const float*)d_in[11], (const float*)d_in[12] };
    const float* dtw[3]   = { (const float*)d_in[13], (const float*)d_in[15], (const float*)d_in[17] };
    const float* dtb[3]   = { (const float*)d_in[14], (const float*)d_in[16], (const float*)d_in[18] };
    const float* Alog[3]  = { (const float*)d_in[19], (const float*)d_in[20], (const float*)d_in[21] };
    const float* Dp[3]    = { (const float*)d_in[22], (const float*)d_in[23], (const float*)d_in[24] };
    const float* Wout = (const float*)d_in[25];
    float* out = (float*)d_out;

    float *p_xz, *p_axz, *p_u, *p_dbl, *p_y, *p_hend, *p_hstart, *p_ssum;
    __half *p_Haug, *p_AHaug, *p_Wi16, *p_Wg16, *p_xsaug, *p_Xp16;
    __half *p_dtw16, *p_dblaug, *p_Wo16, *p_combaug;
    cudaGetSymbolAddress((void**)&p_xz,     g_xz);
    cudaGetSymbolAddress((void**)&p_axz,    g_axz);
    cudaGetSymbolAddress((void**)&p_u,      g_u);
    cudaGetSymbolAddress((void**)&p_dbl,    g_dbl);
    cudaGetSymbolAddress((void**)&p_y,      g_y);
    cudaGetSymbolAddress((void**)&p_hend,   g_hend);
    cudaGetSymbolAddress((void**)&p_hstart, g_hstart);
    cudaGetSymbolAddress((void**)&p_ssum,   g_ssum);
    cudaGetSymbolAddress((void**)&p_Haug,   g_Haug);
    cudaGetSymbolAddress((void**)&p_AHaug,  g_AHaug);
    cudaGetSymbolAddress((void**)&p_Wi16,   g_Wi16);
    cudaGetSymbolAddress((void**)&p_Wg16,   g_Wg16);
    cudaGetSymbolAddress((void**)&p_xsaug,  g_xsaug);
    cudaGetSymbolAddress((void**)&p_Xp16,   g_Xp16);
    cudaGetSymbolAddress((void**)&p_dtw16,  g_dtw16);
    cudaGetSymbolAddress((void**)&p_dblaug, g_dblaug);
    cudaGetSymbolAddress((void**)&p_Wo16,   g_Wo16);
    cudaGetSymbolAddress((void**)&p_combaug,g_combaug);

    const size_t SXS   = (size_t)NTOK*D_INNER;
    const size_t SDBL  = (size_t)NTOK*64;
    const size_t SXSA  = (size_t)NTOK*2*D_INNER;
    const size_t SXP   = (size_t)64*2*D_INNER;
    const size_t SDTW  = (size_t)D_INNER*2*DT_RANK;
    const size_t SDBLA = (size_t)NTOK*64;
    const size_t SHE   = (size_t)B_SZ*NCH*D_INNER*16;
    const size_t SSS   = (size_t)B_SZ*NCH*D_INNER;

    const int SMEM128 = 3*(128+128)*144;   // 110592 B
    const int SMEM64  = 3*(128+ 64)*144;   //  82944 B
    cudaFuncSetAttribute((const void*)mma_gemm<128,false,false>, cudaFuncAttributeMaxDynamicSharedMemorySize, SMEM128);
    cudaFuncSetAttribute((const void*)mma_gemm<128,true,false>,  cudaFuncAttributeMaxDynamicSharedMemorySize, SMEM128);
    cudaFuncSetAttribute((const void*)mma_gemm<64,false,true>,   cudaFuncAttributeMaxDynamicSharedMemorySize, SMEM64);

    // #1: big W conversions
    {
        CJobs7 J;
        J.j[0] = { Winp, p_Wi16, (int)((size_t)D_XZ*D_MODEL/4) };
        J.j[1] = { Wing, p_Wg16, (int)((size_t)D_XZ*D_MODEL/4) };
        const int maxb = ((int)((size_t)D_XZ*D_MODEL/4) + 255)/256;
        convWdup_multi<2><<<dim3(maxb,1,2), 256>>>(J);
    }
    // #2, #3: A-side splits of H / AH
    splitA16<<<(NTOK*D_MODEL/4+255)/256, 256>>>(H,  p_Haug,  D_MODEL, NTOK*D_MODEL/4);
    splitA16<<<(NTOK*D_MODEL/4+255)/256, 256>>>(AH, p_AHaug, D_MODEL, NTOK*D_MODEL/4);

    // #4: in-projections  <-- ncu profile slot
    {
        MG3 P; P.N = D_XZ; P.K2 = 2*D_MODEL;
        P.g[0] = { p_Haug,  p_Wi16, nullptr, p_xz,  nullptr };
        P.g[1] = { p_AHaug, p_Wg16, nullptr, p_axz, nullptr };
        P.g[2] = P.g[0];
        mma_gemm<128,false,false><<<dim3(D_XZ/128, NTOK/128, 2), 256, SMEM128>>>(P);
    }
    // #5: misc W conversions
    {
        CJobs7 J;
        for (int z=0; z<3; z++){
            J.j[z]   = { xproj[z], p_Xp16  + z*SXP,  (int)((size_t)64*D_INNER/4) };
            J.j[3+z] = { dtw[z],   p_dtw16 + z*SDTW, (int)((size_t)D_INNER*DT_RANK/4) };
        }
        J.j[6] = { Wout, p_Wo16, (int)((size_t)D_MODEL*D_INNER/4) };
        const int maxb = ((int)((size_t)D_MODEL*D_INNER/4) + 255)/256;
        convWdup_multi<7><<<dim3(maxb,1,7), 256>>>(J);
    }
    // #6: depthwise conv + silu
    {
        ConvB3 P;
        P.c[0] = { p_xz,  convw[0], convb[0], (__half2*)(p_xsaug + 0*SXSA), 0 };
        P.c[1] = { p_xz,  convw[1], convb[1], (__half2*)(p_xsaug + 1*SXSA), 1 };
        P.c[2] = { p_axz, convw[2], convb[2], (__half2*)(p_xsaug + 2*SXSA), 0 };
        conv_silu_kernel<<<dim3(D_INNER/128, 32, 3), 128>>>(P);
    }
    // #7: x-projection (fused dblaug epilogue)
    {
        MG3 P; P.N = 64; P.K2 = 2*D_INNER;
        for (int z=0; z<3; z++)
            P.g[z] = { p_xsaug + z*SXSA, p_Xp16 + z*SXP, nullptr, p_dbl + z*SDBL, p_dblaug + z*SDBLA };
        mma_gemm<64,false,true><<<dim3(1, NTOK/128, 3), 256, SMEM64>>>(P);
    }
    // #8: dt-projection
    {
        MG3 P; P.N = D_INNER; P.K2 = 2*DT_RANK;
        for (int z=0; z<3; z++)
            P.g[z] = { p_dblaug + z*SDBLA, p_dtw16 + z*SDTW, dtb[z], p_u + z*SXS, nullptr };
        mma_gemm<128,true,false><<<dim3(D_INNER/128, NTOK/128, 3), 256, SMEM128>>>(P);
    }
    // #9-#11: chunked selective scan (A: local, B: prefix, C: emit)
    {
        ScanB3 P;
        P.s[0] = { p_u + 0*SXS, (const __half2*)(p_xsaug + 0*SXSA), p_dbl + 0*SDBL, p_xz,
                   Alog[0], Dp[0], p_y + 0*SXS, p_hend + 0*SHE, p_hstart + 0*SHE, p_ssum + 0*SSS, 0 };
        P.s[1] = { p_u + 1*SXS, (const __half2*)(p_xsaug + 1*SXSA), p_dbl + 1*SDBL, p_xz,
                   Alog[1], Dp[1], p_y + 1*SXS, p_hend + 1*SHE, p_hstart + 1*SHE, p_ssum + 1*SSS, 1 };
        P.s[2] = { p_u + 2*SXS, (const __half2*)(p_xsaug + 2*SXSA), p_dbl + 2*SDBL, p_axz,
                   Alog[2], Dp[2], p_y + 2*SXS, p_hend + 2*SHE, p_hstart + 2*SHE, p_ssum + 2*SSS, 0 };
        scanA_kernel<<<dim3(D_INNER/128, B_SZ*NCH, 3), 128>>>(P);
        scanB_kernel<<<dim3(D_INNER/128, B_SZ, 3), 128>>>(P);
        scanC_kernel<<<dim3(D_INNER/128, B_SZ*NCH, 3), 128>>>(P);
    }
    // #12: combine
    combine_kernel<<<(unsigned)(SXS/256), 256>>>(p_y + 0*SXS, p_y + 1*SXS, p_y + 2*SXS, (__half2*)p_combaug);
    // #13: out-projection
    {
        MG3 P; P.N = D_MODEL; P.K2 = 2*D_INNER;
        P.g[0] = { p_combaug, p_Wo16, nullptr, out, nullptr };
        P.g[1] = P.g[0]; P.g[2] = P.g[0];
        mma_gemm<128,false,false><<<dim3(D_MODEL/128, NTOK/128, 1), 256, SMEM128>>>(P);
    }
    (void)in_sizes; (void)n_in; (void)out_size;
}

// round 10
// speedup vs baseline: 3.5683x; 1.0133x over previous
#include <cuda_runtime.h>
#include <cuda_fp16.h>
#include <cstdint>

#define L_SEQ   4096
#define B_SZ    4
#define D_MODEL 512
#define D_INNER 1024
#define D_XZ    2048
#define NTOK    (B_SZ*L_SEQ)   /* 16384 */
#define DT_RANK 32
#define D_STATE 16
#define NCH     32              /* time chunks for parallel scan */
#define TCH     (L_SEQ/NCH)     /* 128 steps per chunk */

// ---------------- scratch (static device allocations) -------------------------------
__device__ float g_xz  [(size_t)NTOK*D_XZ];
__device__ float g_axz [(size_t)NTOK*D_XZ];
__device__ float g_u   [3][(size_t)NTOK*D_INNER];      // dt logits (fp32)
__device__ float g_dbl [3][(size_t)NTOK*64];           // dt_low | B | C (fp32 for scan)
__device__ float g_y   [3][(size_t)NTOK*D_INNER];      // branch outputs
// chunked-scan carries
__device__ float g_hend  [3][(size_t)B_SZ*NCH*D_INNER*16];
__device__ float g_hstart[3][(size_t)B_SZ*NCH*D_INNER*16];
__device__ float g_ssum  [3][(size_t)B_SZ*NCH*D_INNER];
// interleaved fp16 pairs. A-side rows: [h0,l0,h1,l1,...] (K2=2K halves).
// W-side rows: duplicated [w0,w0,w1,w1,...] (K2 halves).
__device__ __half g_Haug [(size_t)NTOK*2*D_MODEL];
__device__ __half g_AHaug[(size_t)NTOK*2*D_MODEL];
__device__ __half g_Wi16 [(size_t)D_XZ*2*D_MODEL];
__device__ __half g_Wg16 [(size_t)D_XZ*2*D_MODEL];
__device__ __half g_xsaug[3][(size_t)NTOK*2*D_INNER];  // conv+silu x as {hi,lo} pairs
__device__ __half g_Xp16 [3][(size_t)64*2*D_INNER];
__device__ __half g_dtw16[3][(size_t)D_INNER*2*DT_RANK];
__device__ __half g_dblaug[3][(size_t)NTOK*64];        // interleaved pairs of dt_low(32)
__device__ __half g_Wo16 [(size_t)D_MODEL*2*D_INNER];
__device__ __half g_combaug[(size_t)NTOK*2*D_INNER];

__device__ __forceinline__ float sigmoidf_(float x){ return 1.0f/(1.0f+__expf(-x)); }
__device__ __forceinline__ float siluf_(float x){ return x*sigmoidf_(x); }

__device__ __forceinline__ uint32_t smem_u32(const void* p){
    uint32_t a;
    asm("{ .reg .u64 t; cvta.to.shared.u64 t, %1; cvt.u32.u64 %0, t; }" : "=r"(a) : "l"(p));
    return a;
}
__device__ __forceinline__ void cp_async16(uint32_t dst, const void* src){
    asm volatile("cp.async.cg.shared.global [%0], [%1], 16;\n" :: "r"(dst), "l"(src));
}

// ---- packed f32x2 helpers (PTX ISA sm_100+ family, plain target) -------------------
typedef unsigned long long ull;
__device__ __forceinline__ ull pk2(float lo, float hi){
    ull r; asm("mov.b64 %0, {%1,%2};" : "=l"(r) : "f"(lo), "f"(hi)); return r;
}
__device__ __forceinline__ void upk2(ull v, float& lo, float& hi){
    asm("mov.b64 {%0,%1}, %2;" : "=f"(lo), "=f"(hi) : "l"(v));
}
#define F2FMA(d,a,b,c) asm("fma.rn.f32x2 %0, %1, %2, %3;" : "=l"(d) : "l"(a), "l"(b), "l"(c))
#define F2MUL(d,a,b)   asm("mul.rn.f32x2 %0, %1, %2;"     : "=l"(d) : "l"(a), "l"(b))

__device__ __forceinline__ float fast_softplus(float u){
    return (u > 15.f) ? u : __logf(1.f + __expf(u));
}

// ====== W convert: fp32 [.,K] -> fp16 duplicated-interleave [., 2K] ================
struct CJob { const float* src; __half* dst; int n4; };
struct CJobs7 { CJob j[7]; };
template<int NJ>
__global__ void convWdup_multi(CJobs7 J)
{
    const CJob jb = J.j[blockIdx.z];
    const int i = blockIdx.x*256 + threadIdx.x;
    if (i >= jb.n4) return;
    const float4 v = ((const float4*)jb.src)[i];
    __half h0=__float2half_rn(v.x), h1=__float2half_rn(v.y),
           h2=__float2half_rn(v.z), h3=__float2half_rn(v.w);
    __align__(16) __half o[8] = {h0,h0,h1,h1,h2,h2,h3,h3};
    *(uint4*)(jb.dst + (size_t)i*8) = *(const uint4*)o;
}

// ====== A split: fp32 [R,K] -> fp16 interleaved [R, 2K] = [h,l,h,l,...] ============
__global__ void splitA16(const float* __restrict__ src, __half* __restrict__ dst,
                         int K, int n4total)
{
    const int i = blockIdx.x*256 + threadIdx.x;
    if (i >= n4total) return;
    const int kq = K >> 2;
    const int r  = i / kq, k4 = i % kq;
    const float4 v = *(const float4*)(src + (size_t)r*K + k4*4);
    const float f[4] = {v.x, v.y, v.z, v.w};
    __align__(16) __half o[8];
#pragma unroll
    for (int j=0;j<4;j++){
        const __half hh = __float2half_rn(f[j]);
        o[2*j]   = hh;
        o[2*j+1] = __float2half_rn(f[j] - __half2float(hh));
    }
    *(uint4*)(dst + (size_t)r*2*K + (size_t)k4*8) = *(const uint4*)o;
}

// ================= mma.sync fp16 GEMM: BK=64, NS=3, single sync per k-iter ==========
struct MG  { const __half *A, *W; const float* bias; float* C; __half* Daug; };
struct MG3 { MG g[3]; int N, K2; };

template<int BN, bool BIAS, bool DBLAUG>
__global__ void __launch_bounds__(256, 2) mma_gemm(MG3 P)
{
    constexpr int NS  = 3;
    constexpr int WN  = BN/2;
    constexpr int NTL = WN/8;
    constexpr int RSTR = 144;                   // bytes per smem row
    constexpr int SA_B = 128*RSTR;
    constexpr int SW_B = BN*RSTR;
    const MG g = P.g[blockIdx.z];
    const int N = P.N, K2 = P.K2;
    const int tid  = threadIdx.x;
    const int lane = tid & 31, wid = tid >> 5;
    const int warp_m = wid & 3, warp_n = wid >> 2;
    const int m0 = blockIdx.y * 128, n0 = blockIdx.x * BN;

    extern __shared__ __align__(128) __half sm[];
    const uint32_t base = smem_u32(sm);
    uint32_t aB[NS], wB[NS];
#pragma unroll
    for (int s=0;s<NS;s++){
        aB[s] = base + (uint32_t)(s*(SA_B+SW_B));
        wB[s] = aB[s] + SA_B;
    }

    float acc[2][NTL][4];
#pragma unroll
    for (int mt=0;mt<2;mt++)
#pragma unroll
        for (int nt=0;nt<NTL;nt++)
#pragma unroll
            for (int j=0;j<4;j++) acc[mt][nt][j]=0.f;

    const int nk = K2 / 64;

    auto load_tiles = [&](int s, int kt){
        const int k0 = kt*64;
        const __half* Ap = g.A + (size_t)m0*K2 + k0;
#pragma unroll
        for (int q = tid; q < 1024; q += 256){
            const int r = q>>3, c = q&7;
            cp_async16(aB[s] + r*RSTR + c*16, Ap + (size_t)r*K2 + c*8);
        }
        const __half* Wp = g.W + (size_t)n0*K2 + k0;
#pragma unroll
        for (int q = tid; q < BN*8; q += 256){
            const int r = q>>3, c = q&7;
            cp_async16(wB[s] + r*RSTR + c*16, Wp + (size_t)r*K2 + c*8);
        }
        asm volatile("cp.async.commit_group;\n" ::: "memory");
    };

#pragma unroll
    for (int s=0; s<NS-1; s++){
        if (s < nk) load_tiles(s, s);
        else asm volatile("cp.async.commit_group;\n" ::: "memory");
    }

    const int lr       = lane & 7;
    const int arow_off = ((lane>>3)&1)*8 + lr;
    const int akb      = (lane>>4)*16;
    const int brow_off = ((lane>>4)&1)*8 + lr;
    const int bkb      = ((lane>>3)&1)*16;

    for (int kt = 0; kt < nk; kt++){
        asm volatile("cp.async.wait_group 1;\n" ::: "memory");
        __syncthreads();
        const int pf = kt + NS - 1;
        if (pf < nk) load_tiles(pf % NS, pf);
        else asm volatile("cp.async.commit_group;\n" ::: "memory");

        const uint32_t aBc = aB[kt % NS], wBc = wB[kt % NS];
#pragma unroll
        for (int ks = 0; ks < 4; ks++){
            uint32_t a[2][4];
#pragma unroll
            for (int mt=0; mt<2; mt++){
                const uint32_t addr = aBc + (warp_m*32 + mt*16 + arow_off)*RSTR + ks*32 + akb;
                asm volatile("ldmatrix.sync.aligned.m8n8.x4.shared.b16 {%0,%1,%2,%3}, [%4];"
                    : "=r"(a[mt][0]),"=r"(a[mt][1]),"=r"(a[mt][2]),"=r"(a[mt][3]) : "r"(addr));
            }
            uint32_t b[NTL][2];
#pragma unroll
            for (int ntp=0; ntp<NTL/2; ntp++){
                const uint32_t addr = wBc + (warp_n*WN + ntp*16 + brow_off)*RSTR + ks*32 + bkb;
                asm volatile("ldmatrix.sync.aligned.m8n8.x4.shared.b16 {%0,%1,%2,%3}, [%4];"
                    : "=r"(b[2*ntp][0]),"=r"(b[2*ntp][1]),
                      "=r"(b[2*ntp+1][0]),"=r"(b[2*ntp+1][1]) : "r"(addr));
            }
#pragma unroll
            for (int mt=0; mt<2; mt++)
#pragma unroll
                for (int nt=0; nt<NTL; nt++){
                    asm volatile("mma.sync.aligned.m16n8k16.row.col.f32.f16.f16.f32 "
                        "{%0,%1,%2,%3}, {%4,%5,%6,%7}, {%8,%9}, {%0,%1,%2,%3};"
                        : "+f"(acc[mt][nt][0]),"+f"(acc[mt][nt][1]),
                          "+f"(acc[mt][nt][2]),"+f"(acc[mt][nt][3])
                        : "r"(a[mt][0]),"r"(a[mt][1]),"r"(a[mt][2]),"r"(a[mt][3]),
                          "r"(b[nt][0]),"r"(b[nt][1]));
                }
        }
    }

    const int lr4 = lane>>2, lc2 = (lane&3)*2;
#pragma unroll
    for (int mt=0; mt<2; mt++){
        const int r0 = m0 + warp_m*32 + mt*16 + lr4;
#pragma unroll
        for (int nt=0; nt<NTL; nt++){
            const int col = n0 + warp_n*WN + nt*8 + lc2;
            float b0=0.f, b1=0.f;
            if (BIAS){ b0 = g.bias[col]; b1 = g.bias[col+1]; }
            float2 v0, v1;
            v0.x = acc[mt][nt][0]+b0; v0.y = acc[mt][nt][1]+b1;
            v1.x = acc[mt][nt][2]+b0; v1.y = acc[mt][nt][3]+b1;
            *(float2*)(g.C + (size_t)r0*N + col)     = v0;
            *(float2*)(g.C + (size_t)(r0+8)*N + col) = v1;
            if (DBLAUG && col < 32){
                __half2* D0 = (__half2*)(g.Daug + (size_t)r0*64);
                __half2* D1 = (__half2*)(g.Daug + (size_t)(r0+8)*64);
                __half h;
                h = __float2half_rn(v0.x); D0[col]   = __halves2half2(h, __float2half_rn(v0.x - __half2float(h)));
                h = __float2half_rn(v0.y); D0[col+1] = __halves2half2(h, __float2half_rn(v0.y - __half2float(h)));
                h = __float2half_rn(v1.x); D1[col]   = __halves2half2(h, __float2half_rn(v1.x - __half2float(h)));
                h = __float2half_rn(v1.y); D1[col+1] = __halves2half2(h, __float2half_rn(v1.y - __half2float(h)));
            }
        }
    }
}

// ---------------- depthwise causal conv (k=4) + SiLU -> interleaved half2 -----------
struct ConvB { const float* X; const float* w; const float* b;
               __half2* xsi; int rev; };
struct ConvB3 { ConvB c[3]; };
#define CCH 512

__global__ void conv_silu_kernel(ConvB3 P)
{
    const ConvB c = P.c[blockIdx.z];
    const int d  = blockIdx.x*128 + threadIdx.x;
    const int bt = blockIdx.y;
    const int b  = bt >> 3;
    const int t0 = (bt & 7)*CCH;
    const float w0=c.w[d*4+0], w1=c.w[d*4+1], w2=c.w[d*4+2], w3=c.w[d*4+3];
    const float bb=c.b[d];
    const size_t bL = (size_t)b*L_SEQ;

    auto X = [&](int i)->float{
        if (i < 0) return 0.f;
        const int l = c.rev ? (L_SEQ-1-i) : i;
        return c.X[(bL + l)*(size_t)D_XZ + d];
    };
    float x0=X(t0-3), x1=X(t0-2), x2=X(t0-1);
#pragma unroll 4
    for (int t=t0; t<t0+CCH; t++){
        const float x3 = X(t);
        const float v = fmaf(w0,x0,fmaf(w1,x1,fmaf(w2,x2,fmaf(w3,x3,bb))));
        const float s = siluf_(v);
        const __half hh = __float2half_rn(s);
        const __half ll = __float2half_rn(s - __half2float(hh));
        c.xsi[(bL+t)*(size_t)D_INNER + d] = __halves2half2(hh, ll);
        x0=x1; x1=x2; x2=x3;
    }
}

// ============== chunked selective scan (f32x2-vectorized) ===========================
struct ScanB { const float* U; const __half2* XS2; const float* DBL; const float* XZb;
               const float* Alog; const float* Dp; float* Y;
               float* Hend; float* Hstart; float* Ssum; int rev; };
struct ScanB3 { ScanB s[3]; };

__device__ __forceinline__ void load_A16(const float* Alog, int d, float* a,
                                         float& a0, bool& pw){
#pragma unroll
    for (int n=0;n<16;n++) a[n] = -__expf(Alog[d*16+n]);
    a0 = a[0];
    pw = fabsf(a0) > 1e-20f;
#pragma unroll
    for (int n=0;n<16;n++){
        const float r = a[n]/a0;
        pw = pw && (fabsf(r - (float)(n+1)) < 1e-4f);
    }
}

// Phase A: per-chunk local scan from h=0; stores h_end and S=Σdt. grid(8, B*NCH, 3)
__global__ void scanA_kernel(ScanB3 P)
{
    __shared__ float sB[TCH][16];
    const ScanB S = P.s[blockIdx.z];
    const int tid = threadIdx.x;
    const int d   = blockIdx.x*128 + tid;
    const int b   = blockIdx.y >> 5;
    const int ch  = blockIdx.y & (NCH-1);
    const size_t bL = (size_t)b*L_SEQ;
    const int t0 = ch*TCH;

    float a[16], a0; bool pw;
    load_A16(S.Alog, d, a, a0, pw);

#pragma unroll
    for (int r=0;r<(TCH*16)/(4*128);r++){
        const int slot = tid + r*128;
        const int tt = slot>>2, q = slot&3;
        const float4 v = *(const float4*)(S.DBL + (bL + t0 + tt)*64 + 32 + q*4);
        *(float4*)&sB[tt][q*4] = v;
    }
    __syncthreads();

    __align__(16) float h[16];
#pragma unroll
    for (int n=0;n<16;n++) h[n]=0.f;
    ull* h2 = (ull*)h;
    float Ss = 0.f;

#pragma unroll 2
    for (int tt=0;tt<TCH;tt++){
        const size_t idx = (bL + t0 + tt)*(size_t)D_INNER + d;
        const float u = S.U[idx];
        const __half2 xp = S.XS2[idx];
        const float xv = __half2float(__low2half(xp)) + __half2float(__high2half(xp));
        const float dt = fast_softplus(u);
        Ss += dt;
        const float dtx = dt*xv;
        if (pw){
            const float p  = __expf(dt*a0);
            const float p2 = p*p;
            ull ep = pk2(p, p2);
            const ull estep = pk2(p2, p2);
            const ull dtx2  = pk2(dtx, dtx);
            const ull* Bp = (const ull*)&sB[tt][0];
#pragma unroll
            for (int k=0;k<8;k++){
                ull t1; F2MUL(t1, dtx2, Bp[k]);
                F2FMA(h2[k], ep, h2[k], t1);
                if (k<7) F2MUL(ep, ep, estep);
            }
        } else {
#pragma unroll
            for (int n=0;n<16;n++){
                const float e = __expf(dt*a[n]);
                h[n] = fmaf(e, h[n], dtx*sB[tt][n]);
            }
        }
    }
    float* He = S.Hend + ((size_t)(b*NCH + ch)*D_INNER + d)*16;
#pragma unroll
    for (int q=0;q<4;q++) *(float4*)(He + q*4) = *(float4*)&h[q*4];
    S.Ssum[(size_t)(b*NCH + ch)*D_INNER + d] = Ss;
}

// Phase B: prefix over chunks. grid(8, B, 3), 128 threads
__global__ void scanB_kernel(ScanB3 P)
{
    const ScanB S = P.s[blockIdx.z];
    const int tid = threadIdx.x;
    const int d   = blockIdx.x*128 + tid;
    const int b   = blockIdx.y;

    float a[16], a0; bool pw;
    load_A16(S.Alog, d, a, a0, pw);

    __align__(16) float hs[16];
#pragma unroll
    for (int n=0;n<16;n++) hs[n]=0.f;
    ull* hs2 = (ull*)hs;

    for (int c=0;c<NCH;c++){
        const size_t off = ((size_t)(b*NCH + c)*D_INNER + d)*16;
        float* Hs = S.Hstart + off;
#pragma unroll
        for (int q=0;q<4;q++) *(float4*)(Hs + q*4) = *(float4*)&hs[q*4];
        const float Sc = S.Ssum[(size_t)(b*NCH + c)*D_INNER + d];
        const float* He = S.Hend + off;
        __align__(16) float he[16];
#pragma unroll
        for (int q=0;q<4;q++) *(float4*)&he[q*4] = *(const float4*)(He + q*4);
        if (pw){
            const float p  = __expf(Sc*a0);
            const float p2 = p*p;
            ull ep = pk2(p, p2);
            const ull estep = pk2(p2, p2);
            const ull* he2 = (const ull*)he;
#pragma unroll
            for (int k=0;k<8;k++){
                F2FMA(hs2[k], ep, hs2[k], he2[k]);
                if (k<7) F2MUL(ep, ep, estep);
            }
        } else {
#pragma unroll
            for (int n=0;n<16;n++){
                const float e = __expf(Sc*a[n]);
                hs[n] = fmaf(e, hs[n], he[n]);
            }
        }
    }
}

// Phase C: re-run chunk from true h_start, emit gated y. grid(8, B*NCH, 3)
__global__ void scanC_kernel(ScanB3 P)
{
    __shared__ float sBC[TCH][32];
    const ScanB S = P.s[blockIdx.z];
    const int tid = threadIdx.x;
    const int d   = blockIdx.x*128 + tid;
    const int b   = blockIdx.y >> 5;
    const int ch  = blockIdx.y & (NCH-1);
    const size_t bL = (size_t)b*L_SEQ;
    const int t0 = ch*TCH;

    float a[16], a0; bool pw;
    load_A16(S.Alog, d, a, a0, pw);
    const float Dd = S.Dp[d];

    __align__(16) float h[16];
    {
        const float* Hs = S.Hstart + ((size_t)(b*NCH + ch)*D_INNER + d)*16;
#pragma unroll
        for (int q=0;q<4;q++) *(float4*)&h[q*4] = *(const float4*)(Hs + q*4);
    }
    ull* h2 = (ull*)h;

#pragma unroll
    for (int r=0;r<(TCH*32)/(4*128);r++){
        const int slot = tid + r*128;
        const int tt = slot>>3, q = slot&7;
        const float4 v = *(const float4*)(S.DBL + (bL + t0 + tt)*64 + 32 + q*4);
        *(float4*)&sBC[tt][q*4] = v;
    }
    __syncthreads();

#pragma unroll 2
    for (int tt=0;tt<TCH;tt++){
        const int t = t0+tt;
        const size_t idx = (bL + t)*(size_t)D_INNER + d;
        const float u = S.U[idx];
        const __half2 xp = S.XS2[idx];
        const float xv = __half2float(__low2half(xp)) + __half2float(__high2half(xp));
        const int lz = S.rev ? (L_SEQ-1-t) : t;
        const float zv = S.XZb[(bL+lz)*(size_t)D_XZ + D_INNER + d];
        const float dt = fast_softplus(u);
        const float dtx = dt*xv;
        float y;
        if (pw){
            const float p  = __expf(dt*a0);
            const float p2 = p*p;
            ull ep = pk2(p, p2);
            const ull estep = pk2(p2, p2);
            const ull dtx2  = pk2(dtx, dtx);
            const ull* Bp = (const ull*)&sBC[tt][0];
            const ull* Cp = (const ull*)&sBC[tt][16];
            ull ya0 = 0ull, ya1 = 0ull;
#pragma unroll
            for (int k=0;k<8;k++){
                ull t1; F2MUL(t1, dtx2, Bp[k]);
                F2FMA(h2[k], ep, h2[k], t1);
                if (k & 1) { F2FMA(ya1, h2[k], Cp[k], ya1); }
                else       { F2FMA(ya0, h2[k], Cp[k], ya0); }
                if (k<7) F2MUL(ep, ep, estep);
            }
            float s0,s1,s2,s3;
            upk2(ya0, s0, s1); upk2(ya1, s2, s3);
            y = (s0+s1) + (s2+s3);
        } else {
            float ya[4] = {0.f,0.f,0.f,0.f};
#pragma unroll
            for (int n=0;n<16;n++){
                const float e = __expf(dt*a[n]);
                h[n] = fmaf(e, h[n], dtx*sBC[tt][n]);
                ya[n&3] = fmaf(h[n], sBC[tt][16+n], ya[n&3]);
            }
            y = (ya[0]+ya[1]) + (ya[2]+ya[3]);
        }
        S.Y[idx] = (y + Dd*xv) * siluf_(zv);
    }
}

// ---------------- gated combine -> interleaved half2 --------------------------------
__global__ void combine_kernel(const float* __restrict__ yf, const float* __restrict__ yr,
                               const float* __restrict__ yg, __half2* __restrict__ o)
{
    const size_t i = (size_t)blockIdx.x*256 + threadIdx.x;
    const int d = (int)(i % D_INNER);
    const size_t rr = i / D_INNER;
    const int l = (int)(rr % L_SEQ);
    const int b = (int)(rr / L_SEQ);
    const size_t ridx = ((size_t)b*L_SEQ + (L_SEQ-1-l))*(size_t)D_INNER + d;
    const float v = (yf[i] + yr[ridx]) * siluf_(yg[i]);
    const __half hh = __float2half_rn(v);
    o[rr*(size_t)D_INNER + d] = __halves2half2(hh, __float2half_rn(v - __half2float(hh)));
}

// ------------------------------- host driver ----------------------------------------
extern "C" void kernel_launch(void* const* d_in, const int* in_sizes, int n_in,
                              void* d_out, int out_size)
{
    const float* H    = (const float*)d_in[0];
    const float* AH   = (const float*)d_in[1];
    const float* Winp = (const float*)d_in[2];
    const float* Wing = (const float*)d_in[3];
    const float* convw[3] = { (const float*)d_in[4], (const float*)d_in[6], (const float*)d_in[8] };
    const float* convb[3] = { (const float*)d_in[5], (const float*)d_in[7], (const float*)d_in[9] };
    const float* xproj[3] = { (const float*)d_in[10], (const float*)d_in[11], (const float*)d_in[12] };
    const float* dtw[3]   = { (const float*)d_in[13], (const float*)d_in[15], (const float*)d_in[17] };
    const float* dtb[3]   = { (const float*)d_in[14], (const float*)d_in[16], (const float*)d_in[18] };
    const float* Alog[3]  = { (const float*)d_in[19], (const float*)d_in[20], (const float*)d_in[21] };
    const float* Dp[3]    = { (const float*)d_in[22], (const float*)d_in[23], (const float*)d_in[24] };
    const float* Wout = (const float*)d_in[25];
    float* out = (float*)d_out;

    float *p_xz, *p_axz, *p_u, *p_dbl, *p_y, *p_hend, *p_hstart, *p_ssum;
    __half *p_Haug, *p_AHaug, *p_Wi16, *p_Wg16, *p_xsaug, *p_Xp16;
    __half *p_dtw16, *p_dblaug, *p_Wo16, *p_combaug;
    cudaGetSymbolAddress((void**)&p_xz,     g_xz);
    cudaGetSymbolAddress((void**)&p_axz,    g_axz);
    cudaGetSymbolAddress((void**)&p_u,      g_u);
    cudaGetSymbolAddress((void**)&p_dbl,    g_dbl);
    cudaGetSymbolAddress((void**)&p_y,      g_y);
    cudaGetSymbolAddress((void**)&p_hend,   g_hend);
    cudaGetSymbolAddress((void**)&p_hstart, g_hstart);
    cudaGetSymbolAddress((void**)&p_ssum,   g_ssum);
    cudaGetSymbolAddress((void**)&p_Haug,   g_Haug);
    cudaGetSymbolAddress((void**)&p_AHaug,  g_AHaug);
    cudaGetSymbolAddress((void**)&p_Wi16,   g_Wi16);
    cudaGetSymbolAddress((void**)&p_Wg16,   g_Wg16);
    cudaGetSymbolAddress((void**)&p_xsaug,  g_xsaug);
    cudaGetSymbolAddress((void**)&p_Xp16,   g_Xp16);
    cudaGetSymbolAddress((void**)&p_dtw16,  g_dtw16);
    cudaGetSymbolAddress((void**)&p_dblaug, g_dblaug);
    cudaGetSymbolAddress((void**)&p_Wo16,   g_Wo16);
    cudaGetSymbolAddress((void**)&p_combaug,g_combaug);

    const size_t SXS   = (size_t)NTOK*D_INNER;
    const size_t SDBL  = (size_t)NTOK*64;
    const size_t SXSA  = (size_t)NTOK*2*D_INNER;
    const size_t SXP   = (size_t)64*2*D_INNER;
    const size_t SDTW  = (size_t)D_INNER*2*DT_RANK;
    const size_t SDBLA = (size_t)NTOK*64;
    const size_t SHE   = (size_t)B_SZ*NCH*D_INNER*16;
    const size_t SSS   = (size_t)B_SZ*NCH*D_INNER;

    const int SMEM128 = 3*(128+128)*144;   // 110592 B
    const int SMEM64  = 3*(128+ 64)*144;   //  82944 B
    cudaFuncSetAttribute((const void*)mma_gemm<128,false,false>, cudaFuncAttributeMaxDynamicSharedMemorySize, SMEM128);
    cudaFuncSetAttribute((const void*)mma_gemm<128,true,false>,  cudaFuncAttributeMaxDynamicSharedMemorySize, SMEM128);
    cudaFuncSetAttribute((const void*)mma_gemm<64,false,true>,   cudaFuncAttributeMaxDynamicSharedMemorySize, SMEM64);

    // #1: big W conversions
    {
        CJobs7 J;
        J.j[0] = { Winp, p_Wi16, (int)((size_t)D_XZ*D_MODEL/4) };
        J.j[1] = { Wing, p_Wg16, (int)((size_t)D_XZ*D_MODEL/4) };
        const int maxb = ((int)((size_t)D_XZ*D_MODEL/4) + 255)/256;
        convWdup_multi<2><<<dim3(maxb,1,2), 256>>>(J);
    }
    // #2, #3: A-side splits of H / AH
    splitA16<<<(NTOK*D_MODEL/4+255)/256, 256>>>(H,  p_Haug,  D_MODEL, NTOK*D_MODEL/4);
    splitA16<<<(NTOK*D_MODEL/4+255)/256, 256>>>(AH, p_AHaug, D_MODEL, NTOK*D_MODEL/4);

    // #4: in-projections  <-- ncu profile slot
    {
        MG3 P; P.N = D_XZ; P.K2 = 2*D_MODEL;
        P.g[0] = { p_Haug,  p_Wi16, nullptr, p_xz,  nullptr };
        P.g[1] = { p_AHaug, p_Wg16, nullptr, p_axz, nullptr };
        P.g[2] = P.g[0];
        mma_gemm<128,false,false><<<dim3(D_XZ/128, NTOK/128, 2), 256, SMEM128>>>(P);
    }
    // #5: misc W conversions
    {
        CJobs7 J;
        for (int z=0; z<3; z++){
            J.j[z]   = { xproj[z], p_Xp16  + z*SXP,  (int)((size_t)64*D_INNER/4) };
            J.j[3+z] = { dtw[z],   p_dtw16 + z*SDTW, (int)((size_t)D_INNER*DT_RANK/4) };
        }
        J.j[6] = { Wout, p_Wo16, (int)((size_t)D_MODEL*D_INNER/4) };
        const int maxb = ((int)((size_t)D_MODEL*D_INNER/4) + 255)/256;
        convWdup_multi<7><<<dim3(maxb,1,7), 256>>>(J);
    }
    // #6: depthwise conv + silu
    {
        ConvB3 P;
        P.c[0] = { p_xz,  convw[0], convb[0], (__half2*)(p_xsaug + 0*SXSA), 0 };
        P.c[1] = { p_xz,  convw[1], convb[1], (__half2*)(p_xsaug + 1*SXSA), 1 };
        P.c[2] = { p_axz, convw[2], convb[2], (__half2*)(p_xsaug + 2*SXSA), 0 };
        conv_silu_kernel<<<dim3(D_INNER/128, 32, 3), 128>>>(P);
    }
    // #7: x-projection (fused dblaug epilogue)
    {
        MG3 P; P.N = 64; P.K2 = 2*D_INNER;
        for (int z=0; z<3; z++)
            P.g[z] = { p_xsaug + z*SXSA, p_Xp16 + z*SXP, nullptr, p_dbl + z*SDBL, p_dblaug + z*SDBLA };
        mma_gemm<64,false,true><<<dim3(1, NTOK/128, 3), 256, SMEM64>>>(P);
    }
    // #8: dt-projection
    {
        MG3 P; P.N = D_INNER; P.K2 = 2*DT_RANK;
        for (int z=0; z<3; z++)
            P.g[z] = { p_dblaug + z*SDBLA, p_dtw16 + z*SDTW, dtb[z], p_u + z*SXS, nullptr };
        mma_gemm<128,true,false><<<dim3(D_INNER/128, NTOK/128, 3), 256, SMEM128>>>(P);
    }
    // #9-#11: chunked selective scan (A: local, B: prefix, C: emit)
    {
        ScanB3 P;
        P.s[0] = { p_u + 0*SXS, (const __half2*)(p_xsaug + 0*SXSA), p_dbl + 0*SDBL, p_xz,
                   Alog[0], Dp[0], p_y + 0*SXS, p_hend + 0*SHE, p_hstart + 0*SHE, p_ssum + 0*SSS, 0 };
        P.s[1] = { p_u + 1*SXS, (const __half2*)(p_xsaug + 1*SXSA), p_dbl + 1*SDBL, p_xz,
                   Alog[1], Dp[1], p_y + 1*SXS, p_hend + 1*SHE, p_hstart + 1*SHE, p_ssum + 1*SSS, 1 };
        P.s[2] = { p_u + 2*SXS, (const __half2*)(p_xsaug + 2*SXSA), p_dbl + 2*SDBL, p_axz,
                   Alog[2], Dp[2], p_y + 2*SXS, p_hend + 2*SHE, p_hstart + 2*SHE, p_ssum + 2*SSS, 0 };
        scanA_kernel<<<dim3(D_INNER/128, B_SZ*NCH, 3), 128>>>(P);
        scanB_kernel<<<dim3(D_INNER/128, B_SZ, 3), 128>>>(P);
        scanC_kernel<<<dim3(D_INNER/128, B_SZ*NCH, 3), 128>>>(P);
    }
    // #12: combine
    combine_kernel<<<(unsigned)(SXS/256), 256>>>(p_y + 0*SXS, p_y + 1*SXS, p_y + 2*SXS, (__half2*)p_combaug);
    // #13: out-projection
    {
        MG3 P; P.N = D_MODEL; P.K2 = 2*D_INNER;
        P.g[0] = { p_combaug, p_Wo16, nullptr, out, nullptr };
        P.g[1] = P.g[0]; P.g[2] = P.g[0];
        mma_gemm<128,false,false><<<dim3(D_MODEL/128, NTOK/128, 1), 256, SMEM128>>>(P);
    }
    (void)in_sizes; (void)n_in; (void)out_size;
}